// round 4
// baseline (speedup 1.0000x reference)
#include <cuda_runtime.h>
#include <math.h>

#define D_   1024
#define T_   256
#define B_   8
#define M_   (B_*T_)        // 2048 rows (b,t)
#define HMHA 16
#define DH   64
#define HGAT 8
#define GDH  128
#define KW   7
#define K5D  (5*D_)
#define KCONV (KW*D_)       // 7168

typedef unsigned long long u64t;
union F2u { u64t u; float2 f; };

__device__ __forceinline__ void ffma2(u64t &d, u64t a, u64t b) {
    asm("fma.rn.f32x2 %0, %1, %2, %0;" : "+l"(d) : "l"(a), "l"(b));
}

// ---------------- scratch (device globals; no allocation) ----------------
__device__ float g_wt[5 * KW * D_ * D_];    // transformed conv weights [c][tap][o][ci]
__device__ float g_ms[M_ * K5D];            // (2048, 5120) concat conv outputs
__device__ float g_z [M_ * D_];             // post fusion-proj / LN / GELU
__device__ float g_q [M_ * D_];
__device__ float g_k [M_ * D_];
__device__ float g_v [M_ * D_];
__device__ float g_s [B_*HMHA * T_ * T_];   // attention scores (128, 256, 256)
__device__ float g_ctx[M_ * D_];
__device__ float g_att[M_ * D_];
__device__ float g_hg [M_ * D_];
__device__ float g_e1[M_ * HGAT];
__device__ float g_e2[M_ * HGAT];
__device__ float g_m2[HGAT];

// =====================================================================
// Weight transform: wt[tap][o][ci] = w[o*7168 + ci*7 + tap]
// =====================================================================
__global__ __launch_bounds__(256)
void wtrans_kernel(const float* __restrict__ w, float* __restrict__ wt)
{
    int idx = blockIdx.x * 256 + threadIdx.x;      // over 7*1024*1024
    int tap = idx >> 20;
    int rem = idx & ((1 << 20) - 1);
    int o  = rem >> 10;
    int ci = rem & 1023;
    wt[idx] = __ldg(&w[(size_t)o * KCONV + ci * 7 + tap]);
}

// =====================================================================
// 128x128x16 double-buffered GEMM with packed FFMA2 math.
// A staged duplicated in smem: As[k][2m]=As[k][2m+1]=A[m,k].
// C[m,n] = sum_k A[m*lda+k] * W[n*ldw+k] + bias[n]
// =====================================================================
#define GL_A(p, k0) ra[p] = *(const float4*)&A[(size_t)(bm + ar + 64*(p))*lda + (k0) + ac]
#define GL_B(p, k0) rb[p] = *(const float4*)&W[(size_t)(bn + ar + 64*(p))*ldw + (k0) + ac]

#define SST2(buf) do { \
    _Pragma("unroll") \
    for (int p = 0; p < 2; p++) { \
        int mm = ar + 64*p; \
        *(float2*)&As[buf][ac+0][2*mm] = make_float2(ra[p].x, ra[p].x); \
        *(float2*)&As[buf][ac+1][2*mm] = make_float2(ra[p].y, ra[p].y); \
        *(float2*)&As[buf][ac+2][2*mm] = make_float2(ra[p].z, ra[p].z); \
        *(float2*)&As[buf][ac+3][2*mm] = make_float2(ra[p].w, ra[p].w); \
        Bs[buf][ac+0][mm] = rb[p].x; Bs[buf][ac+1][mm] = rb[p].y; \
        Bs[buf][ac+2][mm] = rb[p].z; Bs[buf][ac+3][mm] = rb[p].w; \
    } } while (0)

#define COMPUTE2(buf) do { \
    _Pragma("unroll") \
    for (int k = 0; k < 16; k++) { \
        u64t a2[8], b2[4]; \
        const u64t* ap = (const u64t*)&As[buf][k][ty*16]; \
        const u64t* bp = (const u64t*)&Bs[buf][k][tx*8]; \
        _Pragma("unroll") \
        for (int i = 0; i < 8; i++) a2[i] = ap[i]; \
        _Pragma("unroll") \
        for (int j = 0; j < 4; j++) b2[j] = bp[j]; \
        _Pragma("unroll") \
        for (int i = 0; i < 8; i++) \
            _Pragma("unroll") \
            for (int j = 0; j < 4; j++) \
                ffma2(acc2[i][j], a2[i], b2[j]); \
    } } while (0)

#define EPILOGUE(OUTPTR, LDC, COLBASE) do { \
    _Pragma("unroll") \
    for (int i = 0; i < 8; i++) { \
        int m = bm + ty*8 + i; \
        _Pragma("unroll") \
        for (int j = 0; j < 4; j += 2) { \
            int n = bn + tx*8 + 2*j; \
            F2u t0, t1; t0.u = acc2[i][j]; t1.u = acc2[i][j+1]; \
            float4 o; \
            o.x = t0.f.x + bias[n+0]; \
            o.y = t0.f.y + bias[n+1]; \
            o.z = t1.f.x + bias[n+2]; \
            o.w = t1.f.y + bias[n+3]; \
            *(float4*)&(OUTPTR)[(size_t)m*(LDC) + (COLBASE) + n] = o; \
        } \
    } } while (0)

__global__ __launch_bounds__(256)
void gemm128_wT(const float* __restrict__ A, const float* __restrict__ W,
                const float* __restrict__ bias, float* __restrict__ C,
                int K, int lda, int ldw, int ldc)
{
    __shared__ __align__(16) float As[2][16][264];
    __shared__ __align__(16) float Bs[2][16][132];
    const int bm = blockIdx.y * 128, bn = blockIdx.x * 128;
    const int tid = threadIdx.x;
    const int ar = tid >> 2, ac = (tid & 3) << 2;
    const int tx = tid & 15, ty = tid >> 4;
    float4 ra[2], rb[2];
    u64t acc2[8][4] = {};

    GL_A(0, 0); GL_A(1, 0); GL_B(0, 0); GL_B(1, 0);
    SST2(0);
    __syncthreads();
    const int nk = K >> 4;
    for (int kb = 0; kb < nk; kb++) {
        if (kb + 1 < nk) {
            int k0 = (kb + 1) << 4;
            GL_A(0, k0); GL_A(1, k0); GL_B(0, k0); GL_B(1, k0);
        }
        int buf = kb & 1;
        COMPUTE2(buf);
        if (kb + 1 < nk) SST2(buf ^ 1);
        __syncthreads();
    }
    EPILOGUE(C, ldc, 0);
}

// =====================================================================
// Conv as implicit GEMM, 128x128x16 double-buffered, FFMA2 math.
// out[m, ccol+o] = sum_{tap,ci} feat[b, t+(tap-3)*dil, ci] * wt[tap][o][ci] + b[o]
// =====================================================================
#define GL_CA(p, tap, ci, off) do { \
    int mm = bm + ar + 64*(p); \
    int bb = mm >> 8, tt = (mm & 255) + (off); \
    if (tt >= 0 && tt < T_) \
        ra[p] = *(const float4*)&feat[((size_t)(bb * T_ + tt))*D_ + (ci)]; \
    else ra[p] = make_float4(0.f, 0.f, 0.f, 0.f); \
    } while (0)
#define GL_CB(p, tap, ci) rb[p] = *(const float4*)&wt[(size_t)(tap)*D_*D_ + (size_t)(bn + ar + 64*(p))*D_ + (ci)]

__global__ __launch_bounds__(256)
void conv128_kernel(const float* __restrict__ feat, const float* __restrict__ wt,
                    const float* __restrict__ bias, float* __restrict__ out,
                    int dil, int ccol)
{
    __shared__ __align__(16) float As[2][16][264];
    __shared__ __align__(16) float Bs[2][16][132];
    const int bm = blockIdx.y * 128, bn = blockIdx.x * 128;
    const int tid = threadIdx.x;
    const int ar = tid >> 2, ac = (tid & 3) << 2;
    const int tx = tid & 15, ty = tid >> 4;
    float4 ra[2], rb[2];
    u64t acc2[8][4] = {};

    {
        int ci = ac, off = -3 * dil;
        GL_CA(0, 0, ci, off); GL_CA(1, 0, ci, off);
        GL_CB(0, 0, ci);      GL_CB(1, 0, ci);
    }
    SST2(0);
    __syncthreads();
    const int nk = KCONV >> 4;            // 448
    for (int kb = 0; kb < nk; kb++) {
        if (kb + 1 < nk) {
            int kk = ((kb + 1) << 4) + ac;
            int tap = kk >> 10, ci = kk & 1023;
            int off = (tap - 3) * dil;
            GL_CA(0, tap, ci, off); GL_CA(1, tap, ci, off);
            GL_CB(0, tap, ci);      GL_CB(1, tap, ci);
        }
        int buf = kb & 1;
        COMPUTE2(buf);
        if (kb + 1 < nk) SST2(buf ^ 1);
        __syncthreads();
    }
    EPILOGUE(out, K5D, ccol);
}

// =====================================================================
// LayerNorm + exact GELU, in place on (2048, 1024). One block per row.
// =====================================================================
__global__ __launch_bounds__(256)
void ln_gelu_kernel(float* __restrict__ z, const float* __restrict__ g,
                    const float* __restrict__ b)
{
    const int row = blockIdx.x;
    const int tid = threadIdx.x;
    float* p = z + (size_t)row * D_;
    float4 v = ((const float4*)p)[tid];
    float s  = v.x + v.y + v.z + v.w;
    float ss = v.x*v.x + v.y*v.y + v.z*v.z + v.w*v.w;
    #pragma unroll
    for (int o = 16; o; o >>= 1) {
        s  += __shfl_xor_sync(0xffffffffu, s,  o);
        ss += __shfl_xor_sync(0xffffffffu, ss, o);
    }
    __shared__ float ws[8], wss[8];
    __shared__ float mu_s, inv_s;
    int lane = tid & 31, wid = tid >> 5;
    if (lane == 0) { ws[wid] = s; wss[wid] = ss; }
    __syncthreads();
    if (tid == 0) {
        float S = 0.f, SS = 0.f;
        #pragma unroll
        for (int i = 0; i < 8; i++) { S += ws[i]; SS += wss[i]; }
        float mu = S * (1.f / D_);
        float var = SS * (1.f / D_) - mu * mu;
        mu_s = mu;
        inv_s = rsqrtf(var + 1e-5f);
    }
    __syncthreads();
    float mu = mu_s, inv = inv_s;
    float4 gg = ((const float4*)g)[tid];
    float4 bb = ((const float4*)b)[tid];
    float y[4] = { (v.x-mu)*inv*gg.x + bb.x, (v.y-mu)*inv*gg.y + bb.y,
                   (v.z-mu)*inv*gg.z + bb.z, (v.w-mu)*inv*gg.w + bb.w };
    float4 o;
    o.x = 0.5f*y[0]*(1.f + erff(y[0]*0.70710678118654752f));
    o.y = 0.5f*y[1]*(1.f + erff(y[1]*0.70710678118654752f));
    o.z = 0.5f*y[2]*(1.f + erff(y[2]*0.70710678118654752f));
    o.w = 0.5f*y[3]*(1.f + erff(y[3]*0.70710678118654752f));
    ((float4*)p)[tid] = o;
}

// =====================================================================
// Attention scores: S[bh, m, n] = 0.125 * sum_d q[b,m,h,d] k[b,n,h,d]
// =====================================================================
__global__ __launch_bounds__(256)
void attn_scores_kernel(const float* __restrict__ q, const float* __restrict__ kmat,
                        float* __restrict__ s)
{
    const int bh = blockIdx.z;
    const int b = bh >> 4, h = bh & 15;
    const int bm = blockIdx.y * 64, bn = blockIdx.x * 64;
    __shared__ __align__(16) float As[16][68];
    __shared__ __align__(16) float Bs[16][68];
    const int tid = threadIdx.x;
    const int lk = tid & 15, lr = tid >> 4;
    const int tx = tid & 15, ty = tid >> 4;
    float acc[4][4] = {};
    for (int k0 = 0; k0 < DH; k0 += 16) {
        #pragma unroll
        for (int p = 0; p < 4; p++) {
            int m = bm + lr + 16*p;
            As[lk][lr+16*p] = q[((size_t)(b*T_ + m))*D_ + h*DH + k0 + lk];
        }
        #pragma unroll
        for (int p = 0; p < 4; p++) {
            int n = bn + lr + 16*p;
            Bs[lk][lr+16*p] = kmat[((size_t)(b*T_ + n))*D_ + h*DH + k0 + lk];
        }
        __syncthreads();
        #pragma unroll
        for (int k = 0; k < 16; k++) {
            float a[4], bb[4];
            *(float4*)a  = *(const float4*)&As[k][ty*4];
            *(float4*)bb = *(const float4*)&Bs[k][tx*4];
            #pragma unroll
            for (int i = 0; i < 4; i++)
                #pragma unroll
                for (int j = 0; j < 4; j++)
                    acc[i][j] += a[i]*bb[j];
        }
        __syncthreads();
    }
    #pragma unroll
    for (int i = 0; i < 4; i++) {
        int m = bm + ty*4 + i;
        #pragma unroll
        for (int j = 0; j < 4; j++) {
            int n = bn + tx*4 + j;
            s[((size_t)bh*T_ + m)*T_ + n] = acc[i][j] * 0.125f;
        }
    }
}

// Row softmax over 256 entries. One warp per row.
__global__ __launch_bounds__(256)
void softmax_kernel(float* __restrict__ s)
{
    int row  = (blockIdx.x * blockDim.x + threadIdx.x) >> 5;
    int lane = threadIdx.x & 31;
    float* p = s + (size_t)row * T_;
    float v[8];
    float m = -1e30f;
    #pragma unroll
    for (int r = 0; r < 8; r++) { v[r] = p[lane + 32*r]; m = fmaxf(m, v[r]); }
    #pragma unroll
    for (int o = 16; o; o >>= 1) m = fmaxf(m, __shfl_xor_sync(0xffffffffu, m, o));
    float sum = 0.f;
    #pragma unroll
    for (int r = 0; r < 8; r++) { v[r] = __expf(v[r] - m); sum += v[r]; }
    #pragma unroll
    for (int o = 16; o; o >>= 1) sum += __shfl_xor_sync(0xffffffffu, sum, o);
    float inv = 1.f / sum;
    #pragma unroll
    for (int r = 0; r < 8; r++) p[lane + 32*r] = v[r] * inv;
}

// ctx[b,m,h,d] = sum_k P[bh,m,k] v[b,k,h,d]   (BN = 64 = full head dim)
__global__ __launch_bounds__(256)
void attn_ctx_kernel(const float* __restrict__ s, const float* __restrict__ v,
                     float* __restrict__ ctx)
{
    const int bh = blockIdx.z;
    const int b = bh >> 4, h = bh & 15;
    const int bm = blockIdx.y * 64;
    __shared__ __align__(16) float As[16][68];
    __shared__ __align__(16) float Bs[16][68];
    const int tid = threadIdx.x;
    const int lk = tid & 15, lr = tid >> 4;
    const int bn_ = tid & 63, bkk = tid >> 6;
    const int tx = tid & 15, ty = tid >> 4;
    float acc[4][4] = {};
    for (int k0 = 0; k0 < T_; k0 += 16) {
        #pragma unroll
        for (int p = 0; p < 4; p++) {
            int m = bm + lr + 16*p;
            As[lk][lr+16*p] = s[((size_t)bh*T_ + m)*T_ + k0 + lk];
        }
        #pragma unroll
        for (int p = 0; p < 4; p++) {
            int jj = bkk + 4*p;
            Bs[jj][bn_] = v[((size_t)(b*T_ + k0 + jj))*D_ + h*DH + bn_];
        }
        __syncthreads();
        #pragma unroll
        for (int k = 0; k < 16; k++) {
            float a[4], bb[4];
            *(float4*)a  = *(const float4*)&As[k][ty*4];
            *(float4*)bb = *(const float4*)&Bs[k][tx*4];
            #pragma unroll
            for (int i = 0; i < 4; i++)
                #pragma unroll
                for (int j = 0; j < 4; j++)
                    acc[i][j] += a[i]*bb[j];
        }
        __syncthreads();
    }
    #pragma unroll
    for (int i = 0; i < 4; i++) {
        int m = bm + ty*4 + i;
        #pragma unroll
        for (int j = 0; j < 4; j++)
            ctx[((size_t)(b*T_ + m))*D_ + h*DH + tx*4 + j] = acc[i][j];
    }
}

// =====================================================================
// GAT: e1/e2 per (node, head); one warp each.
// =====================================================================
__global__ __launch_bounds__(256)
void e12_kernel(const float* __restrict__ hg, const float* __restrict__ a1,
                const float* __restrict__ a2, float* __restrict__ e1,
                float* __restrict__ e2)
{
    int wid  = (blockIdx.x * blockDim.x + threadIdx.x) >> 5;
    int lane = threadIdx.x & 31;
    int n = wid >> 3, h = wid & 7;
    const float* row = hg + (size_t)n * D_ + h * GDH;
    float s1 = 0.f, s2 = 0.f;
    #pragma unroll
    for (int r = 0; r < 4; r++) {
        float x = row[lane + 32*r];
        s1 += x * a1[lane + 32*r];
        s2 += x * a2[lane + 32*r];
    }
    #pragma unroll
    for (int o = 16; o; o >>= 1) {
        s1 += __shfl_xor_sync(0xffffffffu, s1, o);
        s2 += __shfl_xor_sync(0xffffffffu, s2, o);
    }
    if (lane == 0) { e1[n*HGAT + h] = s1; e2[n*HGAT + h] = s2; }
}

__global__ __launch_bounds__(256)
void e2max_kernel(const float* __restrict__ e2, float* __restrict__ m2)
{
    int h = blockIdx.x, tid = threadIdx.x;
    float m = -1e30f;
    for (int n = tid; n < M_; n += 256) m = fmaxf(m, e2[n*HGAT + h]);
    __shared__ float sm[256];
    sm[tid] = m; __syncthreads();
    for (int s = 128; s > 0; s >>= 1) {
        if (tid < s) sm[tid] = fmaxf(sm[tid], sm[tid + s]);
        __syncthreads();
    }
    if (tid == 0) m2[h] = sm[0];
}

// =====================================================================
// GAT aggregation GEMM with on-the-fly alpha, fused denom + ELU + residual.
// =====================================================================
__global__ __launch_bounds__(256)
void gat_gemm_kernel(const float* __restrict__ hg, const float* __restrict__ e1,
                     const float* __restrict__ e2, const float* __restrict__ m2,
                     const float* __restrict__ feat, float* __restrict__ out)
{
    const int h  = blockIdx.x;
    const int bm = blockIdx.y * 64;
    __shared__ __align__(16) float As[16][68];
    __shared__ __align__(16) float Bs[16][136];
    __shared__ float se1[64], smrow[64];
    const int tid = threadIdx.x;
    if (tid < 64) {
        float v1 = e1[(bm + tid)*HGAT + h];
        float s = v1 + m2[h];
        smrow[tid] = s > 0.f ? s : 0.2f * s;
        se1[tid] = v1;
    }
    __syncthreads();
    const int lk = tid & 15, lr = tid >> 4;
    const int bd = tid & 127, bj = tid >> 7;
    const int tx = tid & 15, ty = tid >> 4;
    float acc[4][8] = {};
    float dacc[4] = {};
    for (int k0 = 0; k0 < M_; k0 += 16) {
        float e2v = e2[(k0 + lk)*HGAT + h];
        #pragma unroll
        for (int p = 0; p < 4; p++) {
            int i = lr + 16*p;
            float s = se1[i] + e2v;
            float l = s > 0.f ? s : 0.2f * s;
            As[lk][i] = __expf(l - smrow[i]);
        }
        #pragma unroll
        for (int p = 0; p < 8; p++) {
            int jj = bj + 2*p;
            Bs[jj][bd] = hg[(size_t)(k0 + jj)*D_ + h*GDH + bd];
        }
        __syncthreads();
        #pragma unroll
        for (int k = 0; k < 16; k++) {
            float a[4], b[8];
            *(float4*)a      = *(const float4*)&As[k][ty*4];
            *(float4*)&b[0]  = *(const float4*)&Bs[k][tx*8];
            *(float4*)&b[4]  = *(const float4*)&Bs[k][tx*8 + 4];
            #pragma unroll
            for (int i = 0; i < 4; i++) {
                dacc[i] += a[i];
                #pragma unroll
                for (int j = 0; j < 8; j++)
                    acc[i][j] += a[i]*b[j];
            }
        }
        __syncthreads();
    }
    #pragma unroll
    for (int i = 0; i < 4; i++) {
        int m = bm + ty*4 + i;
        float inv = 1.f / dacc[i];
        #pragma unroll
        for (int j = 0; j < 8; j++) {
            float v = acc[i][j] * inv;
            v = v > 0.f ? v : expm1f(v);                 // ELU
            int col = h*GDH + tx*8 + j;
            out[(size_t)m*D_ + col] = v + feat[(size_t)m*D_ + col];
        }
    }
}

// =====================================================================
extern "C" void kernel_launch(void* const* d_in, const int* in_sizes, int n_in,
                              void* d_out, int out_size)
{
    const float* feat = (const float*)d_in[0];

    // Bind conv weights/biases by SIZE (robust to interleaved or grouped order).
    const float* cw[5];
    const float* cb[5];
    int wi = 0, bi = 0;
    for (int i = 1; i <= 10; i++) {
        if (in_sizes[i] == D_ * D_ * KW) { if (wi < 5) cw[wi++] = (const float*)d_in[i]; }
        else                             { if (bi < 5) cb[bi++] = (const float*)d_in[i]; }
    }

    const float* fp_w = (const float*)d_in[11];
    const float* fp_b = (const float*)d_in[12];
    const float* ln_g = (const float*)d_in[13];
    const float* ln_b = (const float*)d_in[14];
    const float* wq = (const float*)d_in[15];
    const float* bq = (const float*)d_in[16];
    const float* wk = (const float*)d_in[17];
    const float* bk = (const float*)d_in[18];
    const float* wv = (const float*)d_in[19];
    const float* bv = (const float*)d_in[20];
    const float* wo = (const float*)d_in[21];
    const float* bo = (const float*)d_in[22];
    const float* gat_w = (const float*)d_in[23];
    const float* gat_b = (const float*)d_in[24];
    const float* a1 = (const float*)d_in[25];
    const float* a2 = (const float*)d_in[26];
    float* out = (float*)d_out;

    float *wt, *ms, *z, *q, *k, *v, *s, *ctx, *att, *hg, *e1, *e2, *m2;
    cudaGetSymbolAddress((void**)&wt,  g_wt);
    cudaGetSymbolAddress((void**)&ms,  g_ms);
    cudaGetSymbolAddress((void**)&z,   g_z);
    cudaGetSymbolAddress((void**)&q,   g_q);
    cudaGetSymbolAddress((void**)&k,   g_k);
    cudaGetSymbolAddress((void**)&v,   g_v);
    cudaGetSymbolAddress((void**)&s,   g_s);
    cudaGetSymbolAddress((void**)&ctx, g_ctx);
    cudaGetSymbolAddress((void**)&att, g_att);
    cudaGetSymbolAddress((void**)&hg,  g_hg);
    cudaGetSymbolAddress((void**)&e1,  g_e1);
    cudaGetSymbolAddress((void**)&e2,  g_e2);
    cudaGetSymbolAddress((void**)&m2,  g_m2);

    const int dil[5] = {1, 2, 4, 8, 16};
    const int WTN = KW * D_ * D_;                    // 7,340,032 per conv

    // 0) transform conv weights to [tap][o][ci] (coalesced GEMM loads)
    for (int c = 0; c < 5; c++)
        wtrans_kernel<<<WTN / 256, 256>>>(cw[c], wt + (size_t)c * WTN);

    // 1) dilated convs -> g_ms (2048, 5120)
    for (int c = 0; c < 5; c++)
        conv128_kernel<<<dim3(8, 16), 256>>>(feat, wt + (size_t)c * WTN, cb[c], ms,
                                             dil[c], c*D_);

    // 2) fusion projection (K=5120) -> g_z, then LN+GELU in place
    gemm128_wT<<<dim3(8, 16), 256>>>(ms, fp_w, fp_b, z, K5D, K5D, K5D, D_);
    ln_gelu_kernel<<<M_, 256>>>(z, ln_g, ln_b);

    // 3) q, k, v projections
    gemm128_wT<<<dim3(8, 16), 256>>>(z, wq, bq, q, D_, D_, D_, D_);
    gemm128_wT<<<dim3(8, 16), 256>>>(z, wk, bk, k, D_, D_, D_, D_);
    gemm128_wT<<<dim3(8, 16), 256>>>(z, wv, bv, v, D_, D_, D_, D_);

    // 4) attention
    attn_scores_kernel<<<dim3(4, 4, B_*HMHA), 256>>>(q, k, s);
    softmax_kernel<<<(B_*HMHA*T_)/8, 256>>>(s);
    attn_ctx_kernel<<<dim3(1, 4, B_*HMHA), 256>>>(s, v, ctx);

    // 5) output projection, GAT projection
    gemm128_wT<<<dim3(8, 16), 256>>>(ctx, wo, bo, att, D_, D_, D_, D_);
    gemm128_wT<<<dim3(8, 16), 256>>>(att, gat_w, gat_b, hg, D_, D_, D_, D_);

    // 6) GAT attention logits + stable max
    e12_kernel<<<(M_*HGAT)/8, 256>>>(hg, a1, a2, e1, e2);
    e2max_kernel<<<HGAT, 256>>>(e2, m2);

    // 7) GAT aggregation + ELU + residual -> d_out
    gat_gemm_kernel<<<dim3(HGAT, 32), 256>>>(hg, e1, e2, m2, feat, out);
}

// round 6
// speedup vs baseline: 2.7718x; 2.7718x over previous
#include <cuda_runtime.h>
#include <cuda_bf16.h>
#include <math.h>
#include <stdint.h>

#define D_   1024
#define T_   256
#define B_   8
#define M_   (B_*T_)        // 2048 rows (b,t)
#define HMHA 16
#define DH   64
#define HGAT 8
#define GDH  128
#define KW   7
#define K5D  (5*D_)
#define KCONV (KW*D_)       // 7168

#define KC     32                   // K per chunk (bf16)
#define ROWB   80                   // bytes per smem row (32 bf16 + 8 pad)
#define TILE_B (128*ROWB)           // 10240 B per tile
#define SMEM_DYN (2*4*TILE_B)       // 81920 B (double buffer x 4 tiles)

// ===================== PTX helpers (baseline ISA only) =====================
__device__ __forceinline__ uint32_t smem_u32(const void* p) {
    uint32_t a;
    asm("{ .reg .u64 t; cvta.to.shared.u64 t, %1; cvt.u32.u64 %0, t; }"
        : "=r"(a) : "l"(p));
    return a;
}
#define CP16(dst, src, sz) \
    asm volatile("cp.async.cg.shared.global [%0], [%1], 16, %2;" \
                 :: "r"(dst), "l"(src), "r"(sz))
#define CP_COMMIT() asm volatile("cp.async.commit_group;" ::: "memory")
#define CP_WAIT1()  asm volatile("cp.async.wait_group 1;" ::: "memory")
#define CP_WAIT0()  asm volatile("cp.async.wait_group 0;" ::: "memory")

#define LDMX4(r, addr) \
    asm volatile("ldmatrix.sync.aligned.m8n8.x4.shared.b16 {%0,%1,%2,%3}, [%4];" \
        : "=r"((r)[0]), "=r"((r)[1]), "=r"((r)[2]), "=r"((r)[3]) : "r"(addr))
#define LDMX2(r, addr) \
    asm volatile("ldmatrix.sync.aligned.m8n8.x2.shared.b16 {%0,%1}, [%2];" \
        : "=r"((r)[0]), "=r"((r)[1]) : "r"(addr))

#define MMA16816(c, a, b) \
    asm volatile("mma.sync.aligned.m16n8k16.row.col.f32.bf16.bf16.f32 " \
        "{%0,%1,%2,%3}, {%4,%5,%6,%7}, {%8,%9}, {%0,%1,%2,%3};" \
        : "+f"((c)[0]), "+f"((c)[1]), "+f"((c)[2]), "+f"((c)[3]) \
        : "r"((a)[0]), "r"((a)[1]), "r"((a)[2]), "r"((a)[3]), \
          "r"((b)[0]), "r"((b)[1]))

// ---------------- scratch (device globals; no allocation) ----------------
__device__ __nv_bfloat16 g_fh [M_ * D_];           // feat hi
__device__ __nv_bfloat16 g_fl [M_ * D_];           // feat lo
__device__ __nv_bfloat16 g_wth[5 * KW * D_ * D_];  // conv weights hi [c][tap][o][ci]
__device__ __nv_bfloat16 g_wtl[5 * KW * D_ * D_];
__device__ __nv_bfloat16 g_fph[D_ * K5D];
__device__ __nv_bfloat16 g_fpl[D_ * K5D];
__device__ __nv_bfloat16 g_dwh[5 * D_ * D_];       // wq,wk,wv,wo,gat_w hi
__device__ __nv_bfloat16 g_dwl[5 * D_ * D_];
__device__ float g_ms [M_ * K5D];
__device__ __nv_bfloat16 g_msh[M_ * K5D];
__device__ __nv_bfloat16 g_msl[M_ * K5D];
__device__ float g_z  [M_ * D_];
__device__ __nv_bfloat16 g_zh [M_ * D_];
__device__ __nv_bfloat16 g_zl [M_ * D_];
__device__ float g_q  [M_ * D_];
__device__ float g_k  [M_ * D_];
__device__ float g_v  [M_ * D_];
__device__ float g_s  [B_*HMHA * T_ * T_];
__device__ float g_ctx[M_ * D_];
__device__ __nv_bfloat16 g_cxh[M_ * D_];
__device__ __nv_bfloat16 g_cxl[M_ * D_];
__device__ float g_att[M_ * D_];
__device__ __nv_bfloat16 g_ath[M_ * D_];
__device__ __nv_bfloat16 g_atl[M_ * D_];
__device__ float g_hg [M_ * D_];
__device__ float g_e1[M_ * HGAT];
__device__ float g_e2[M_ * HGAT];
__device__ float g_m2[HGAT];

// =====================================================================
// fp32 -> (bf16 hi, bf16 lo)
// =====================================================================
__global__ __launch_bounds__(256)
void cvt_pair_kernel(const float* __restrict__ src, __nv_bfloat16* __restrict__ hi,
                     __nv_bfloat16* __restrict__ lo, int n4)
{
    int i = blockIdx.x * 256 + threadIdx.x;
    if (i >= n4) return;
    float4 v = ((const float4*)src)[i];
    __nv_bfloat16 h0 = __float2bfloat16(v.x), h1 = __float2bfloat16(v.y);
    __nv_bfloat16 h2 = __float2bfloat16(v.z), h3 = __float2bfloat16(v.w);
    __nv_bfloat16 l0 = __float2bfloat16(v.x - __bfloat162float(h0));
    __nv_bfloat16 l1 = __float2bfloat16(v.y - __bfloat162float(h1));
    __nv_bfloat16 l2 = __float2bfloat16(v.z - __bfloat162float(h2));
    __nv_bfloat16 l3 = __float2bfloat16(v.w - __bfloat162float(h3));
    __nv_bfloat162* ph = (__nv_bfloat162*)hi;
    __nv_bfloat162* pl = (__nv_bfloat162*)lo;
    ph[2*i]   = __nv_bfloat162(h0, h1);
    ph[2*i+1] = __nv_bfloat162(h2, h3);
    pl[2*i]   = __nv_bfloat162(l0, l1);
    pl[2*i+1] = __nv_bfloat162(l2, l3);
}

// =====================================================================
// conv weight transform + split: wt[tap][o][ci] (hi/lo) from w[o][ci*7+tap]
// =====================================================================
__global__ __launch_bounds__(256)
void wtrans_pair_kernel(const float* __restrict__ w, __nv_bfloat16* __restrict__ wh,
                        __nv_bfloat16* __restrict__ wl)
{
    int idx = blockIdx.x * 256 + threadIdx.x;      // over 7*1024*1024
    int tap = idx >> 20;
    int rem = idx & ((1 << 20) - 1);
    int o  = rem >> 10;
    int ci = rem & 1023;
    float x = __ldg(&w[(size_t)o * KCONV + ci * 7 + tap]);
    __nv_bfloat16 h = __float2bfloat16(x);
    wh[idx] = h;
    wl[idx] = __float2bfloat16(x - __bfloat162float(h));
}

// =====================================================================
// Warp-level HMMA compute on one 128x128 CTA tile, one K-chunk (32).
// Tiles in smem: 0=Ah, 1=Al, 2=Bh, 3=Bl; rows padded to 80B.
// =====================================================================
__device__ __forceinline__
void hmma_chunk(uint32_t bufu, int wm, int wn, int lane, float acc[4][4][4])
{
    #pragma unroll
    for (int kk = 0; kk < 32; kk += 16) {
        uint32_t bh[4][2], bl[4][2];
        #pragma unroll
        for (int j = 0; j < 4; j++) {
            int nrow = wn*32 + j*8 + (lane & 7);
            int colb = (kk + ((lane >> 3) & 1)*8) * 2;
            LDMX2(bh[j], bufu + 2*TILE_B + nrow*ROWB + colb);
            LDMX2(bl[j], bufu + 3*TILE_B + nrow*ROWB + colb);
        }
        #pragma unroll
        for (int i = 0; i < 4; i++) {
            int mrow = wm*64 + i*16 + (lane & 15);
            int colb = (kk + ((lane >> 4) & 1)*8) * 2;
            uint32_t ah[4], al[4];
            LDMX4(ah, bufu + 0*TILE_B + mrow*ROWB + colb);
            LDMX4(al, bufu + 1*TILE_B + mrow*ROWB + colb);
            #pragma unroll
            for (int j = 0; j < 4; j++) {
                MMA16816(acc[i][j], ah, bh[j]);
                MMA16816(acc[i][j], ah, bl[j]);
                MMA16816(acc[i][j], al, bh[j]);
            }
        }
    }
}

__device__ __forceinline__
void hmma_epilogue(float acc[4][4][4], const float* __restrict__ bias,
                   float* __restrict__ C, int bm, int bn, int ldc, int colbase,
                   int wm, int wn, int lane)
{
    #pragma unroll
    for (int i = 0; i < 4; i++) {
        int m0 = bm + wm*64 + i*16 + (lane >> 2);
        #pragma unroll
        for (int j = 0; j < 4; j++) {
            int n0 = wn*32 + j*8 + (lane & 3)*2;
            float b0 = bias[bn + n0], b1 = bias[bn + n0 + 1];
            float2 v01 = make_float2(acc[i][j][0] + b0, acc[i][j][1] + b1);
            float2 v23 = make_float2(acc[i][j][2] + b0, acc[i][j][3] + b1);
            *(float2*)&C[(size_t)m0*ldc + colbase + bn + n0] = v01;
            *(float2*)&C[(size_t)(m0+8)*ldc + colbase + bn + n0] = v23;
        }
    }
}

// ---- dense: A[m][k], W[n][k] (bf16 hi/lo), K multiple of 32 ----
__global__ __launch_bounds__(256)
void hmma_gemm_kernel(const __nv_bfloat16* __restrict__ Ah, const __nv_bfloat16* __restrict__ Al,
                      const __nv_bfloat16* __restrict__ Wh, const __nv_bfloat16* __restrict__ Wl,
                      const float* __restrict__ bias, float* __restrict__ C,
                      int K, int ldc)
{
    extern __shared__ __align__(16) char smem_raw[];
    const uint32_t smem_base = smem_u32(smem_raw);
    const int bm = blockIdx.y * 128, bn = blockIdx.x * 128;
    const int tid = threadIdx.x;
    const int wid = tid >> 5, lane = tid & 31;
    const int wm = wid & 1, wn = wid >> 1;
    float acc[4][4][4] = {};

#define ISSUE_D(c) do { \
    int k0 = (c) << 5; \
    uint32_t bufu = smem_base + ((c) & 1) * 4*TILE_B; \
    _Pragma("unroll") \
    for (int it = 0; it < 8; it++) { \
        int g = tid + it*256; \
        int tile = g >> 9; \
        int ct = g & 511; int row = ct >> 2, cc = ct & 3; \
        const __nv_bfloat16* src; \
        if      (tile == 0) src = Ah + (size_t)(bm+row)*K + k0 + cc*8; \
        else if (tile == 1) src = Al + (size_t)(bm+row)*K + k0 + cc*8; \
        else if (tile == 2) src = Wh + (size_t)(bn+row)*K + k0 + cc*8; \
        else                src = Wl + (size_t)(bn+row)*K + k0 + cc*8; \
        CP16(bufu + tile*TILE_B + row*ROWB + cc*16, src, 16); \
    } \
    CP_COMMIT(); } while (0)

    const int nc = K >> 5;
    ISSUE_D(0);
    for (int c = 0; c < nc; c++) {
        if (c + 1 < nc) { ISSUE_D(c + 1); CP_WAIT1(); }
        else           { CP_WAIT0(); }
        __syncthreads();
        hmma_chunk(smem_base + (c & 1)*4*TILE_B, wm, wn, lane, acc);
        __syncthreads();
    }
#undef ISSUE_D
    hmma_epilogue(acc, bias, C, bm, bn, ldc, 0, wm, wn, lane);
}

// ---- conv: A gathered from feat hi/lo (zero-fill OOB), W = [tap][o][ci] ----
__global__ __launch_bounds__(256)
void hmma_conv_kernel(const __nv_bfloat16* __restrict__ Fh, const __nv_bfloat16* __restrict__ Fl,
                      const __nv_bfloat16* __restrict__ Wh, const __nv_bfloat16* __restrict__ Wl,
                      const float* __restrict__ bias, float* __restrict__ out,
                      int dil, int ccol)
{
    extern __shared__ __align__(16) char smem_raw[];
    const uint32_t smem_base = smem_u32(smem_raw);
    const int bm = blockIdx.y * 128, bn = blockIdx.x * 128;
    const int tid = threadIdx.x;
    const int wid = tid >> 5, lane = tid & 31;
    const int wm = wid & 1, wn = wid >> 1;
    float acc[4][4][4] = {};

#define ISSUE_C(c) do { \
    int k0 = (c) << 5; \
    int tap = k0 >> 10, ci0 = k0 & 1023; \
    int offt = (tap - 3) * dil; \
    uint32_t bufu = smem_base + ((c) & 1) * 4*TILE_B; \
    _Pragma("unroll") \
    for (int it = 0; it < 8; it++) { \
        int g = tid + it*256; \
        int tile = g >> 9; \
        int ct = g & 511; int row = ct >> 2, cc = ct & 3; \
        const __nv_bfloat16* src; \
        uint32_t sz = 16; \
        if (tile <= 1) { \
            int m = bm + row; \
            int bb = m >> 8, tt = (m & 255) + offt; \
            if (tt >= 0 && tt < T_) \
                src = (tile == 0 ? Fh : Fl) + ((size_t)(bb*T_ + tt))*D_ + ci0 + cc*8; \
            else { src = Fh; sz = 0; } \
        } else { \
            src = (tile == 2 ? Wh : Wl) + (size_t)tap*D_*D_ + (size_t)(bn+row)*D_ + ci0 + cc*8; \
        } \
        CP16(bufu + tile*TILE_B + row*ROWB + cc*16, src, sz); \
    } \
    CP_COMMIT(); } while (0)

    const int nc = KCONV >> 5;        // 224
    ISSUE_C(0);
    for (int c = 0; c < nc; c++) {
        if (c + 1 < nc) { ISSUE_C(c + 1); CP_WAIT1(); }
        else           { CP_WAIT0(); }
        __syncthreads();
        hmma_chunk(smem_base + (c & 1)*4*TILE_B, wm, wn, lane, acc);
        __syncthreads();
    }
#undef ISSUE_C
    hmma_epilogue(acc, bias, out, bm, bn, K5D, ccol, wm, wn, lane);
}

// =====================================================================
// LayerNorm + exact GELU, in place on (2048, 1024). One block per row.
// =====================================================================
__global__ __launch_bounds__(256)
void ln_gelu_kernel(float* __restrict__ z, const float* __restrict__ g,
                    const float* __restrict__ b)
{
    const int row = blockIdx.x;
    const int tid = threadIdx.x;
    float* p = z + (size_t)row * D_;
    float4 v = ((const float4*)p)[tid];
    float s  = v.x + v.y + v.z + v.w;
    float ss = v.x*v.x + v.y*v.y + v.z*v.z + v.w*v.w;
    #pragma unroll
    for (int o = 16; o; o >>= 1) {
        s  += __shfl_xor_sync(0xffffffffu, s,  o);
        ss += __shfl_xor_sync(0xffffffffu, ss, o);
    }
    __shared__ float ws[8], wss[8];
    __shared__ float mu_s, inv_s;
    int lane = tid & 31, wid = tid >> 5;
    if (lane == 0) { ws[wid] = s; wss[wid] = ss; }
    __syncthreads();
    if (tid == 0) {
        float S = 0.f, SS = 0.f;
        #pragma unroll
        for (int i = 0; i < 8; i++) { S += ws[i]; SS += wss[i]; }
        float mu = S * (1.f / D_);
        float var = SS * (1.f / D_) - mu * mu;
        mu_s = mu;
        inv_s = rsqrtf(var + 1e-5f);
    }
    __syncthreads();
    float mu = mu_s, inv = inv_s;
    float4 gg = ((const float4*)g)[tid];
    float4 bb = ((const float4*)b)[tid];
    float y[4] = { (v.x-mu)*inv*gg.x + bb.x, (v.y-mu)*inv*gg.y + bb.y,
                   (v.z-mu)*inv*gg.z + bb.z, (v.w-mu)*inv*gg.w + bb.w };
    float4 o;
    o.x = 0.5f*y[0]*(1.f + erff(y[0]*0.70710678118654752f));
    o.y = 0.5f*y[1]*(1.f + erff(y[1]*0.70710678118654752f));
    o.z = 0.5f*y[2]*(1.f + erff(y[2]*0.70710678118654752f));
    o.w = 0.5f*y[3]*(1.f + erff(y[3]*0.70710678118654752f));
    ((float4*)p)[tid] = o;
}

// =====================================================================
// Attention (fp32 SIMT; ~2 GF total)
// =====================================================================
__global__ __launch_bounds__(256)
void attn_scores_kernel(const float* __restrict__ q, const float* __restrict__ kmat,
                        float* __restrict__ s)
{
    const int bh = blockIdx.z;
    const int b = bh >> 4, h = bh & 15;
    const int bm = blockIdx.y * 64, bn = blockIdx.x * 64;
    __shared__ __align__(16) float As[16][68];
    __shared__ __align__(16) float Bs[16][68];
    const int tid = threadIdx.x;
    const int lk = tid & 15, lr = tid >> 4;
    const int tx = tid & 15, ty = tid >> 4;
    float acc[4][4] = {};
    for (int k0 = 0; k0 < DH; k0 += 16) {
        #pragma unroll
        for (int p = 0; p < 4; p++) {
            int m = bm + lr + 16*p;
            As[lk][lr+16*p] = q[((size_t)(b*T_ + m))*D_ + h*DH + k0 + lk];
        }
        #pragma unroll
        for (int p = 0; p < 4; p++) {
            int n = bn + lr + 16*p;
            Bs[lk][lr+16*p] = kmat[((size_t)(b*T_ + n))*D_ + h*DH + k0 + lk];
        }
        __syncthreads();
        #pragma unroll
        for (int k = 0; k < 16; k++) {
            float a[4], bb[4];
            *(float4*)a  = *(const float4*)&As[k][ty*4];
            *(float4*)bb = *(const float4*)&Bs[k][tx*4];
            #pragma unroll
            for (int i = 0; i < 4; i++)
                #pragma unroll
                for (int j = 0; j < 4; j++)
                    acc[i][j] += a[i]*bb[j];
        }
        __syncthreads();
    }
    #pragma unroll
    for (int i = 0; i < 4; i++) {
        int m = bm + ty*4 + i;
        #pragma unroll
        for (int j = 0; j < 4; j++) {
            int n = bn + tx*4 + j;
            s[((size_t)bh*T_ + m)*T_ + n] = acc[i][j] * 0.125f;
        }
    }
}

__global__ __launch_bounds__(256)
void softmax_kernel(float* __restrict__ s)
{
    int row  = (blockIdx.x * blockDim.x + threadIdx.x) >> 5;
    int lane = threadIdx.x & 31;
    float* p = s + (size_t)row * T_;
    float v[8];
    float m = -1e30f;
    #pragma unroll
    for (int r = 0; r < 8; r++) { v[r] = p[lane + 32*r]; m = fmaxf(m, v[r]); }
    #pragma unroll
    for (int o = 16; o; o >>= 1) m = fmaxf(m, __shfl_xor_sync(0xffffffffu, m, o));
    float sum = 0.f;
    #pragma unroll
    for (int r = 0; r < 8; r++) { v[r] = __expf(v[r] - m); sum += v[r]; }
    #pragma unroll
    for (int o = 16; o; o >>= 1) sum += __shfl_xor_sync(0xffffffffu, sum, o);
    float inv = 1.f / sum;
    #pragma unroll
    for (int r = 0; r < 8; r++) p[lane + 32*r] = v[r] * inv;
}

__global__ __launch_bounds__(256)
void attn_ctx_kernel(const float* __restrict__ s, const float* __restrict__ v,
                     float* __restrict__ ctx)
{
    const int bh = blockIdx.z;
    const int b = bh >> 4, h = bh & 15;
    const int bm = blockIdx.y * 64;
    __shared__ __align__(16) float As[16][68];
    __shared__ __align__(16) float Bs[16][68];
    const int tid = threadIdx.x;
    const int lk = tid & 15, lr = tid >> 4;
    const int bn_ = tid & 63, bkk = tid >> 6;
    const int tx = tid & 15, ty = tid >> 4;
    float acc[4][4] = {};
    for (int k0 = 0; k0 < T_; k0 += 16) {
        #pragma unroll
        for (int p = 0; p < 4; p++) {
            int m = bm + lr + 16*p;
            As[lk][lr+16*p] = s[((size_t)bh*T_ + m)*T_ + k0 + lk];
        }
        #pragma unroll
        for (int p = 0; p < 4; p++) {
            int jj = bkk + 4*p;
            Bs[jj][bn_] = v[((size_t)(b*T_ + k0 + jj))*D_ + h*DH + bn_];
        }
        __syncthreads();
        #pragma unroll
        for (int k = 0; k < 16; k++) {
            float a[4], bb[4];
            *(float4*)a  = *(const float4*)&As[k][ty*4];
            *(float4*)bb = *(const float4*)&Bs[k][tx*4];
            #pragma unroll
            for (int i = 0; i < 4; i++)
                #pragma unroll
                for (int j = 0; j < 4; j++)
                    acc[i][j] += a[i]*bb[j];
        }
        __syncthreads();
    }
    #pragma unroll
    for (int i = 0; i < 4; i++) {
        int m = bm + ty*4 + i;
        #pragma unroll
        for (int j = 0; j < 4; j++)
            ctx[((size_t)(b*T_ + m))*D_ + h*DH + tx*4 + j] = acc[i][j];
    }
}

// =====================================================================
// GAT pieces (fp32)
// =====================================================================
__global__ __launch_bounds__(256)
void e12_kernel(const float* __restrict__ hg, const float* __restrict__ a1,
                const float* __restrict__ a2, float* __restrict__ e1,
                float* __restrict__ e2)
{
    int wid  = (blockIdx.x * blockDim.x + threadIdx.x) >> 5;
    int lane = threadIdx.x & 31;
    int n = wid >> 3, h = wid & 7;
    const float* row = hg + (size_t)n * D_ + h * GDH;
    float s1 = 0.f, s2 = 0.f;
    #pragma unroll
    for (int r = 0; r < 4; r++) {
        float x = row[lane + 32*r];
        s1 += x * a1[lane + 32*r];
        s2 += x * a2[lane + 32*r];
    }
    #pragma unroll
    for (int o = 16; o; o >>= 1) {
        s1 += __shfl_xor_sync(0xffffffffu, s1, o);
        s2 += __shfl_xor_sync(0xffffffffu, s2, o);
    }
    if (lane == 0) { e1[n*HGAT + h] = s1; e2[n*HGAT + h] = s2; }
}

__global__ __launch_bounds__(256)
void e2max_kernel(const float* __restrict__ e2, float* __restrict__ m2)
{
    int h = blockIdx.x, tid = threadIdx.x;
    float m = -1e30f;
    for (int n = tid; n < M_; n += 256) m = fmaxf(m, e2[n*HGAT + h]);
    __shared__ float sm[256];
    sm[tid] = m; __syncthreads();
    for (int s = 128; s > 0; s >>= 1) {
        if (tid < s) sm[tid] = fmaxf(sm[tid], sm[tid + s]);
        __syncthreads();
    }
    if (tid == 0) m2[h] = sm[0];
}

__global__ __launch_bounds__(256)
void gat_gemm_kernel(const float* __restrict__ hg, const float* __restrict__ e1,
                     const float* __restrict__ e2, const float* __restrict__ m2,
                     const float* __restrict__ feat, float* __restrict__ out)
{
    const int h  = blockIdx.x;
    const int bm = blockIdx.y * 64;
    __shared__ __align__(16) float As[16][68];
    __shared__ __align__(16) float Bs[16][136];
    __shared__ float se1[64], smrow[64];
    const int tid = threadIdx.x;
    if (tid < 64) {
        float v1 = e1[(bm + tid)*HGAT + h];
        float s = v1 + m2[h];
        smrow[tid] = s > 0.f ? s : 0.2f * s;
        se1[tid] = v1;
    }
    __syncthreads();
    const int lk = tid & 15, lr = tid >> 4;
    const int bd = tid & 127, bj = tid >> 7;
    const int tx = tid & 15, ty = tid >> 4;
    float acc[4][8] = {};
    float dacc[4] = {};
    for (int k0 = 0; k0 < M_; k0 += 16) {
        float e2v = e2[(k0 + lk)*HGAT + h];
        #pragma unroll
        for (int p = 0; p < 4; p++) {
            int i = lr + 16*p;
            float s = se1[i] + e2v;
            float l = s > 0.f ? s : 0.2f * s;
            As[lk][i] = __expf(l - smrow[i]);
        }
        #pragma unroll
        for (int p = 0; p < 8; p++) {
            int jj = bj + 2*p;
            Bs[jj][bd] = hg[(size_t)(k0 + jj)*D_ + h*GDH + bd];
        }
        __syncthreads();
        #pragma unroll
        for (int k = 0; k < 16; k++) {
            float a[4], b[8];
            *(float4*)a      = *(const float4*)&As[k][ty*4];
            *(float4*)&b[0]  = *(const float4*)&Bs[k][tx*8];
            *(float4*)&b[4]  = *(const float4*)&Bs[k][tx*8 + 4];
            #pragma unroll
            for (int i = 0; i < 4; i++) {
                dacc[i] += a[i];
                #pragma unroll
                for (int j = 0; j < 8; j++)
                    acc[i][j] += a[i]*b[j];
            }
        }
        __syncthreads();
    }
    #pragma unroll
    for (int i = 0; i < 4; i++) {
        int m = bm + ty*4 + i;
        float inv = 1.f / dacc[i];
        #pragma unroll
        for (int j = 0; j < 8; j++) {
            float v = acc[i][j] * inv;
            v = v > 0.f ? v : expm1f(v);                 // ELU
            int col = h*GDH + tx*8 + j;
            out[(size_t)m*D_ + col] = v + feat[(size_t)m*D_ + col];
        }
    }
}

// =====================================================================
extern "C" void kernel_launch(void* const* d_in, const int* in_sizes, int n_in,
                              void* d_out, int out_size)
{
    const float* feat = (const float*)d_in[0];

    // Bind conv weights/biases by SIZE (robust to interleaved or grouped order).
    const float* cw[5];
    const float* cb[5];
    int wi = 0, bi = 0;
    for (int i = 1; i <= 10; i++) {
        if (in_sizes[i] == D_ * D_ * KW) { if (wi < 5) cw[wi++] = (const float*)d_in[i]; }
        else                             { if (bi < 5) cb[bi++] = (const float*)d_in[i]; }
    }

    const float* fp_w = (const float*)d_in[11];
    const float* fp_b = (const float*)d_in[12];
    const float* ln_g = (const float*)d_in[13];
    const float* ln_b = (const float*)d_in[14];
    const float* wq = (const float*)d_in[15];
    const float* bq = (const float*)d_in[16];
    const float* wk = (const float*)d_in[17];
    const float* bk = (const float*)d_in[18];
    const float* wv = (const float*)d_in[19];
    const float* bv = (const float*)d_in[20];
    const float* wo = (const float*)d_in[21];
    const float* bo = (const float*)d_in[22];
    const float* gat_w = (const float*)d_in[23];
    const float* gat_b = (const float*)d_in[24];
    const float* a1 = (const float*)d_in[25];
    const float* a2 = (const float*)d_in[26];
    float* out = (float*)d_out;

    // resolve scratch symbols
    __nv_bfloat16 *fh, *fl, *wth, *wtl, *fph, *fpl, *dwh, *dwl;
    __nv_bfloat16 *msh, *msl, *zh, *zl, *cxh, *cxl, *ath, *atl;
    float *ms, *z, *q, *k, *v, *s, *ctx, *att, *hg, *e1, *e2, *m2;
    cudaGetSymbolAddress((void**)&fh,  g_fh);
    cudaGetSymbolAddress((void**)&fl,  g_fl);
    cudaGetSymbolAddress((void**)&wth, g_wth);
    cudaGetSymbolAddress((void**)&wtl, g_wtl);
    cudaGetSymbolAddress((void**)&fph, g_fph);
    cudaGetSymbolAddress((void**)&fpl, g_fpl);
    cudaGetSymbolAddress((void**)&dwh, g_dwh);
    cudaGetSymbolAddress((void**)&dwl, g_dwl);
    cudaGetSymbolAddress((void**)&ms,  g_ms);
    cudaGetSymbolAddress((void**)&msh, g_msh);
    cudaGetSymbolAddress((void**)&msl, g_msl);
    cudaGetSymbolAddress((void**)&z,   g_z);
    cudaGetSymbolAddress((void**)&zh,  g_zh);
    cudaGetSymbolAddress((void**)&zl,  g_zl);
    cudaGetSymbolAddress((void**)&q,   g_q);
    cudaGetSymbolAddress((void**)&k,   g_k);
    cudaGetSymbolAddress((void**)&v,   g_v);
    cudaGetSymbolAddress((void**)&s,   g_s);
    cudaGetSymbolAddress((void**)&ctx, g_ctx);
    cudaGetSymbolAddress((void**)&cxh, g_cxh);
    cudaGetSymbolAddress((void**)&cxl, g_cxl);
    cudaGetSymbolAddress((void**)&att, g_att);
    cudaGetSymbolAddress((void**)&ath, g_ath);
    cudaGetSymbolAddress((void**)&atl, g_atl);
    cudaGetSymbolAddress((void**)&hg,  g_hg);
    cudaGetSymbolAddress((void**)&e1,  g_e1);
    cudaGetSymbolAddress((void**)&e2,  g_e2);
    cudaGetSymbolAddress((void**)&m2,  g_m2);

    cudaFuncSetAttribute(hmma_gemm_kernel, cudaFuncAttributeMaxDynamicSharedMemorySize, SMEM_DYN);
    cudaFuncSetAttribute(hmma_conv_kernel, cudaFuncAttributeMaxDynamicSharedMemorySize, SMEM_DYN);

    const int dil[5] = {1, 2, 4, 8, 16};
    const size_t WTN = (size_t)KW * D_ * D_;         // 7,340,032 per conv
    const dim3 mma_grid(8, 16);

    // 0) splits: features, conv weights (transposed), dense weights
    cvt_pair_kernel<<<(M_*D_/4 + 255)/256, 256>>>(feat, fh, fl, M_*D_/4);
    for (int c = 0; c < 5; c++)
        wtrans_pair_kernel<<<(int)(WTN / 256), 256>>>(cw[c], wth + c * WTN, wtl + c * WTN);
    cvt_pair_kernel<<<(D_*K5D/4 + 255)/256, 256>>>(fp_w, fph, fpl, D_*K5D/4);
    const float* dws[5] = { wq, wk, wv, wo, gat_w };
    for (int c = 0; c < 5; c++)
        cvt_pair_kernel<<<(D_*D_/4 + 255)/256, 256>>>(dws[c],
            dwh + (size_t)c * D_*D_, dwl + (size_t)c * D_*D_, D_*D_/4);

    // 1) dilated convs (HMMA) -> g_ms (2048, 5120)
    for (int c = 0; c < 5; c++)
        hmma_conv_kernel<<<mma_grid, 256, SMEM_DYN>>>(fh, fl,
            wth + c * WTN, wtl + c * WTN, cb[c], ms, dil[c], c*D_);

    // 2) fusion projection (K=5120) -> g_z, then LN+GELU
    cvt_pair_kernel<<<(M_*K5D/4 + 255)/256, 256>>>(ms, msh, msl, M_*K5D/4);
    hmma_gemm_kernel<<<mma_grid, 256, SMEM_DYN>>>(msh, msl, fph, fpl, fp_b, z, K5D, D_);
    ln_gelu_kernel<<<M_, 256>>>(z, ln_g, ln_b);

    // 3) q, k, v projections
    cvt_pair_kernel<<<(M_*D_/4 + 255)/256, 256>>>(z, zh, zl, M_*D_/4);
    hmma_gemm_kernel<<<mma_grid, 256, SMEM_DYN>>>(zh, zl, dwh + 0*(size_t)D_*D_, dwl + 0*(size_t)D_*D_, bq, q, D_, D_);
    hmma_gemm_kernel<<<mma_grid, 256, SMEM_DYN>>>(zh, zl, dwh + 1*(size_t)D_*D_, dwl + 1*(size_t)D_*D_, bk, k, D_, D_);
    hmma_gemm_kernel<<<mma_grid, 256, SMEM_DYN>>>(zh, zl, dwh + 2*(size_t)D_*D_, dwl + 2*(size_t)D_*D_, bv, v, D_, D_);

    // 4) attention (fp32)
    attn_scores_kernel<<<dim3(4, 4, B_*HMHA), 256>>>(q, k, s);
    softmax_kernel<<<(B_*HMHA*T_)/8, 256>>>(s);
    attn_ctx_kernel<<<dim3(1, 4, B_*HMHA), 256>>>(s, v, ctx);

    // 5) output projection, GAT projection
    cvt_pair_kernel<<<(M_*D_/4 + 255)/256, 256>>>(ctx, cxh, cxl, M_*D_/4);
    hmma_gemm_kernel<<<mma_grid, 256, SMEM_DYN>>>(cxh, cxl, dwh + 3*(size_t)D_*D_, dwl + 3*(size_t)D_*D_, bo, att, D_, D_);
    cvt_pair_kernel<<<(M_*D_/4 + 255)/256, 256>>>(att, ath, atl, M_*D_/4);
    hmma_gemm_kernel<<<mma_grid, 256, SMEM_DYN>>>(ath, atl, dwh + 4*(size_t)D_*D_, dwl + 4*(size_t)D_*D_, gat_b, hg, D_, D_);

    // 6) GAT logits + stable max
    e12_kernel<<<(M_*HGAT)/8, 256>>>(hg, a1, a2, e1, e2);
    e2max_kernel<<<HGAT, 256>>>(e2, m2);

    // 7) GAT aggregation + ELU + residual -> d_out
    gat_gemm_kernel<<<dim3(HGAT, 32), 256>>>(hg, e1, e2, m2, feat, out);
}

// round 7
// speedup vs baseline: 2.8795x; 1.0388x over previous
#include <cuda_runtime.h>
#include <cuda_bf16.h>
#include <math.h>
#include <stdint.h>

#define D_   1024
#define T_   256
#define B_   8
#define M_   (B_*T_)        // 2048 rows (b,t)
#define HMHA 16
#define DH   64
#define HGAT 8
#define GDH  128
#define KW   7
#define K5D  (5*D_)
#define KCONV (KW*D_)       // 7168

#define ROWB   80                   // bytes per smem row (32 bf16 + 8 pad)
#define TILE_B (128*ROWB)           // 10240 B per tile
#define SMEM_DYN (2*4*TILE_B)       // 81920 B (double buffer x 4 tiles)

// ===================== PTX helpers (baseline ISA only) =====================
__device__ __forceinline__ uint32_t smem_u32(const void* p) {
    uint32_t a;
    asm("{ .reg .u64 t; cvta.to.shared.u64 t, %1; cvt.u32.u64 %0, t; }"
        : "=r"(a) : "l"(p));
    return a;
}
#define CP16(dst, src, sz) \
    asm volatile("cp.async.cg.shared.global [%0], [%1], 16, %2;" \
                 :: "r"(dst), "l"(src), "r"(sz))
#define CP_COMMIT() asm volatile("cp.async.commit_group;" ::: "memory")
#define CP_WAIT1()  asm volatile("cp.async.wait_group 1;" ::: "memory")
#define CP_WAIT0()  asm volatile("cp.async.wait_group 0;" ::: "memory")

#define LDMX4(r, addr) \
    asm volatile("ldmatrix.sync.aligned.m8n8.x4.shared.b16 {%0,%1,%2,%3}, [%4];" \
        : "=r"((r)[0]), "=r"((r)[1]), "=r"((r)[2]), "=r"((r)[3]) : "r"(addr))
#define LDMX2(r, addr) \
    asm volatile("ldmatrix.sync.aligned.m8n8.x2.shared.b16 {%0,%1}, [%2];" \
        : "=r"((r)[0]), "=r"((r)[1]) : "r"(addr))

#define MMA16816(c, a, b) \
    asm volatile("mma.sync.aligned.m16n8k16.row.col.f32.bf16.bf16.f32 " \
        "{%0,%1,%2,%3}, {%4,%5,%6,%7}, {%8,%9}, {%0,%1,%2,%3};" \
        : "+f"((c)[0]), "+f"((c)[1]), "+f"((c)[2]), "+f"((c)[3]) \
        : "r"((a)[0]), "r"((a)[1]), "r"((a)[2]), "r"((a)[3]), \
          "r"((b)[0]), "r"((b)[1]))

struct Ptr5  { const float* p[5]; };
struct QkvArgs { float* o[3]; const float* b[3]; };

// ---------------- scratch (device globals; no allocation) ----------------
__device__ __nv_bfloat16 g_fh [M_ * D_];
__device__ __nv_bfloat16 g_fl [M_ * D_];
__device__ __nv_bfloat16 g_wth[5 * KW * D_ * D_];  // [c][tap][o][ci]
__device__ __nv_bfloat16 g_wtl[5 * KW * D_ * D_];
__device__ __nv_bfloat16 g_fph[D_ * K5D];
__device__ __nv_bfloat16 g_fpl[D_ * K5D];
__device__ __nv_bfloat16 g_dwh[5 * D_ * D_];       // wq,wk,wv,wo,gat_w
__device__ __nv_bfloat16 g_dwl[5 * D_ * D_];
__device__ __nv_bfloat16 g_msh[M_ * K5D];
__device__ __nv_bfloat16 g_msl[M_ * K5D];
__device__ float g_z  [M_ * D_];
__device__ __nv_bfloat16 g_zh [M_ * D_];
__device__ __nv_bfloat16 g_zl [M_ * D_];
__device__ float g_q  [M_ * D_];
__device__ float g_k  [M_ * D_];
__device__ float g_v  [M_ * D_];
__device__ float g_s  [B_*HMHA * T_ * T_];
__device__ __nv_bfloat16 g_cxh[M_ * D_];
__device__ __nv_bfloat16 g_cxl[M_ * D_];
__device__ __nv_bfloat16 g_ath[M_ * D_];
__device__ __nv_bfloat16 g_atl[M_ * D_];
__device__ float g_hg [M_ * D_];
__device__ float g_e1[M_ * HGAT];
__device__ float g_e2[M_ * HGAT];
__device__ float g_m2[HGAT];

// =====================================================================
// fp32 -> (bf16 hi, lo) split helpers / kernels
// =====================================================================
__device__ __forceinline__ void split_bf16(float v, __nv_bfloat16& h, __nv_bfloat16& l) {
    h = __float2bfloat16(v);
    l = __float2bfloat16(v - __bfloat162float(h));
}

__global__ __launch_bounds__(256)
void cvt_pair_kernel(const float* __restrict__ src, __nv_bfloat16* __restrict__ hi,
                     __nv_bfloat16* __restrict__ lo, int n4)
{
    int i = blockIdx.x * 256 + threadIdx.x;
    if (i >= n4) return;
    float4 v = ((const float4*)src)[i];
    __nv_bfloat16 h0, h1, h2, h3, l0, l1, l2, l3;
    split_bf16(v.x, h0, l0); split_bf16(v.y, h1, l1);
    split_bf16(v.z, h2, l2); split_bf16(v.w, h3, l3);
    __nv_bfloat162* ph = (__nv_bfloat162*)hi;
    __nv_bfloat162* pl = (__nv_bfloat162*)lo;
    ph[2*i]   = __nv_bfloat162(h0, h1);
    ph[2*i+1] = __nv_bfloat162(h2, h3);
    pl[2*i]   = __nv_bfloat162(l0, l1);
    pl[2*i+1] = __nv_bfloat162(l2, l3);
}

// merged dense-weight split (5 x D*D), blockIdx.y = which weight
__global__ __launch_bounds__(256)
void cvt5_kernel(Ptr5 ws, __nv_bfloat16* __restrict__ hi, __nv_bfloat16* __restrict__ lo)
{
    int c = blockIdx.y;
    int i = blockIdx.x * 256 + threadIdx.x;           // over D*D/4
    const float* src = ws.p[c];
    size_t base = (size_t)c * D_ * D_;
    float4 v = ((const float4*)src)[i];
    __nv_bfloat16 h0, h1, h2, h3, l0, l1, l2, l3;
    split_bf16(v.x, h0, l0); split_bf16(v.y, h1, l1);
    split_bf16(v.z, h2, l2); split_bf16(v.w, h3, l3);
    __nv_bfloat162* ph = (__nv_bfloat162*)(hi + base);
    __nv_bfloat162* pl = (__nv_bfloat162*)(lo + base);
    ph[2*i]   = __nv_bfloat162(h0, h1);
    ph[2*i+1] = __nv_bfloat162(h2, h3);
    pl[2*i]   = __nv_bfloat162(l0, l1);
    pl[2*i+1] = __nv_bfloat162(l2, l3);
}

// merged conv weight transform+split: blockIdx.y = conv id
__global__ __launch_bounds__(256)
void wtrans5_kernel(Ptr5 cw, __nv_bfloat16* __restrict__ wh, __nv_bfloat16* __restrict__ wl)
{
    int c = blockIdx.y;
    int idx = blockIdx.x * 256 + threadIdx.x;      // over 7*1024*1024
    int tap = idx >> 20;
    int rem = idx & ((1 << 20) - 1);
    int o  = rem >> 10;
    int ci = rem & 1023;
    float x = __ldg(&cw.p[c][(size_t)o * KCONV + ci * 7 + tap]);
    size_t dst = (size_t)c * (KW*D_*D_) + idx;
    __nv_bfloat16 h = __float2bfloat16(x);
    wh[dst] = h;
    wl[dst] = __float2bfloat16(x - __bfloat162float(h));
}

// =====================================================================
// HMMA core pieces
// =====================================================================
__device__ __forceinline__
void hmma_chunk(uint32_t bufu, int wm, int wn, int lane, float acc[4][4][4])
{
    #pragma unroll
    for (int kk = 0; kk < 32; kk += 16) {
        uint32_t bh[4][2], bl[4][2];
        #pragma unroll
        for (int j = 0; j < 4; j++) {
            int nrow = wn*32 + j*8 + (lane & 7);
            int colb = (kk + ((lane >> 3) & 1)*8) * 2;
            LDMX2(bh[j], bufu + 2*TILE_B + nrow*ROWB + colb);
            LDMX2(bl[j], bufu + 3*TILE_B + nrow*ROWB + colb);
        }
        #pragma unroll
        for (int i = 0; i < 4; i++) {
            int mrow = wm*64 + i*16 + (lane & 15);
            int colb = (kk + ((lane >> 4) & 1)*8) * 2;
            uint32_t ah[4], al[4];
            LDMX4(ah, bufu + 0*TILE_B + mrow*ROWB + colb);
            LDMX4(al, bufu + 1*TILE_B + mrow*ROWB + colb);
            #pragma unroll
            for (int j = 0; j < 4; j++) {
                MMA16816(acc[i][j], ah, bh[j]);
                MMA16816(acc[i][j], ah, bl[j]);
                MMA16816(acc[i][j], al, bh[j]);
            }
        }
    }
}

__device__ __forceinline__
void issue_dense(uint32_t smem_base, int c, int tid,
                 const __nv_bfloat16* __restrict__ Ah, const __nv_bfloat16* __restrict__ Al,
                 const __nv_bfloat16* __restrict__ Wh, const __nv_bfloat16* __restrict__ Wl,
                 int bm, int bn, int K)
{
    int k0 = c << 5;
    uint32_t bufu = smem_base + (c & 1) * 4*TILE_B;
    #pragma unroll
    for (int it = 0; it < 8; it++) {
        int g = tid + it*256;
        int tile = g >> 9;
        int ct = g & 511, row = ct >> 2, cc = ct & 3;
        const __nv_bfloat16* src;
        if      (tile == 0) src = Ah + (size_t)(bm+row)*K + k0 + cc*8;
        else if (tile == 1) src = Al + (size_t)(bm+row)*K + k0 + cc*8;
        else if (tile == 2) src = Wh + (size_t)(bn+row)*K + k0 + cc*8;
        else                src = Wl + (size_t)(bn+row)*K + k0 + cc*8;
        CP16(bufu + tile*TILE_B + row*ROWB + cc*16, src, 16);
    }
    CP_COMMIT();
}

__device__ __forceinline__
void epi_f32(float acc[4][4][4], const float* __restrict__ bias,
             float* __restrict__ C, int bm, int bn, int ldc,
             int wm, int wn, int lane)
{
    #pragma unroll
    for (int i = 0; i < 4; i++) {
        int m0 = bm + wm*64 + i*16 + (lane >> 2);
        #pragma unroll
        for (int j = 0; j < 4; j++) {
            int n0 = wn*32 + j*8 + (lane & 3)*2;
            float b0 = bias[bn + n0], b1 = bias[bn + n0 + 1];
            *(float2*)&C[(size_t)m0*ldc + bn + n0] =
                make_float2(acc[i][j][0] + b0, acc[i][j][1] + b1);
            *(float2*)&C[(size_t)(m0+8)*ldc + bn + n0] =
                make_float2(acc[i][j][2] + b0, acc[i][j][3] + b1);
        }
    }
}

__device__ __forceinline__
void epi_b16(float acc[4][4][4], const float* __restrict__ bias,
             __nv_bfloat16* __restrict__ Ch, __nv_bfloat16* __restrict__ Cl,
             int bm, int bn, int ldc, int colbase, int wm, int wn, int lane)
{
    #pragma unroll
    for (int i = 0; i < 4; i++) {
        int m0 = bm + wm*64 + i*16 + (lane >> 2);
        #pragma unroll
        for (int j = 0; j < 4; j++) {
            int n0 = wn*32 + j*8 + (lane & 3)*2;
            float b0 = bias[bn + n0], b1 = bias[bn + n0 + 1];
            float v0 = acc[i][j][0] + b0, v1 = acc[i][j][1] + b1;
            float v2 = acc[i][j][2] + b0, v3 = acc[i][j][3] + b1;
            __nv_bfloat16 h0, h1, h2, h3, l0, l1, l2, l3;
            split_bf16(v0, h0, l0); split_bf16(v1, h1, l1);
            split_bf16(v2, h2, l2); split_bf16(v3, h3, l3);
            size_t o01 = (size_t)m0*ldc + colbase + bn + n0;
            size_t o23 = (size_t)(m0+8)*ldc + colbase + bn + n0;
            *(__nv_bfloat162*)&Ch[o01] = __nv_bfloat162(h0, h1);
            *(__nv_bfloat162*)&Cl[o01] = __nv_bfloat162(l0, l1);
            *(__nv_bfloat162*)&Ch[o23] = __nv_bfloat162(h2, h3);
            *(__nv_bfloat162*)&Cl[o23] = __nv_bfloat162(l2, l3);
        }
    }
}

#define HMMA_PROLOG() \
    extern __shared__ __align__(16) char smem_raw[]; \
    const uint32_t smem_base = smem_u32(smem_raw); \
    const int bm = blockIdx.y * 128, bn = blockIdx.x * 128; \
    const int tid = threadIdx.x; \
    const int wid = tid >> 5, lane = tid & 31; \
    const int wm = wid & 1, wn = wid >> 1; \
    float acc[4][4][4] = {};

#define HMMA_LOOP(NC, ISSUE) \
    ISSUE(0); \
    for (int c = 0; c < (NC); c++) { \
        if (c + 1 < (NC)) { ISSUE(c + 1); CP_WAIT1(); } \
        else              { CP_WAIT0(); } \
        __syncthreads(); \
        hmma_chunk(smem_base + (c & 1)*4*TILE_B, wm, wn, lane, acc); \
        __syncthreads(); \
    }

// ---- generic dense GEMM, fp32 out ----
__global__ __launch_bounds__(256, 2)
void hmma_gemm_kernel(const __nv_bfloat16* __restrict__ Ah, const __nv_bfloat16* __restrict__ Al,
                      const __nv_bfloat16* __restrict__ Wh, const __nv_bfloat16* __restrict__ Wl,
                      const float* __restrict__ bias, float* __restrict__ C,
                      int K, int ldc)
{
    HMMA_PROLOG();
#define ISS(c) issue_dense(smem_base, c, tid, Ah, Al, Wh, Wl, bm, bn, K)
    HMMA_LOOP(K >> 5, ISS);
#undef ISS
    epi_f32(acc, bias, C, bm, bn, ldc, wm, wn, lane);
}

// ---- generic dense GEMM, bf16-pair out ----
__global__ __launch_bounds__(256, 2)
void hmma_gemm_b16_kernel(const __nv_bfloat16* __restrict__ Ah, const __nv_bfloat16* __restrict__ Al,
                          const __nv_bfloat16* __restrict__ Wh, const __nv_bfloat16* __restrict__ Wl,
                          const float* __restrict__ bias,
                          __nv_bfloat16* __restrict__ Ch, __nv_bfloat16* __restrict__ Cl,
                          int K, int ldc)
{
    HMMA_PROLOG();
#define ISS(c) issue_dense(smem_base, c, tid, Ah, Al, Wh, Wl, bm, bn, K)
    HMMA_LOOP(K >> 5, ISS);
#undef ISS
    epi_b16(acc, bias, Ch, Cl, bm, bn, ldc, 0, wm, wn, lane);
}

// ---- QKV: grid.z selects weight/bias/output ----
__global__ __launch_bounds__(256, 2)
void hmma_qkv_kernel(const __nv_bfloat16* __restrict__ Ah, const __nv_bfloat16* __restrict__ Al,
                     const __nv_bfloat16* __restrict__ dwh, const __nv_bfloat16* __restrict__ dwl,
                     QkvArgs args)
{
    const int z = blockIdx.z;
    const __nv_bfloat16* Wh = dwh + (size_t)z * D_ * D_;
    const __nv_bfloat16* Wl = dwl + (size_t)z * D_ * D_;
    HMMA_PROLOG();
#define ISS(c) issue_dense(smem_base, c, tid, Ah, Al, Wh, Wl, bm, bn, D_)
    HMMA_LOOP(D_ >> 5, ISS);
#undef ISS
    epi_f32(acc, args.b[z], args.o[z], bm, bn, D_, wm, wn, lane);
}

// ---- convs: grid.z = conv id; A gathered, bf16-pair out to ms ----
__global__ __launch_bounds__(256, 2)
void hmma_conv_kernel(const __nv_bfloat16* __restrict__ Fh, const __nv_bfloat16* __restrict__ Fl,
                      const __nv_bfloat16* __restrict__ wth, const __nv_bfloat16* __restrict__ wtl,
                      Ptr5 cbs,
                      __nv_bfloat16* __restrict__ msh, __nv_bfloat16* __restrict__ msl)
{
    const int z = blockIdx.z;
    const int dil = 1 << z;
    const int ccol = z * D_;
    const __nv_bfloat16* Wh = wth + (size_t)z * (KW*D_*D_);
    const __nv_bfloat16* Wl = wtl + (size_t)z * (KW*D_*D_);
    HMMA_PROLOG();

#define ISSUE_C(c) do { \
    int k0 = (c) << 5; \
    int tap = k0 >> 10, ci0 = k0 & 1023; \
    int offt = (tap - 3) * dil; \
    uint32_t bufu = smem_base + ((c) & 1) * 4*TILE_B; \
    _Pragma("unroll") \
    for (int it = 0; it < 8; it++) { \
        int g = tid + it*256; \
        int tile = g >> 9; \
        int ct = g & 511; int row = ct >> 2, cc = ct & 3; \
        const __nv_bfloat16* src; \
        uint32_t sz = 16; \
        if (tile <= 1) { \
            int m = bm + row; \
            int bb = m >> 8, tt = (m & 255) + offt; \
            if (tt >= 0 && tt < T_) \
                src = (tile == 0 ? Fh : Fl) + ((size_t)(bb*T_ + tt))*D_ + ci0 + cc*8; \
            else { src = Fh; sz = 0; } \
        } else { \
            src = (tile == 2 ? Wh : Wl) + (size_t)tap*D_*D_ + (size_t)(bn+row)*D_ + ci0 + cc*8; \
        } \
        CP16(bufu + tile*TILE_B + row*ROWB + cc*16, src, sz); \
    } \
    CP_COMMIT(); } while (0)

    HMMA_LOOP(KCONV >> 5, ISSUE_C);
#undef ISSUE_C
    epi_b16(acc, cbs.p[z], msh, msl, bm, bn, K5D, ccol, wm, wn, lane);
}

// =====================================================================
// LayerNorm + exact GELU: reads z fp32, writes zh/zl bf16 pairs.
// =====================================================================
__global__ __launch_bounds__(256)
void ln_gelu_kernel(const float* __restrict__ z, const float* __restrict__ g,
                    const float* __restrict__ b,
                    __nv_bfloat16* __restrict__ zh, __nv_bfloat16* __restrict__ zl)
{
    const int row = blockIdx.x;
    const int tid = threadIdx.x;
    const float* p = z + (size_t)row * D_;
    float4 v = ((const float4*)p)[tid];
    float s  = v.x + v.y + v.z + v.w;
    float ss = v.x*v.x + v.y*v.y + v.z*v.z + v.w*v.w;
    #pragma unroll
    for (int o = 16; o; o >>= 1) {
        s  += __shfl_xor_sync(0xffffffffu, s,  o);
        ss += __shfl_xor_sync(0xffffffffu, ss, o);
    }
    __shared__ float ws[8], wss[8];
    __shared__ float mu_s, inv_s;
    int lane = tid & 31, wid = tid >> 5;
    if (lane == 0) { ws[wid] = s; wss[wid] = ss; }
    __syncthreads();
    if (tid == 0) {
        float S = 0.f, SS = 0.f;
        #pragma unroll
        for (int i = 0; i < 8; i++) { S += ws[i]; SS += wss[i]; }
        float mu = S * (1.f / D_);
        float var = SS * (1.f / D_) - mu * mu;
        mu_s = mu;
        inv_s = rsqrtf(var + 1e-5f);
    }
    __syncthreads();
    float mu = mu_s, inv = inv_s;
    float4 gg = ((const float4*)g)[tid];
    float4 bb = ((const float4*)b)[tid];
    float y[4] = { (v.x-mu)*inv*gg.x + bb.x, (v.y-mu)*inv*gg.y + bb.y,
                   (v.z-mu)*inv*gg.z + bb.z, (v.w-mu)*inv*gg.w + bb.w };
    float o[4];
    o[0] = 0.5f*y[0]*(1.f + erff(y[0]*0.70710678118654752f));
    o[1] = 0.5f*y[1]*(1.f + erff(y[1]*0.70710678118654752f));
    o[2] = 0.5f*y[2]*(1.f + erff(y[2]*0.70710678118654752f));
    o[3] = 0.5f*y[3]*(1.f + erff(y[3]*0.70710678118654752f));
    __nv_bfloat16 h0, h1, h2, h3, l0, l1, l2, l3;
    split_bf16(o[0], h0, l0); split_bf16(o[1], h1, l1);
    split_bf16(o[2], h2, l2); split_bf16(o[3], h3, l3);
    __nv_bfloat162* ph = (__nv_bfloat162*)(zh + (size_t)row * D_);
    __nv_bfloat162* pl = (__nv_bfloat162*)(zl + (size_t)row * D_);
    ph[2*tid]   = __nv_bfloat162(h0, h1);
    ph[2*tid+1] = __nv_bfloat162(h2, h3);
    pl[2*tid]   = __nv_bfloat162(l0, l1);
    pl[2*tid+1] = __nv_bfloat162(l2, l3);
}

// =====================================================================
// Attention (fp32 SIMT)
// =====================================================================
__global__ __launch_bounds__(256)
void attn_scores_kernel(const float* __restrict__ q, const float* __restrict__ kmat,
                        float* __restrict__ s)
{
    const int bh = blockIdx.z;
    const int b = bh >> 4, h = bh & 15;
    const int bm = blockIdx.y * 64, bn = blockIdx.x * 64;
    __shared__ __align__(16) float As[16][68];
    __shared__ __align__(16) float Bs[16][68];
    const int tid = threadIdx.x;
    const int lk = tid & 15, lr = tid >> 4;
    const int tx = tid & 15, ty = tid >> 4;
    float acc[4][4] = {};
    for (int k0 = 0; k0 < DH; k0 += 16) {
        #pragma unroll
        for (int p = 0; p < 4; p++) {
            int m = bm + lr + 16*p;
            As[lk][lr+16*p] = q[((size_t)(b*T_ + m))*D_ + h*DH + k0 + lk];
        }
        #pragma unroll
        for (int p = 0; p < 4; p++) {
            int n = bn + lr + 16*p;
            Bs[lk][lr+16*p] = kmat[((size_t)(b*T_ + n))*D_ + h*DH + k0 + lk];
        }
        __syncthreads();
        #pragma unroll
        for (int k = 0; k < 16; k++) {
            float a[4], bb[4];
            *(float4*)a  = *(const float4*)&As[k][ty*4];
            *(float4*)bb = *(const float4*)&Bs[k][tx*4];
            #pragma unroll
            for (int i = 0; i < 4; i++)
                #pragma unroll
                for (int j = 0; j < 4; j++)
                    acc[i][j] += a[i]*bb[j];
        }
        __syncthreads();
    }
    #pragma unroll
    for (int i = 0; i < 4; i++) {
        int m = bm + ty*4 + i;
        #pragma unroll
        for (int j = 0; j < 4; j++) {
            int n = bn + tx*4 + j;
            s[((size_t)bh*T_ + m)*T_ + n] = acc[i][j] * 0.125f;
        }
    }
}

__global__ __launch_bounds__(256)
void softmax_kernel(float* __restrict__ s)
{
    int row  = (blockIdx.x * blockDim.x + threadIdx.x) >> 5;
    int lane = threadIdx.x & 31;
    float* p = s + (size_t)row * T_;
    float v[8];
    float m = -1e30f;
    #pragma unroll
    for (int r = 0; r < 8; r++) { v[r] = p[lane + 32*r]; m = fmaxf(m, v[r]); }
    #pragma unroll
    for (int o = 16; o; o >>= 1) m = fmaxf(m, __shfl_xor_sync(0xffffffffu, m, o));
    float sum = 0.f;
    #pragma unroll
    for (int r = 0; r < 8; r++) { v[r] = __expf(v[r] - m); sum += v[r]; }
    #pragma unroll
    for (int o = 16; o; o >>= 1) sum += __shfl_xor_sync(0xffffffffu, sum, o);
    float inv = 1.f / sum;
    #pragma unroll
    for (int r = 0; r < 8; r++) p[lane + 32*r] = v[r] * inv;
}

// ctx written directly as bf16 hi/lo pairs
__global__ __launch_bounds__(256)
void attn_ctx_kernel(const float* __restrict__ s, const float* __restrict__ v,
                     __nv_bfloat16* __restrict__ cxh, __nv_bfloat16* __restrict__ cxl)
{
    const int bh = blockIdx.z;
    const int b = bh >> 4, h = bh & 15;
    const int bm = blockIdx.y * 64;
    __shared__ __align__(16) float As[16][68];
    __shared__ __align__(16) float Bs[16][68];
    const int tid = threadIdx.x;
    const int lk = tid & 15, lr = tid >> 4;
    const int bn_ = tid & 63, bkk = tid >> 6;
    const int tx = tid & 15, ty = tid >> 4;
    float acc[4][4] = {};
    for (int k0 = 0; k0 < T_; k0 += 16) {
        #pragma unroll
        for (int p = 0; p < 4; p++) {
            int m = bm + lr + 16*p;
            As[lk][lr+16*p] = s[((size_t)bh*T_ + m)*T_ + k0 + lk];
        }
        #pragma unroll
        for (int p = 0; p < 4; p++) {
            int jj = bkk + 4*p;
            Bs[jj][bn_] = v[((size_t)(b*T_ + k0 + jj))*D_ + h*DH + bn_];
        }
        __syncthreads();
        #pragma unroll
        for (int k = 0; k < 16; k++) {
            float a[4], bb[4];
            *(float4*)a  = *(const float4*)&As[k][ty*4];
            *(float4*)bb = *(const float4*)&Bs[k][tx*4];
            #pragma unroll
            for (int i = 0; i < 4; i++)
                #pragma unroll
                for (int j = 0; j < 4; j++)
                    acc[i][j] += a[i]*bb[j];
        }
        __syncthreads();
    }
    #pragma unroll
    for (int i = 0; i < 4; i++) {
        int m = bm + ty*4 + i;
        size_t o = ((size_t)(b*T_ + m))*D_ + h*DH + tx*4;
        __nv_bfloat16 h0, h1, h2, h3, l0, l1, l2, l3;
        split_bf16(acc[i][0], h0, l0); split_bf16(acc[i][1], h1, l1);
        split_bf16(acc[i][2], h2, l2); split_bf16(acc[i][3], h3, l3);
        *(__nv_bfloat162*)&cxh[o]   = __nv_bfloat162(h0, h1);
        *(__nv_bfloat162*)&cxh[o+2] = __nv_bfloat162(h2, h3);
        *(__nv_bfloat162*)&cxl[o]   = __nv_bfloat162(l0, l1);
        *(__nv_bfloat162*)&cxl[o+2] = __nv_bfloat162(l2, l3);
    }
}

// =====================================================================
// GAT pieces (fp32)
// =====================================================================
__global__ __launch_bounds__(256)
void e12_kernel(const float* __restrict__ hg, const float* __restrict__ a1,
                const float* __restrict__ a2, float* __restrict__ e1,
                float* __restrict__ e2)
{
    int wid  = (blockIdx.x * blockDim.x + threadIdx.x) >> 5;
    int lane = threadIdx.x & 31;
    int n = wid >> 3, h = wid & 7;
    const float* row = hg + (size_t)n * D_ + h * GDH;
    float s1 = 0.f, s2 = 0.f;
    #pragma unroll
    for (int r = 0; r < 4; r++) {
        float x = row[lane + 32*r];
        s1 += x * a1[lane + 32*r];
        s2 += x * a2[lane + 32*r];
    }
    #pragma unroll
    for (int o = 16; o; o >>= 1) {
        s1 += __shfl_xor_sync(0xffffffffu, s1, o);
        s2 += __shfl_xor_sync(0xffffffffu, s2, o);
    }
    if (lane == 0) { e1[n*HGAT + h] = s1; e2[n*HGAT + h] = s2; }
}

__global__ __launch_bounds__(256)
void e2max_kernel(const float* __restrict__ e2, float* __restrict__ m2)
{
    int h = blockIdx.x, tid = threadIdx.x;
    float m = -1e30f;
    for (int n = tid; n < M_; n += 256) m = fmaxf(m, e2[n*HGAT + h]);
    __shared__ float sm[256];
    sm[tid] = m; __syncthreads();
    for (int s = 128; s > 0; s >>= 1) {
        if (tid < s) sm[tid] = fmaxf(sm[tid], sm[tid + s]);
        __syncthreads();
    }
    if (tid == 0) m2[h] = sm[0];
}

__global__ __launch_bounds__(256)
void gat_gemm_kernel(const float* __restrict__ hg, const float* __restrict__ e1,
                     const float* __restrict__ e2, const float* __restrict__ m2,
                     const float* __restrict__ feat, float* __restrict__ out)
{
    const int h  = blockIdx.x;
    const int bm = blockIdx.y * 64;
    __shared__ __align__(16) float As[16][68];
    __shared__ __align__(16) float Bs[16][136];
    __shared__ float se1[64], smrow[64];
    const int tid = threadIdx.x;
    if (tid < 64) {
        float v1 = e1[(bm + tid)*HGAT + h];
        float s = v1 + m2[h];
        smrow[tid] = s > 0.f ? s : 0.2f * s;
        se1[tid] = v1;
    }
    __syncthreads();
    const int lk = tid & 15, lr = tid >> 4;
    const int bd = tid & 127, bj = tid >> 7;
    const int tx = tid & 15, ty = tid >> 4;
    float acc[4][8] = {};
    float dacc[4] = {};
    for (int k0 = 0; k0 < M_; k0 += 16) {
        float e2v = e2[(k0 + lk)*HGAT + h];
        #pragma unroll
        for (int p = 0; p < 4; p++) {
            int i = lr + 16*p;
            float s = se1[i] + e2v;
            float l = s > 0.f ? s : 0.2f * s;
            As[lk][i] = __expf(l - smrow[i]);
        }
        #pragma unroll
        for (int p = 0; p < 8; p++) {
            int jj = bj + 2*p;
            Bs[jj][bd] = hg[(size_t)(k0 + jj)*D_ + h*GDH + bd];
        }
        __syncthreads();
        #pragma unroll
        for (int k = 0; k < 16; k++) {
            float a[4], b[8];
            *(float4*)a      = *(const float4*)&As[k][ty*4];
            *(float4*)&b[0]  = *(const float4*)&Bs[k][tx*8];
            *(float4*)&b[4]  = *(const float4*)&Bs[k][tx*8 + 4];
            #pragma unroll
            for (int i = 0; i < 4; i++) {
                dacc[i] += a[i];
                #pragma unroll
                for (int j = 0; j < 8; j++)
                    acc[i][j] += a[i]*b[j];
            }
        }
        __syncthreads();
    }
    #pragma unroll
    for (int i = 0; i < 4; i++) {
        int m = bm + ty*4 + i;
        float inv = 1.f / dacc[i];
        #pragma unroll
        for (int j = 0; j < 8; j++) {
            float v = acc[i][j] * inv;
            v = v > 0.f ? v : expm1f(v);                 // ELU
            int col = h*GDH + tx*8 + j;
            out[(size_t)m*D_ + col] = v + feat[(size_t)m*D_ + col];
        }
    }
}

// =====================================================================
extern "C" void kernel_launch(void* const* d_in, const int* in_sizes, int n_in,
                              void* d_out, int out_size)
{
    const float* feat = (const float*)d_in[0];

    // Bind conv weights/biases by SIZE (robust to interleaved or grouped order).
    Ptr5 cw{}, cb{};
    int wi = 0, bi = 0;
    for (int i = 1; i <= 10; i++) {
        if (in_sizes[i] == D_ * D_ * KW) { if (wi < 5) cw.p[wi++] = (const float*)d_in[i]; }
        else                             { if (bi < 5) cb.p[bi++] = (const float*)d_in[i]; }
    }

    const float* fp_w = (const float*)d_in[11];
    const float* fp_b = (const float*)d_in[12];
    const float* ln_g = (const float*)d_in[13];
    const float* ln_b = (const float*)d_in[14];
    const float* wq = (const float*)d_in[15];
    const float* bq = (const float*)d_in[16];
    const float* wk = (const float*)d_in[17];
    const float* bk = (const float*)d_in[18];
    const float* wv = (const float*)d_in[19];
    const float* bv = (const float*)d_in[20];
    const float* wo = (const float*)d_in[21];
    const float* bo = (const float*)d_in[22];
    const float* gat_w = (const float*)d_in[23];
    const float* gat_b = (const float*)d_in[24];
    const float* a1 = (const float*)d_in[25];
    const float* a2 = (const float*)d_in[26];
    float* out = (float*)d_out;

    __nv_bfloat16 *fh, *fl, *wth, *wtl, *fph, *fpl, *dwh, *dwl;
    __nv_bfloat16 *msh, *msl, *zh, *zl, *cxh, *cxl, *ath, *atl;
    float *z, *q, *k, *v, *s, *hg, *e1, *e2, *m2;
    cudaGetSymbolAddress((void**)&fh,  g_fh);
    cudaGetSymbolAddress((void**)&fl,  g_fl);
    cudaGetSymbolAddress((void**)&wth, g_wth);
    cudaGetSymbolAddress((void**)&wtl, g_wtl);
    cudaGetSymbolAddress((void**)&fph, g_fph);
    cudaGetSymbolAddress((void**)&fpl, g_fpl);
    cudaGetSymbolAddress((void**)&dwh, g_dwh);
    cudaGetSymbolAddress((void**)&dwl, g_dwl);
    cudaGetSymbolAddress((void**)&msh, g_msh);
    cudaGetSymbolAddress((void**)&msl, g_msl);
    cudaGetSymbolAddress((void**)&z,   g_z);
    cudaGetSymbolAddress((void**)&zh,  g_zh);
    cudaGetSymbolAddress((void**)&zl,  g_zl);
    cudaGetSymbolAddress((void**)&q,   g_q);
    cudaGetSymbolAddress((void**)&k,   g_k);
    cudaGetSymbolAddress((void**)&v,   g_v);
    cudaGetSymbolAddress((void**)&s,   g_s);
    cudaGetSymbolAddress((void**)&cxh, g_cxh);
    cudaGetSymbolAddress((void**)&cxl, g_cxl);
    cudaGetSymbolAddress((void**)&ath, g_ath);
    cudaGetSymbolAddress((void**)&atl, g_atl);
    cudaGetSymbolAddress((void**)&hg,  g_hg);
    cudaGetSymbolAddress((void**)&e1,  g_e1);
    cudaGetSymbolAddress((void**)&e2,  g_e2);
    cudaGetSymbolAddress((void**)&m2,  g_m2);

    cudaFuncSetAttribute(hmma_gemm_kernel,     cudaFuncAttributeMaxDynamicSharedMemorySize, SMEM_DYN);
    cudaFuncSetAttribute(hmma_gemm_b16_kernel, cudaFuncAttributeMaxDynamicSharedMemorySize, SMEM_DYN);
    cudaFuncSetAttribute(hmma_qkv_kernel,      cudaFuncAttributeMaxDynamicSharedMemorySize, SMEM_DYN);
    cudaFuncSetAttribute(hmma_conv_kernel,     cudaFuncAttributeMaxDynamicSharedMemorySize, SMEM_DYN);

    const size_t WTN = (size_t)KW * D_ * D_;

    // 0) splits
    cvt_pair_kernel<<<(M_*D_/4 + 255)/256, 256>>>(feat, fh, fl, M_*D_/4);
    wtrans5_kernel<<<dim3((int)(WTN/256), 5), 256>>>(cw, wth, wtl);
    cvt_pair_kernel<<<(D_*K5D/4 + 255)/256, 256>>>(fp_w, fph, fpl, D_*K5D/4);
    Ptr5 dws{{ wq, wk, wv, wo, gat_w }};
    cvt5_kernel<<<dim3(D_*D_/4/256, 5), 256>>>(dws, dwh, dwl);

    // 1) dilated convs (merged, HMMA) -> msh/msl (2048, 5120) bf16 pairs
    hmma_conv_kernel<<<dim3(8, 16, 5), 256, SMEM_DYN>>>(fh, fl, wth, wtl, cb, msh, msl);

    // 2) fusion projection (K=5120) -> z fp32, then LN+GELU -> zh/zl
    hmma_gemm_kernel<<<dim3(8, 16), 256, SMEM_DYN>>>(msh, msl, fph, fpl, fp_b, z, K5D, D_);
    ln_gelu_kernel<<<M_, 256>>>(z, ln_g, ln_b, zh, zl);

    // 3) q, k, v projections (merged)
    QkvArgs qkv{{ q, k, v }, { bq, bk, bv }};
    hmma_qkv_kernel<<<dim3(8, 16, 3), 256, SMEM_DYN>>>(zh, zl, dwh, dwl, qkv);

    // 4) attention (fp32) -> cxh/cxl bf16 pairs
    attn_scores_kernel<<<dim3(4, 4, B_*HMHA), 256>>>(q, k, s);
    softmax_kernel<<<(B_*HMHA*T_)/8, 256>>>(s);
    attn_ctx_kernel<<<dim3(1, 4, B_*HMHA), 256>>>(s, v, cxh, cxl);

    // 5) wo projection -> ath/atl bf16 pairs; gat_w projection -> hg fp32
    hmma_gemm_b16_kernel<<<dim3(8, 16), 256, SMEM_DYN>>>(cxh, cxl,
        dwh + 3*(size_t)D_*D_, dwl + 3*(size_t)D_*D_, bo, ath, atl, D_, D_);
    hmma_gemm_kernel<<<dim3(8, 16), 256, SMEM_DYN>>>(ath, atl,
        dwh + 4*(size_t)D_*D_, dwl + 4*(size_t)D_*D_, gat_b, hg, D_, D_);

    // 6) GAT logits + stable max
    e12_kernel<<<(M_*HGAT)/8, 256>>>(hg, a1, a2, e1, e2);
    e2max_kernel<<<HGAT, 256>>>(e2, m2);

    // 7) GAT aggregation + ELU + residual -> d_out
    gat_gemm_kernel<<<dim3(HGAT, 32), 256>>>(hg, e1, e2, m2, feat, out);
}

// round 8
// speedup vs baseline: 3.4833x; 1.2097x over previous
#include <cuda_runtime.h>
#include <cuda_bf16.h>
#include <cuda_fp16.h>
#include <math.h>
#include <stdint.h>

#define D_   1024
#define T_   256
#define B_   8
#define M_   (B_*T_)        // 2048 rows (b,t)
#define HMHA 16
#define DH   64
#define HGAT 8
#define GDH  128
#define KW   7
#define K5D  (5*D_)
#define KCONV (KW*D_)       // 7168

#define ROWB   80                    // bytes per smem row (32 elems + pad)
#define TILE_B (128*ROWB)            // 10240 B per tile
#define SMEM_DYN  (2*4*TILE_B)       // dense: 2 buffers x 4 tiles = 81920
#define SMEM_CONV (3*3*TILE_B)       // conv: 3 buffers x 3 tiles = 92160

// ===================== PTX helpers (baseline ISA only) =====================
__device__ __forceinline__ uint32_t smem_u32(const void* p) {
    uint32_t a;
    asm("{ .reg .u64 t; cvta.to.shared.u64 t, %1; cvt.u32.u64 %0, t; }"
        : "=r"(a) : "l"(p));
    return a;
}
#define CP16(dst, src, sz) \
    asm volatile("cp.async.cg.shared.global [%0], [%1], 16, %2;" \
                 :: "r"(dst), "l"(src), "r"(sz))
#define CP_COMMIT() asm volatile("cp.async.commit_group;" ::: "memory")
#define CP_WAIT1()  asm volatile("cp.async.wait_group 1;" ::: "memory")
#define CP_WAIT0()  asm volatile("cp.async.wait_group 0;" ::: "memory")

#define LDMX4(r, addr) \
    asm volatile("ldmatrix.sync.aligned.m8n8.x4.shared.b16 {%0,%1,%2,%3}, [%4];" \
        : "=r"((r)[0]), "=r"((r)[1]), "=r"((r)[2]), "=r"((r)[3]) : "r"(addr))
#define LDMX2(r, addr) \
    asm volatile("ldmatrix.sync.aligned.m8n8.x2.shared.b16 {%0,%1}, [%2];" \
        : "=r"((r)[0]), "=r"((r)[1]) : "r"(addr))

#define MMA16816(c, a, b) \
    asm volatile("mma.sync.aligned.m16n8k16.row.col.f32.bf16.bf16.f32 " \
        "{%0,%1,%2,%3}, {%4,%5,%6,%7}, {%8,%9}, {%0,%1,%2,%3};" \
        : "+f"((c)[0]), "+f"((c)[1]), "+f"((c)[2]), "+f"((c)[3]) \
        : "r"((a)[0]), "r"((a)[1]), "r"((a)[2]), "r"((a)[3]), \
          "r"((b)[0]), "r"((b)[1]))

#define MMA16816F(c, a, b) \
    asm volatile("mma.sync.aligned.m16n8k16.row.col.f32.f16.f16.f32 " \
        "{%0,%1,%2,%3}, {%4,%5,%6,%7}, {%8,%9}, {%0,%1,%2,%3};" \
        : "+f"((c)[0]), "+f"((c)[1]), "+f"((c)[2]), "+f"((c)[3]) \
        : "r"((a)[0]), "r"((a)[1]), "r"((a)[2]), "r"((a)[3]), \
          "r"((b)[0]), "r"((b)[1]))

struct Ptr5  { const float* p[5]; };
struct QkvArgs { float* o[3]; const float* b[3]; };

// ---------------- scratch (device globals; no allocation) ----------------
__device__ __half g_f16h[M_ * D_];                 // feat fp16 hi
__device__ __half g_f16l[M_ * D_];                 // feat fp16 lo
__device__ __half g_wt16[5 * KW * D_ * D_];        // conv weights fp16 hi [c][tap][o][ci]
__device__ __nv_bfloat16 g_fph[D_ * K5D];
__device__ __nv_bfloat16 g_fpl[D_ * K5D];
__device__ __nv_bfloat16 g_dwh[5 * D_ * D_];       // wq,wk,wv,wo,gat_w
__device__ __nv_bfloat16 g_dwl[5 * D_ * D_];
__device__ __nv_bfloat16 g_msh[M_ * K5D];
__device__ __nv_bfloat16 g_msl[M_ * K5D];
__device__ float g_z  [M_ * D_];
__device__ __nv_bfloat16 g_zh [M_ * D_];
__device__ __nv_bfloat16 g_zl [M_ * D_];
__device__ float g_q  [M_ * D_];
__device__ float g_k  [M_ * D_];
__device__ float g_v  [M_ * D_];
__device__ float g_s  [B_*HMHA * T_ * T_];
__device__ __nv_bfloat16 g_cxh[M_ * D_];
__device__ __nv_bfloat16 g_cxl[M_ * D_];
__device__ __nv_bfloat16 g_ath[M_ * D_];
__device__ __nv_bfloat16 g_atl[M_ * D_];
__device__ float g_hg [M_ * D_];
__device__ float g_e1[M_ * HGAT];
__device__ float g_e2[M_ * HGAT];
__device__ float g_m2[HGAT];

// =====================================================================
// split helpers / conversion kernels
// =====================================================================
__device__ __forceinline__ void split_bf16(float v, __nv_bfloat16& h, __nv_bfloat16& l) {
    h = __float2bfloat16(v);
    l = __float2bfloat16(v - __bfloat162float(h));
}
__device__ __forceinline__ void split_f16(float v, __half& h, __half& l) {
    h = __float2half_rn(v);
    l = __float2half_rn(v - __half2float(h));
}

__global__ __launch_bounds__(256)
void cvt_pair_kernel(const float* __restrict__ src, __nv_bfloat16* __restrict__ hi,
                     __nv_bfloat16* __restrict__ lo, int n4)
{
    int i = blockIdx.x * 256 + threadIdx.x;
    if (i >= n4) return;
    float4 v = ((const float4*)src)[i];
    __nv_bfloat16 h0, h1, h2, h3, l0, l1, l2, l3;
    split_bf16(v.x, h0, l0); split_bf16(v.y, h1, l1);
    split_bf16(v.z, h2, l2); split_bf16(v.w, h3, l3);
    __nv_bfloat162* ph = (__nv_bfloat162*)hi;
    __nv_bfloat162* pl = (__nv_bfloat162*)lo;
    ph[2*i]   = __nv_bfloat162(h0, h1);
    ph[2*i+1] = __nv_bfloat162(h2, h3);
    pl[2*i]   = __nv_bfloat162(l0, l1);
    pl[2*i+1] = __nv_bfloat162(l2, l3);
}

__global__ __launch_bounds__(256)
void cvt_pair_f16_kernel(const float* __restrict__ src, __half* __restrict__ hi,
                         __half* __restrict__ lo, int n4)
{
    int i = blockIdx.x * 256 + threadIdx.x;
    if (i >= n4) return;
    float4 v = ((const float4*)src)[i];
    __half h0, h1, h2, h3, l0, l1, l2, l3;
    split_f16(v.x, h0, l0); split_f16(v.y, h1, l1);
    split_f16(v.z, h2, l2); split_f16(v.w, h3, l3);
    __half2* ph = (__half2*)hi;
    __half2* pl = (__half2*)lo;
    ph[2*i]   = __half2(h0, h1);
    ph[2*i+1] = __half2(h2, h3);
    pl[2*i]   = __half2(l0, l1);
    pl[2*i+1] = __half2(l2, l3);
}

// merged dense-weight split (5 x D*D), blockIdx.y = which weight
__global__ __launch_bounds__(256)
void cvt5_kernel(Ptr5 ws, __nv_bfloat16* __restrict__ hi, __nv_bfloat16* __restrict__ lo)
{
    int c = blockIdx.y;
    int i = blockIdx.x * 256 + threadIdx.x;           // over D*D/4
    const float* src = ws.p[c];
    size_t base = (size_t)c * D_ * D_;
    float4 v = ((const float4*)src)[i];
    __nv_bfloat16 h0, h1, h2, h3, l0, l1, l2, l3;
    split_bf16(v.x, h0, l0); split_bf16(v.y, h1, l1);
    split_bf16(v.z, h2, l2); split_bf16(v.w, h3, l3);
    __nv_bfloat162* ph = (__nv_bfloat162*)(hi + base);
    __nv_bfloat162* pl = (__nv_bfloat162*)(lo + base);
    ph[2*i]   = __nv_bfloat162(h0, h1);
    ph[2*i+1] = __nv_bfloat162(h2, h3);
    pl[2*i]   = __nv_bfloat162(l0, l1);
    pl[2*i+1] = __nv_bfloat162(l2, l3);
}

// merged conv weight transform: fp16 hi only, [c][tap][o][ci]
__global__ __launch_bounds__(256)
void wtrans5_kernel(Ptr5 cw, __half* __restrict__ wh)
{
    int c = blockIdx.y;
    int idx = blockIdx.x * 256 + threadIdx.x;      // over 7*1024*1024
    int tap = idx >> 20;
    int rem = idx & ((1 << 20) - 1);
    int o  = rem >> 10;
    int ci = rem & 1023;
    float x = __ldg(&cw.p[c][(size_t)o * KCONV + ci * 7 + tap]);
    wh[(size_t)c * (KW*D_*D_) + idx] = __float2half_rn(x);
}

// =====================================================================
// HMMA core pieces (bf16 3-term, dense path)
// =====================================================================
__device__ __forceinline__
void hmma_chunk(uint32_t bufu, int wm, int wn, int lane, float acc[4][4][4])
{
    #pragma unroll
    for (int kk = 0; kk < 32; kk += 16) {
        uint32_t bh[4][2], bl[4][2];
        #pragma unroll
        for (int j = 0; j < 4; j++) {
            int nrow = wn*32 + j*8 + (lane & 7);
            int colb = (kk + ((lane >> 3) & 1)*8) * 2;
            LDMX2(bh[j], bufu + 2*TILE_B + nrow*ROWB + colb);
            LDMX2(bl[j], bufu + 3*TILE_B + nrow*ROWB + colb);
        }
        #pragma unroll
        for (int i = 0; i < 4; i++) {
            int mrow = wm*64 + i*16 + (lane & 15);
            int colb = (kk + ((lane >> 4) & 1)*8) * 2;
            uint32_t ah[4], al[4];
            LDMX4(ah, bufu + 0*TILE_B + mrow*ROWB + colb);
            LDMX4(al, bufu + 1*TILE_B + mrow*ROWB + colb);
            #pragma unroll
            for (int j = 0; j < 4; j++) {
                MMA16816(acc[i][j], ah, bh[j]);
                MMA16816(acc[i][j], ah, bl[j]);
                MMA16816(acc[i][j], al, bh[j]);
            }
        }
    }
}

// fp16 2-term chunk: tiles 0=Ah, 1=Al, 2=Bh
__device__ __forceinline__
void hmma_chunk_f16(uint32_t bufu, int wm, int wn, int lane, float acc[4][4][4])
{
    #pragma unroll
    for (int kk = 0; kk < 32; kk += 16) {
        uint32_t bh[4][2];
        #pragma unroll
        for (int j = 0; j < 4; j++) {
            int nrow = wn*32 + j*8 + (lane & 7);
            int colb = (kk + ((lane >> 3) & 1)*8) * 2;
            LDMX2(bh[j], bufu + 2*TILE_B + nrow*ROWB + colb);
        }
        #pragma unroll
        for (int i = 0; i < 4; i++) {
            int mrow = wm*64 + i*16 + (lane & 15);
            int colb = (kk + ((lane >> 4) & 1)*8) * 2;
            uint32_t ah[4], al[4];
            LDMX4(ah, bufu + 0*TILE_B + mrow*ROWB + colb);
            LDMX4(al, bufu + 1*TILE_B + mrow*ROWB + colb);
            #pragma unroll
            for (int j = 0; j < 4; j++) {
                MMA16816F(acc[i][j], ah, bh[j]);
                MMA16816F(acc[i][j], al, bh[j]);
            }
        }
    }
}

__device__ __forceinline__
void issue_dense(uint32_t smem_base, int c, int tid,
                 const __nv_bfloat16* __restrict__ Ah, const __nv_bfloat16* __restrict__ Al,
                 const __nv_bfloat16* __restrict__ Wh, const __nv_bfloat16* __restrict__ Wl,
                 int bm, int bn, int K)
{
    int k0 = c << 5;
    uint32_t bufu = smem_base + (c & 1) * 4*TILE_B;
    #pragma unroll
    for (int it = 0; it < 8; it++) {
        int g = tid + it*256;
        int tile = g >> 9;
        int ct = g & 511, row = ct >> 2, cc = ct & 3;
        const __nv_bfloat16* src;
        if      (tile == 0) src = Ah + (size_t)(bm+row)*K + k0 + cc*8;
        else if (tile == 1) src = Al + (size_t)(bm+row)*K + k0 + cc*8;
        else if (tile == 2) src = Wh + (size_t)(bn+row)*K + k0 + cc*8;
        else                src = Wl + (size_t)(bn+row)*K + k0 + cc*8;
        CP16(bufu + tile*TILE_B + row*ROWB + cc*16, src, 16);
    }
    CP_COMMIT();
}

__device__ __forceinline__
void epi_f32(float acc[4][4][4], const float* __restrict__ bias,
             float* __restrict__ C, int bm, int bn, int ldc,
             int wm, int wn, int lane)
{
    #pragma unroll
    for (int i = 0; i < 4; i++) {
        int m0 = bm + wm*64 + i*16 + (lane >> 2);
        #pragma unroll
        for (int j = 0; j < 4; j++) {
            int n0 = wn*32 + j*8 + (lane & 3)*2;
            float b0 = bias[bn + n0], b1 = bias[bn + n0 + 1];
            *(float2*)&C[(size_t)m0*ldc + bn + n0] =
                make_float2(acc[i][j][0] + b0, acc[i][j][1] + b1);
            *(float2*)&C[(size_t)(m0+8)*ldc + bn + n0] =
                make_float2(acc[i][j][2] + b0, acc[i][j][3] + b1);
        }
    }
}

__device__ __forceinline__
void epi_b16(float acc[4][4][4], const float* __restrict__ bias,
             __nv_bfloat16* __restrict__ Ch, __nv_bfloat16* __restrict__ Cl,
             int bm, int bn, int ldc, int colbase, int wm, int wn, int lane)
{
    #pragma unroll
    for (int i = 0; i < 4; i++) {
        int m0 = bm + wm*64 + i*16 + (lane >> 2);
        #pragma unroll
        for (int j = 0; j < 4; j++) {
            int n0 = wn*32 + j*8 + (lane & 3)*2;
            float b0 = bias[bn + n0], b1 = bias[bn + n0 + 1];
            float v0 = acc[i][j][0] + b0, v1 = acc[i][j][1] + b1;
            float v2 = acc[i][j][2] + b0, v3 = acc[i][j][3] + b1;
            __nv_bfloat16 h0, h1, h2, h3, l0, l1, l2, l3;
            split_bf16(v0, h0, l0); split_bf16(v1, h1, l1);
            split_bf16(v2, h2, l2); split_bf16(v3, h3, l3);
            size_t o01 = (size_t)m0*ldc + colbase + bn + n0;
            size_t o23 = (size_t)(m0+8)*ldc + colbase + bn + n0;
            *(__nv_bfloat162*)&Ch[o01] = __nv_bfloat162(h0, h1);
            *(__nv_bfloat162*)&Cl[o01] = __nv_bfloat162(l0, l1);
            *(__nv_bfloat162*)&Ch[o23] = __nv_bfloat162(h2, h3);
            *(__nv_bfloat162*)&Cl[o23] = __nv_bfloat162(l2, l3);
        }
    }
}

#define HMMA_PROLOG() \
    extern __shared__ __align__(16) char smem_raw[]; \
    const uint32_t smem_base = smem_u32(smem_raw); \
    const int bm = blockIdx.y * 128, bn = blockIdx.x * 128; \
    const int tid = threadIdx.x; \
    const int wid = tid >> 5, lane = tid & 31; \
    const int wm = wid & 1, wn = wid >> 1; \
    float acc[4][4][4] = {};

#define HMMA_LOOP(NC, ISSUE) \
    ISSUE(0); \
    for (int c = 0; c < (NC); c++) { \
        if (c + 1 < (NC)) { ISSUE(c + 1); CP_WAIT1(); } \
        else              { CP_WAIT0(); } \
        __syncthreads(); \
        hmma_chunk(smem_base + (c & 1)*4*TILE_B, wm, wn, lane, acc); \
        __syncthreads(); \
    }

// ---- generic dense GEMM, fp32 out ----
__global__ __launch_bounds__(256, 2)
void hmma_gemm_kernel(const __nv_bfloat16* __restrict__ Ah, const __nv_bfloat16* __restrict__ Al,
                      const __nv_bfloat16* __restrict__ Wh, const __nv_bfloat16* __restrict__ Wl,
                      const float* __restrict__ bias, float* __restrict__ C,
                      int K, int ldc)
{
    HMMA_PROLOG();
#define ISS(c) issue_dense(smem_base, c, tid, Ah, Al, Wh, Wl, bm, bn, K)
    HMMA_LOOP(K >> 5, ISS);
#undef ISS
    epi_f32(acc, bias, C, bm, bn, ldc, wm, wn, lane);
}

// ---- generic dense GEMM, bf16-pair out ----
__global__ __launch_bounds__(256, 2)
void hmma_gemm_b16_kernel(const __nv_bfloat16* __restrict__ Ah, const __nv_bfloat16* __restrict__ Al,
                          const __nv_bfloat16* __restrict__ Wh, const __nv_bfloat16* __restrict__ Wl,
                          const float* __restrict__ bias,
                          __nv_bfloat16* __restrict__ Ch, __nv_bfloat16* __restrict__ Cl,
                          int K, int ldc)
{
    HMMA_PROLOG();
#define ISS(c) issue_dense(smem_base, c, tid, Ah, Al, Wh, Wl, bm, bn, K)
    HMMA_LOOP(K >> 5, ISS);
#undef ISS
    epi_b16(acc, bias, Ch, Cl, bm, bn, ldc, 0, wm, wn, lane);
}

// ---- QKV: grid.z selects weight/bias/output ----
__global__ __launch_bounds__(256, 2)
void hmma_qkv_kernel(const __nv_bfloat16* __restrict__ Ah, const __nv_bfloat16* __restrict__ Al,
                     const __nv_bfloat16* __restrict__ dwh, const __nv_bfloat16* __restrict__ dwl,
                     QkvArgs args)
{
    const int z = blockIdx.z;
    const __nv_bfloat16* Wh = dwh + (size_t)z * D_ * D_;
    const __nv_bfloat16* Wl = dwl + (size_t)z * D_ * D_;
    HMMA_PROLOG();
#define ISS(c) issue_dense(smem_base, c, tid, Ah, Al, Wh, Wl, bm, bn, D_)
    HMMA_LOOP(D_ >> 5, ISS);
#undef ISS
    epi_f32(acc, args.b[z], args.o[z], bm, bn, D_, wm, wn, lane);
}

// ---- convs: fp16 2-term, 3-stage pipeline, grid.z = conv id ----
__global__ __launch_bounds__(256, 2)
void hmma_conv_kernel(const __half* __restrict__ Fh, const __half* __restrict__ Fl,
                      const __half* __restrict__ wt16, Ptr5 cbs,
                      __nv_bfloat16* __restrict__ msh, __nv_bfloat16* __restrict__ msl)
{
    const int z = blockIdx.z;
    const int dil = 1 << z;
    const int ccol = z * D_;
    const __half* Wh = wt16 + (size_t)z * (KW*D_*D_);
    HMMA_PROLOG();

#define ISSUE_C(c) do { \
    int k0 = (c) << 5; \
    int tap = k0 >> 10, ci0 = k0 & 1023; \
    int offt = (tap - 3) * dil; \
    uint32_t bufu = smem_base + ((c) % 3) * 3*TILE_B; \
    _Pragma("unroll") \
    for (int it = 0; it < 6; it++) { \
        int g = tid + it*256; \
        int tile = g >> 9; \
        int ct = g & 511; int row = ct >> 2, cc = ct & 3; \
        const __half* src; \
        uint32_t sz = 16; \
        if (tile <= 1) { \
            int m = bm + row; \
            int bb = m >> 8, tt = (m & 255) + offt; \
            if (tt >= 0 && tt < T_) \
                src = (tile == 0 ? Fh : Fl) + ((size_t)(bb*T_ + tt))*D_ + ci0 + cc*8; \
            else { src = Fh; sz = 0; } \
        } else { \
            src = Wh + (size_t)tap*D_*D_ + (size_t)(bn+row)*D_ + ci0 + cc*8; \
        } \
        CP16(bufu + tile*TILE_B + row*ROWB + cc*16, src, sz); \
    } \
    CP_COMMIT(); } while (0)

    const int nc = KCONV >> 5;        // 224
    ISSUE_C(0);
    ISSUE_C(1);
    for (int c = 0; c < nc; c++) {
        if (c + 1 < nc) CP_WAIT1(); else CP_WAIT0();
        __syncthreads();
        if (c + 2 < nc) ISSUE_C(c + 2);
        hmma_chunk_f16(smem_base + (c % 3)*3*TILE_B, wm, wn, lane, acc);
    }
#undef ISSUE_C
    __syncthreads();
    epi_b16(acc, cbs.p[z], msh, msl, bm, bn, K5D, ccol, wm, wn, lane);
}

// =====================================================================
// LayerNorm + exact GELU: reads z fp32, writes zh/zl bf16 pairs.
// =====================================================================
__global__ __launch_bounds__(256)
void ln_gelu_kernel(const float* __restrict__ z, const float* __restrict__ g,
                    const float* __restrict__ b,
                    __nv_bfloat16* __restrict__ zh, __nv_bfloat16* __restrict__ zl)
{
    const int row = blockIdx.x;
    const int tid = threadIdx.x;
    const float* p = z + (size_t)row * D_;
    float4 v = ((const float4*)p)[tid];
    float s  = v.x + v.y + v.z + v.w;
    float ss = v.x*v.x + v.y*v.y + v.z*v.z + v.w*v.w;
    #pragma unroll
    for (int o = 16; o; o >>= 1) {
        s  += __shfl_xor_sync(0xffffffffu, s,  o);
        ss += __shfl_xor_sync(0xffffffffu, ss, o);
    }
    __shared__ float ws[8], wss[8];
    __shared__ float mu_s, inv_s;
    int lane = tid & 31, wid = tid >> 5;
    if (lane == 0) { ws[wid] = s; wss[wid] = ss; }
    __syncthreads();
    if (tid == 0) {
        float S = 0.f, SS = 0.f;
        #pragma unroll
        for (int i = 0; i < 8; i++) { S += ws[i]; SS += wss[i]; }
        float mu = S * (1.f / D_);
        float var = SS * (1.f / D_) - mu * mu;
        mu_s = mu;
        inv_s = rsqrtf(var + 1e-5f);
    }
    __syncthreads();
    float mu = mu_s, inv = inv_s;
    float4 gg = ((const float4*)g)[tid];
    float4 bb = ((const float4*)b)[tid];
    float y[4] = { (v.x-mu)*inv*gg.x + bb.x, (v.y-mu)*inv*gg.y + bb.y,
                   (v.z-mu)*inv*gg.z + bb.z, (v.w-mu)*inv*gg.w + bb.w };
    float o[4];
    o[0] = 0.5f*y[0]*(1.f + erff(y[0]*0.70710678118654752f));
    o[1] = 0.5f*y[1]*(1.f + erff(y[1]*0.70710678118654752f));
    o[2] = 0.5f*y[2]*(1.f + erff(y[2]*0.70710678118654752f));
    o[3] = 0.5f*y[3]*(1.f + erff(y[3]*0.70710678118654752f));
    __nv_bfloat16 h0, h1, h2, h3, l0, l1, l2, l3;
    split_bf16(o[0], h0, l0); split_bf16(o[1], h1, l1);
    split_bf16(o[2], h2, l2); split_bf16(o[3], h3, l3);
    __nv_bfloat162* ph = (__nv_bfloat162*)(zh + (size_t)row * D_);
    __nv_bfloat162* pl = (__nv_bfloat162*)(zl + (size_t)row * D_);
    ph[2*tid]   = __nv_bfloat162(h0, h1);
    ph[2*tid+1] = __nv_bfloat162(h2, h3);
    pl[2*tid]   = __nv_bfloat162(l0, l1);
    pl[2*tid+1] = __nv_bfloat162(l2, l3);
}

// =====================================================================
// Attention (fp32 SIMT)
// =====================================================================
__global__ __launch_bounds__(256)
void attn_scores_kernel(const float* __restrict__ q, const float* __restrict__ kmat,
                        float* __restrict__ s)
{
    const int bh = blockIdx.z;
    const int b = bh >> 4, h = bh & 15;
    const int bm = blockIdx.y * 64, bn = blockIdx.x * 64;
    __shared__ __align__(16) float As[16][68];
    __shared__ __align__(16) float Bs[16][68];
    const int tid = threadIdx.x;
    const int lk = tid & 15, lr = tid >> 4;
    const int tx = tid & 15, ty = tid >> 4;
    float acc[4][4] = {};
    for (int k0 = 0; k0 < DH; k0 += 16) {
        #pragma unroll
        for (int p = 0; p < 4; p++) {
            int m = bm + lr + 16*p;
            As[lk][lr+16*p] = q[((size_t)(b*T_ + m))*D_ + h*DH + k0 + lk];
        }
        #pragma unroll
        for (int p = 0; p < 4; p++) {
            int n = bn + lr + 16*p;
            Bs[lk][lr+16*p] = kmat[((size_t)(b*T_ + n))*D_ + h*DH + k0 + lk];
        }
        __syncthreads();
        #pragma unroll
        for (int k = 0; k < 16; k++) {
            float a[4], bb[4];
            *(float4*)a  = *(const float4*)&As[k][ty*4];
            *(float4*)bb = *(const float4*)&Bs[k][tx*4];
            #pragma unroll
            for (int i = 0; i < 4; i++)
                #pragma unroll
                for (int j = 0; j < 4; j++)
                    acc[i][j] += a[i]*bb[j];
        }
        __syncthreads();
    }
    #pragma unroll
    for (int i = 0; i < 4; i++) {
        int m = bm + ty*4 + i;
        #pragma unroll
        for (int j = 0; j < 4; j++) {
            int n = bn + tx*4 + j;
            s[((size_t)bh*T_ + m)*T_ + n] = acc[i][j] * 0.125f;
        }
    }
}

__global__ __launch_bounds__(256)
void softmax_kernel(float* __restrict__ s)
{
    int row  = (blockIdx.x * blockDim.x + threadIdx.x) >> 5;
    int lane = threadIdx.x & 31;
    float* p = s + (size_t)row * T_;
    float v[8];
    float m = -1e30f;
    #pragma unroll
    for (int r = 0; r < 8; r++) { v[r] = p[lane + 32*r]; m = fmaxf(m, v[r]); }
    #pragma unroll
    for (int o = 16; o; o >>= 1) m = fmaxf(m, __shfl_xor_sync(0xffffffffu, m, o));
    float sum = 0.f;
    #pragma unroll
    for (int r = 0; r < 8; r++) { v[r] = __expf(v[r] - m); sum += v[r]; }
    #pragma unroll
    for (int o = 16; o; o >>= 1) sum += __shfl_xor_sync(0xffffffffu, sum, o);
    float inv = 1.f / sum;
    #pragma unroll
    for (int r = 0; r < 8; r++) p[lane + 32*r] = v[r] * inv;
}

// ctx written directly as bf16 hi/lo pairs
__global__ __launch_bounds__(256)
void attn_ctx_kernel(const float* __restrict__ s, const float* __restrict__ v,
                     __nv_bfloat16* __restrict__ cxh, __nv_bfloat16* __restrict__ cxl)
{
    const int bh = blockIdx.z;
    const int b = bh >> 4, h = bh & 15;
    const int bm = blockIdx.y * 64;
    __shared__ __align__(16) float As[16][68];
    __shared__ __align__(16) float Bs[16][68];
    const int tid = threadIdx.x;
    const int lk = tid & 15, lr = tid >> 4;
    const int bn_ = tid & 63, bkk = tid >> 6;
    const int tx = tid & 15, ty = tid >> 4;
    float acc[4][4] = {};
    for (int k0 = 0; k0 < T_; k0 += 16) {
        #pragma unroll
        for (int p = 0; p < 4; p++) {
            int m = bm + lr + 16*p;
            As[lk][lr+16*p] = s[((size_t)bh*T_ + m)*T_ + k0 + lk];
        }
        #pragma unroll
        for (int p = 0; p < 4; p++) {
            int jj = bkk + 4*p;
            Bs[jj][bn_] = v[((size_t)(b*T_ + k0 + jj))*D_ + h*DH + bn_];
        }
        __syncthreads();
        #pragma unroll
        for (int k = 0; k < 16; k++) {
            float a[4], bb[4];
            *(float4*)a  = *(const float4*)&As[k][ty*4];
            *(float4*)bb = *(const float4*)&Bs[k][tx*4];
            #pragma unroll
            for (int i = 0; i < 4; i++)
                #pragma unroll
                for (int j = 0; j < 4; j++)
                    acc[i][j] += a[i]*bb[j];
        }
        __syncthreads();
    }
    #pragma unroll
    for (int i = 0; i < 4; i++) {
        int m = bm + ty*4 + i;
        size_t o = ((size_t)(b*T_ + m))*D_ + h*DH + tx*4;
        __nv_bfloat16 h0, h1, h2, h3, l0, l1, l2, l3;
        split_bf16(acc[i][0], h0, l0); split_bf16(acc[i][1], h1, l1);
        split_bf16(acc[i][2], h2, l2); split_bf16(acc[i][3], h3, l3);
        *(__nv_bfloat162*)&cxh[o]   = __nv_bfloat162(h0, h1);
        *(__nv_bfloat162*)&cxh[o+2] = __nv_bfloat162(h2, h3);
        *(__nv_bfloat162*)&cxl[o]   = __nv_bfloat162(l0, l1);
        *(__nv_bfloat162*)&cxl[o+2] = __nv_bfloat162(l2, l3);
    }
}

// =====================================================================
// GAT pieces (fp32)
// =====================================================================
__global__ __launch_bounds__(256)
void e12_kernel(const float* __restrict__ hg, const float* __restrict__ a1,
                const float* __restrict__ a2, float* __restrict__ e1,
                float* __restrict__ e2)
{
    int wid  = (blockIdx.x * blockDim.x + threadIdx.x) >> 5;
    int lane = threadIdx.x & 31;
    int n = wid >> 3, h = wid & 7;
    const float* row = hg + (size_t)n * D_ + h * GDH;
    float s1 = 0.f, s2 = 0.f;
    #pragma unroll
    for (int r = 0; r < 4; r++) {
        float x = row[lane + 32*r];
        s1 += x * a1[lane + 32*r];
        s2 += x * a2[lane + 32*r];
    }
    #pragma unroll
    for (int o = 16; o; o >>= 1) {
        s1 += __shfl_xor_sync(0xffffffffu, s1, o);
        s2 += __shfl_xor_sync(0xffffffffu, s2, o);
    }
    if (lane == 0) { e1[n*HGAT + h] = s1; e2[n*HGAT + h] = s2; }
}

__global__ __launch_bounds__(256)
void e2max_kernel(const float* __restrict__ e2, float* __restrict__ m2)
{
    int h = blockIdx.x, tid = threadIdx.x;
    float m = -1e30f;
    for (int n = tid; n < M_; n += 256) m = fmaxf(m, e2[n*HGAT + h]);
    __shared__ float sm[256];
    sm[tid] = m; __syncthreads();
    for (int s = 128; s > 0; s >>= 1) {
        if (tid < s) sm[tid] = fmaxf(sm[tid], sm[tid + s]);
        __syncthreads();
    }
    if (tid == 0) m2[h] = sm[0];
}

__global__ __launch_bounds__(256)
void gat_gemm_kernel(const float* __restrict__ hg, const float* __restrict__ e1,
                     const float* __restrict__ e2, const float* __restrict__ m2,
                     const float* __restrict__ feat, float* __restrict__ out)
{
    const int h  = blockIdx.x;
    const int bm = blockIdx.y * 64;
    __shared__ __align__(16) float As[16][68];
    __shared__ __align__(16) float Bs[16][136];
    __shared__ float se1[64], smrow[64];
    const int tid = threadIdx.x;
    if (tid < 64) {
        float v1 = e1[(bm + tid)*HGAT + h];
        float s = v1 + m2[h];
        smrow[tid] = s > 0.f ? s : 0.2f * s;
        se1[tid] = v1;
    }
    __syncthreads();
    const int lk = tid & 15, lr = tid >> 4;
    const int bd = tid & 127, bj = tid >> 7;
    const int tx = tid & 15, ty = tid >> 4;
    float acc[4][8] = {};
    float dacc[4] = {};
    for (int k0 = 0; k0 < M_; k0 += 16) {
        float e2v = e2[(k0 + lk)*HGAT + h];
        #pragma unroll
        for (int p = 0; p < 4; p++) {
            int i = lr + 16*p;
            float s = se1[i] + e2v;
            float l = s > 0.f ? s : 0.2f * s;
            As[lk][i] = __expf(l - smrow[i]);
        }
        #pragma unroll
        for (int p = 0; p < 8; p++) {
            int jj = bj + 2*p;
            Bs[jj][bd] = hg[(size_t)(k0 + jj)*D_ + h*GDH + bd];
        }
        __syncthreads();
        #pragma unroll
        for (int k = 0; k < 16; k++) {
            float a[4], b[8];
            *(float4*)a      = *(const float4*)&As[k][ty*4];
            *(float4*)&b[0]  = *(const float4*)&Bs[k][tx*8];
            *(float4*)&b[4]  = *(const float4*)&Bs[k][tx*8 + 4];
            #pragma unroll
            for (int i = 0; i < 4; i++) {
                dacc[i] += a[i];
                #pragma unroll
                for (int j = 0; j < 8; j++)
                    acc[i][j] += a[i]*b[j];
            }
        }
        __syncthreads();
    }
    #pragma unroll
    for (int i = 0; i < 4; i++) {
        int m = bm + ty*4 + i;
        float inv = 1.f / dacc[i];
        #pragma unroll
        for (int j = 0; j < 8; j++) {
            float v = acc[i][j] * inv;
            v = v > 0.f ? v : expm1f(v);                 // ELU
            int col = h*GDH + tx*8 + j;
            out[(size_t)m*D_ + col] = v + feat[(size_t)m*D_ + col];
        }
    }
}

// =====================================================================
extern "C" void kernel_launch(void* const* d_in, const int* in_sizes, int n_in,
                              void* d_out, int out_size)
{
    const float* feat = (const float*)d_in[0];

    Ptr5 cw{}, cb{};
    int wi = 0, bi = 0;
    for (int i = 1; i <= 10; i++) {
        if (in_sizes[i] == D_ * D_ * KW) { if (wi < 5) cw.p[wi++] = (const float*)d_in[i]; }
        else                             { if (bi < 5) cb.p[bi++] = (const float*)d_in[i]; }
    }

    const float* fp_w = (const float*)d_in[11];
    const float* fp_b = (const float*)d_in[12];
    const float* ln_g = (const float*)d_in[13];
    const float* ln_b = (const float*)d_in[14];
    const float* wq = (const float*)d_in[15];
    const float* bq = (const float*)d_in[16];
    const float* wk = (const float*)d_in[17];
    const float* bk = (const float*)d_in[18];
    const float* wv = (const float*)d_in[19];
    const float* bv = (const float*)d_in[20];
    const float* wo = (const float*)d_in[21];
    const float* bo = (const float*)d_in[22];
    const float* gat_w = (const float*)d_in[23];
    const float* gat_b = (const float*)d_in[24];
    const float* a1 = (const float*)d_in[25];
    const float* a2 = (const float*)d_in[26];
    float* out = (float*)d_out;

    __half *f16h, *f16l, *wt16;
    __nv_bfloat16 *fph, *fpl, *dwh, *dwl;
    __nv_bfloat16 *msh, *msl, *zh, *zl, *cxh, *cxl, *ath, *atl;
    float *z, *q, *k, *v, *s, *hg, *e1, *e2, *m2;
    cudaGetSymbolAddress((void**)&f16h, g_f16h);
    cudaGetSymbolAddress((void**)&f16l, g_f16l);
    cudaGetSymbolAddress((void**)&wt16, g_wt16);
    cudaGetSymbolAddress((void**)&fph, g_fph);
    cudaGetSymbolAddress((void**)&fpl, g_fpl);
    cudaGetSymbolAddress((void**)&dwh, g_dwh);
    cudaGetSymbolAddress((void**)&dwl, g_dwl);
    cudaGetSymbolAddress((void**)&msh, g_msh);
    cudaGetSymbolAddress((void**)&msl, g_msl);
    cudaGetSymbolAddress((void**)&z,   g_z);
    cudaGetSymbolAddress((void**)&zh,  g_zh);
    cudaGetSymbolAddress((void**)&zl,  g_zl);
    cudaGetSymbolAddress((void**)&q,   g_q);
    cudaGetSymbolAddress((void**)&k,   g_k);
    cudaGetSymbolAddress((void**)&v,   g_v);
    cudaGetSymbolAddress((void**)&s,   g_s);
    cudaGetSymbolAddress((void**)&cxh, g_cxh);
    cudaGetSymbolAddress((void**)&cxl, g_cxl);
    cudaGetSymbolAddress((void**)&ath, g_ath);
    cudaGetSymbolAddress((void**)&atl, g_atl);
    cudaGetSymbolAddress((void**)&hg,  g_hg);
    cudaGetSymbolAddress((void**)&e1,  g_e1);
    cudaGetSymbolAddress((void**)&e2,  g_e2);
    cudaGetSymbolAddress((void**)&m2,  g_m2);

    cudaFuncSetAttribute(hmma_gemm_kernel,     cudaFuncAttributeMaxDynamicSharedMemorySize, SMEM_DYN);
    cudaFuncSetAttribute(hmma_gemm_b16_kernel, cudaFuncAttributeMaxDynamicSharedMemorySize, SMEM_DYN);
    cudaFuncSetAttribute(hmma_qkv_kernel,      cudaFuncAttributeMaxDynamicSharedMemorySize, SMEM_DYN);
    cudaFuncSetAttribute(hmma_conv_kernel,     cudaFuncAttributeMaxDynamicSharedMemorySize, SMEM_CONV);

    const size_t WTN = (size_t)KW * D_ * D_;

    // 0) splits: features fp16 pair, conv weights fp16 hi, dense weights bf16 pairs
    cvt_pair_f16_kernel<<<(M_*D_/4 + 255)/256, 256>>>(feat, f16h, f16l, M_*D_/4);
    wtrans5_kernel<<<dim3((int)(WTN/256), 5), 256>>>(cw, wt16);
    cvt_pair_kernel<<<(D_*K5D/4 + 255)/256, 256>>>(fp_w, fph, fpl, D_*K5D/4);
    Ptr5 dws{{ wq, wk, wv, wo, gat_w }};
    cvt5_kernel<<<dim3(D_*D_/4/256, 5), 256>>>(dws, dwh, dwl);

    // 1) dilated convs (fp16 2-term HMMA, 3-stage) -> msh/msl bf16 pairs
    hmma_conv_kernel<<<dim3(8, 16, 5), 256, SMEM_CONV>>>(f16h, f16l, wt16, cb, msh, msl);

    // 2) fusion projection (K=5120, bf16 3-term) -> z fp32, then LN+GELU -> zh/zl
    hmma_gemm_kernel<<<dim3(8, 16), 256, SMEM_DYN>>>(msh, msl, fph, fpl, fp_b, z, K5D, D_);
    ln_gelu_kernel<<<M_, 256>>>(z, ln_g, ln_b, zh, zl);

    // 3) q, k, v projections (merged)
    QkvArgs qkv{{ q, k, v }, { bq, bk, bv }};
    hmma_qkv_kernel<<<dim3(8, 16, 3), 256, SMEM_DYN>>>(zh, zl, dwh, dwl, qkv);

    // 4) attention (fp32) -> cxh/cxl bf16 pairs
    attn_scores_kernel<<<dim3(4, 4, B_*HMHA), 256>>>(q, k, s);
    softmax_kernel<<<(B_*HMHA*T_)/8, 256>>>(s);
    attn_ctx_kernel<<<dim3(1, 4, B_*HMHA), 256>>>(s, v, cxh, cxl);

    // 5) wo projection -> ath/atl bf16 pairs; gat_w projection -> hg fp32
    hmma_gemm_b16_kernel<<<dim3(8, 16), 256, SMEM_DYN>>>(cxh, cxl,
        dwh + 3*(size_t)D_*D_, dwl + 3*(size_t)D_*D_, bo, ath, atl, D_, D_);
    hmma_gemm_kernel<<<dim3(8, 16), 256, SMEM_DYN>>>(ath, atl,
        dwh + 4*(size_t)D_*D_, dwl + 4*(size_t)D_*D_, gat_b, hg, D_, D_);

    // 6) GAT logits + stable max
    e12_kernel<<<(M_*HGAT)/8, 256>>>(hg, a1, a2, e1, e2);
    e2max_kernel<<<HGAT, 256>>>(e2, m2);

    // 7) GAT aggregation + ELU + residual -> d_out
    gat_gemm_kernel<<<dim3(HGAT, 32), 256>>>(hg, e1, e2, m2, feat, out);
}

// round 9
// speedup vs baseline: 4.3477x; 1.2482x over previous
#include <cuda_runtime.h>
#include <cuda_bf16.h>
#include <cuda_fp16.h>
#include <math.h>
#include <stdint.h>

#define D_   1024
#define T_   256
#define B_   8
#define M_   (B_*T_)        // 2048 rows (b,t)
#define HMHA 16
#define DH   64
#define HGAT 8
#define GDH  128
#define KW   7
#define K5D  (5*D_)
#define KCONV (KW*D_)       // 7168

#define ROWB   80                    // bytes per smem row (32 fp16 + pad)
#define TILE_B (128*ROWB)            // 10240 B per tile
#define SMEM_3S (3*3*TILE_B)         // 3 stages x 3 tiles = 92160

// ===================== PTX helpers (baseline ISA only) =====================
__device__ __forceinline__ uint32_t smem_u32(const void* p) {
    uint32_t a;
    asm("{ .reg .u64 t; cvta.to.shared.u64 t, %1; cvt.u32.u64 %0, t; }"
        : "=r"(a) : "l"(p));
    return a;
}
#define CP16(dst, src, sz) \
    asm volatile("cp.async.cg.shared.global [%0], [%1], 16, %2;" \
                 :: "r"(dst), "l"(src), "r"(sz))
#define CP_COMMIT() asm volatile("cp.async.commit_group;" ::: "memory")
#define CP_WAIT1()  asm volatile("cp.async.wait_group 1;" ::: "memory")
#define CP_WAIT0()  asm volatile("cp.async.wait_group 0;" ::: "memory")

#define LDMX4(r, addr) \
    asm volatile("ldmatrix.sync.aligned.m8n8.x4.shared.b16 {%0,%1,%2,%3}, [%4];" \
        : "=r"((r)[0]), "=r"((r)[1]), "=r"((r)[2]), "=r"((r)[3]) : "r"(addr))
#define LDMX2(r, addr) \
    asm volatile("ldmatrix.sync.aligned.m8n8.x2.shared.b16 {%0,%1}, [%2];" \
        : "=r"((r)[0]), "=r"((r)[1]) : "r"(addr))

#define MMA16816F(c, a, b) \
    asm volatile("mma.sync.aligned.m16n8k16.row.col.f32.f16.f16.f32 " \
        "{%0,%1,%2,%3}, {%4,%5,%6,%7}, {%8,%9}, {%0,%1,%2,%3};" \
        : "+f"((c)[0]), "+f"((c)[1]), "+f"((c)[2]), "+f"((c)[3]) \
        : "r"((a)[0]), "r"((a)[1]), "r"((a)[2]), "r"((a)[3]), \
          "r"((b)[0]), "r"((b)[1]))

struct Ptr5  { const float* p[5]; };
struct QkvArgs { float* o[3]; const float* b[3]; };

// ---------------- scratch (device globals; no allocation) ----------------
__device__ __half g_f16h[M_ * D_];                 // feat fp16 hi
__device__ __half g_f16l[M_ * D_];                 // feat fp16 lo
__device__ __half g_wt16[5 * KW * D_ * D_];        // conv weights fp16 hi [c][tap][o][ci]
__device__ __half g_fp16[D_ * K5D];                // fusion weight fp16 hi
__device__ __half g_dw16[5 * D_ * D_];             // wq,wk,wv,wo,gat_w fp16 hi
__device__ __half g_msh[M_ * K5D];                 // conv out fp16 pair
__device__ __half g_msl[M_ * K5D];
__device__ float  g_z  [M_ * D_];
__device__ __half g_zh [M_ * D_];
__device__ __half g_zl [M_ * D_];
__device__ float  g_q  [M_ * D_];
__device__ float  g_k  [M_ * D_];
__device__ float  g_v  [M_ * D_];
__device__ float  g_s  [B_*HMHA * T_ * T_];
__device__ __half g_cxh[M_ * D_];
__device__ __half g_cxl[M_ * D_];
__device__ __half g_ath[M_ * D_];
__device__ __half g_atl[M_ * D_];
__device__ float  g_hg [M_ * D_];
__device__ __half g_hgT[D_ * M_];                  // transpose of hg, fp16
__device__ float  g_e1[M_ * HGAT];
__device__ float  g_e2[M_ * HGAT];
__device__ float  g_m2[HGAT];

// =====================================================================
// split helpers / conversion kernels
// =====================================================================
__device__ __forceinline__ void split_f16(float v, __half& h, __half& l) {
    h = __float2half_rn(v);
    l = __float2half_rn(v - __half2float(h));
}

__global__ __launch_bounds__(256)
void cvt_pair_f16_kernel(const float* __restrict__ src, __half* __restrict__ hi,
                         __half* __restrict__ lo, int n4)
{
    int i = blockIdx.x * 256 + threadIdx.x;
    if (i >= n4) return;
    float4 v = ((const float4*)src)[i];
    __half h0, h1, h2, h3, l0, l1, l2, l3;
    split_f16(v.x, h0, l0); split_f16(v.y, h1, l1);
    split_f16(v.z, h2, l2); split_f16(v.w, h3, l3);
    __half2* ph = (__half2*)hi;
    __half2* pl = (__half2*)lo;
    ph[2*i]   = __half2(h0, h1);
    ph[2*i+1] = __half2(h2, h3);
    pl[2*i]   = __half2(l0, l1);
    pl[2*i+1] = __half2(l2, l3);
}

__global__ __launch_bounds__(256)
void cvt_f16_kernel(const float* __restrict__ src, __half* __restrict__ hi, int n4)
{
    int i = blockIdx.x * 256 + threadIdx.x;
    if (i >= n4) return;
    float4 v = ((const float4*)src)[i];
    __half2* ph = (__half2*)hi;
    ph[2*i]   = __half2(__float2half_rn(v.x), __float2half_rn(v.y));
    ph[2*i+1] = __half2(__float2half_rn(v.z), __float2half_rn(v.w));
}

// merged dense-weight convert (5 x D*D), fp16 hi only
__global__ __launch_bounds__(256)
void cvt5_f16_kernel(Ptr5 ws, __half* __restrict__ hi)
{
    int c = blockIdx.y;
    int i = blockIdx.x * 256 + threadIdx.x;           // over D*D/4
    float4 v = ((const float4*)ws.p[c])[i];
    __half2* ph = (__half2*)(hi + (size_t)c * D_ * D_);
    ph[2*i]   = __half2(__float2half_rn(v.x), __float2half_rn(v.y));
    ph[2*i+1] = __half2(__float2half_rn(v.z), __float2half_rn(v.w));
}

// merged conv weight transform: fp16 hi only, [c][tap][o][ci]
__global__ __launch_bounds__(256)
void wtrans5_kernel(Ptr5 cw, __half* __restrict__ wh)
{
    int c = blockIdx.y;
    int idx = blockIdx.x * 256 + threadIdx.x;      // over 7*1024*1024
    int tap = idx >> 20;
    int rem = idx & ((1 << 20) - 1);
    int o  = rem >> 10;
    int ci = rem & 1023;
    float x = __ldg(&cw.p[c][(size_t)o * KCONV + ci * 7 + tap]);
    wh[(size_t)c * (KW*D_*D_) + idx] = __float2half_rn(x);
}

// hg fp32 (2048 x 1024) -> hgT fp16 (1024 x 2048)
__global__ __launch_bounds__(256)
void transpose_f16_kernel(const float* __restrict__ hg, __half* __restrict__ hgT)
{
    __shared__ float tile[32][33];
    int j0 = blockIdx.x * 32, c0 = blockIdx.y * 32;
    int tx = threadIdx.x & 31, ty = threadIdx.x >> 5;   // 32 x 8
    #pragma unroll
    for (int r = ty; r < 32; r += 8)
        tile[r][tx] = hg[(size_t)(j0 + r) * D_ + c0 + tx];
    __syncthreads();
    #pragma unroll
    for (int r = ty; r < 32; r += 8)
        hgT[(size_t)(c0 + r) * M_ + j0 + tx] = __float2half_rn(tile[tx][r]);
}

// =====================================================================
// fp16 2-term HMMA chunk: tiles 0=Ah, 1=Al, 2=Bh
// =====================================================================
__device__ __forceinline__
void hmma_chunk_f16(uint32_t bufu, int wm, int wn, int lane, float acc[4][4][4])
{
    #pragma unroll
    for (int kk = 0; kk < 32; kk += 16) {
        uint32_t bh[4][2];
        #pragma unroll
        for (int j = 0; j < 4; j++) {
            int nrow = wn*32 + j*8 + (lane & 7);
            int colb = (kk + ((lane >> 3) & 1)*8) * 2;
            LDMX2(bh[j], bufu + 2*TILE_B + nrow*ROWB + colb);
        }
        #pragma unroll
        for (int i = 0; i < 4; i++) {
            int mrow = wm*64 + i*16 + (lane & 15);
            int colb = (kk + ((lane >> 4) & 1)*8) * 2;
            uint32_t ah[4], al[4];
            LDMX4(ah, bufu + 0*TILE_B + mrow*ROWB + colb);
            LDMX4(al, bufu + 1*TILE_B + mrow*ROWB + colb);
            #pragma unroll
            for (int j = 0; j < 4; j++) {
                MMA16816F(acc[i][j], ah, bh[j]);
                MMA16816F(acc[i][j], al, bh[j]);
            }
        }
    }
}

__device__ __forceinline__
void issue_d16(uint32_t smem_base, int c, int tid,
               const __half* __restrict__ Ah, const __half* __restrict__ Al,
               const __half* __restrict__ Wh, int bm, int bn, int K)
{
    int k0 = c << 5;
    uint32_t bufu = smem_base + (c % 3) * 3*TILE_B;
    #pragma unroll
    for (int it = 0; it < 6; it++) {
        int g = tid + it*256;
        int tile = g >> 9;
        int ct = g & 511, row = ct >> 2, cc = ct & 3;
        const __half* src;
        if      (tile == 0) src = Ah + (size_t)(bm+row)*K + k0 + cc*8;
        else if (tile == 1) src = Al + (size_t)(bm+row)*K + k0 + cc*8;
        else                src = Wh + (size_t)(bn+row)*K + k0 + cc*8;
        CP16(bufu + tile*TILE_B + row*ROWB + cc*16, src, 16);
    }
    CP_COMMIT();
}

__device__ __forceinline__
void epi_f32(float acc[4][4][4], const float* __restrict__ bias,
             float* __restrict__ C, int bm, int bn, int ldc,
             int wm, int wn, int lane)
{
    #pragma unroll
    for (int i = 0; i < 4; i++) {
        int m0 = bm + wm*64 + i*16 + (lane >> 2);
        #pragma unroll
        for (int j = 0; j < 4; j++) {
            int n0 = wn*32 + j*8 + (lane & 3)*2;
            float b0 = bias[bn + n0], b1 = bias[bn + n0 + 1];
            *(float2*)&C[(size_t)m0*ldc + bn + n0] =
                make_float2(acc[i][j][0] + b0, acc[i][j][1] + b1);
            *(float2*)&C[(size_t)(m0+8)*ldc + bn + n0] =
                make_float2(acc[i][j][2] + b0, acc[i][j][3] + b1);
        }
    }
}

__device__ __forceinline__
void epi_f16pair(float acc[4][4][4], const float* __restrict__ bias,
                 __half* __restrict__ Ch, __half* __restrict__ Cl,
                 int bm, int bn, int ldc, int colbase, int wm, int wn, int lane)
{
    #pragma unroll
    for (int i = 0; i < 4; i++) {
        int m0 = bm + wm*64 + i*16 + (lane >> 2);
        #pragma unroll
        for (int j = 0; j < 4; j++) {
            int n0 = wn*32 + j*8 + (lane & 3)*2;
            float b0 = bias[bn + n0], b1 = bias[bn + n0 + 1];
            float v0 = acc[i][j][0] + b0, v1 = acc[i][j][1] + b1;
            float v2 = acc[i][j][2] + b0, v3 = acc[i][j][3] + b1;
            __half h0, h1, h2, h3, l0, l1, l2, l3;
            split_f16(v0, h0, l0); split_f16(v1, h1, l1);
            split_f16(v2, h2, l2); split_f16(v3, h3, l3);
            size_t o01 = (size_t)m0*ldc + colbase + bn + n0;
            size_t o23 = (size_t)(m0+8)*ldc + colbase + bn + n0;
            *(__half2*)&Ch[o01] = __half2(h0, h1);
            *(__half2*)&Cl[o01] = __half2(l0, l1);
            *(__half2*)&Ch[o23] = __half2(h2, h3);
            *(__half2*)&Cl[o23] = __half2(l2, l3);
        }
    }
}

#define HMMA_PROLOG() \
    extern __shared__ __align__(16) char smem_raw[]; \
    const uint32_t smem_base = smem_u32(smem_raw); \
    const int bm = blockIdx.y * 128, bn = blockIdx.x * 128; \
    const int tid = threadIdx.x; \
    const int wid = tid >> 5, lane = tid & 31; \
    const int wm = wid & 1, wn = wid >> 1; \
    float acc[4][4][4] = {};

#define HMMA_LOOP3(NC, ISSUE) \
    ISSUE(0); \
    ISSUE(1); \
    for (int c = 0; c < (NC); c++) { \
        if (c + 1 < (NC)) CP_WAIT1(); else CP_WAIT0(); \
        __syncthreads(); \
        if (c + 2 < (NC)) ISSUE(c + 2); \
        hmma_chunk_f16(smem_base + (c % 3)*3*TILE_B, wm, wn, lane, acc); \
        __syncthreads(); \
    }

// ---- dense GEMM fp16 2-term, fp32 out ----
__global__ __launch_bounds__(256, 2)
void hmma_d16_f32(const __half* __restrict__ Ah, const __half* __restrict__ Al,
                  const __half* __restrict__ Wh, const float* __restrict__ bias,
                  float* __restrict__ C, int K, int ldc)
{
    HMMA_PROLOG();
#define ISS(c) issue_d16(smem_base, c, tid, Ah, Al, Wh, bm, bn, K)
    HMMA_LOOP3(K >> 5, ISS);
#undef ISS
    epi_f32(acc, bias, C, bm, bn, ldc, wm, wn, lane);
}

// ---- dense GEMM fp16 2-term, fp16-pair out ----
__global__ __launch_bounds__(256, 2)
void hmma_d16_pair(const __half* __restrict__ Ah, const __half* __restrict__ Al,
                   const __half* __restrict__ Wh, const float* __restrict__ bias,
                   __half* __restrict__ Ch, __half* __restrict__ Cl, int K, int ldc)
{
    HMMA_PROLOG();
#define ISS(c) issue_d16(smem_base, c, tid, Ah, Al, Wh, bm, bn, K)
    HMMA_LOOP3(K >> 5, ISS);
#undef ISS
    epi_f16pair(acc, bias, Ch, Cl, bm, bn, ldc, 0, wm, wn, lane);
}

// ---- QKV: grid.z selects weight/bias/output ----
__global__ __launch_bounds__(256, 2)
void hmma_d16_qkv(const __half* __restrict__ Ah, const __half* __restrict__ Al,
                  const __half* __restrict__ dw16, QkvArgs args)
{
    const int z = blockIdx.z;
    const __half* Wh = dw16 + (size_t)z * D_ * D_;
    HMMA_PROLOG();
#define ISS(c) issue_d16(smem_base, c, tid, Ah, Al, Wh, bm, bn, D_)
    HMMA_LOOP3(D_ >> 5, ISS);
#undef ISS
    epi_f32(acc, args.b[z], args.o[z], bm, bn, D_, wm, wn, lane);
}

// ---- convs: fp16 2-term gather, grid.z = conv id ----
__global__ __launch_bounds__(256, 2)
void hmma_conv_kernel(const __half* __restrict__ Fh, const __half* __restrict__ Fl,
                      const __half* __restrict__ wt16, Ptr5 cbs,
                      __half* __restrict__ msh, __half* __restrict__ msl)
{
    const int z = blockIdx.z;
    const int dil = 1 << z;
    const int ccol = z * D_;
    const __half* Wh = wt16 + (size_t)z * (KW*D_*D_);
    HMMA_PROLOG();

#define ISSUE_C(c) do { \
    int k0 = (c) << 5; \
    int tap = k0 >> 10, ci0 = k0 & 1023; \
    int offt = (tap - 3) * dil; \
    uint32_t bufu = smem_base + ((c) % 3) * 3*TILE_B; \
    _Pragma("unroll") \
    for (int it = 0; it < 6; it++) { \
        int g = tid + it*256; \
        int tile = g >> 9; \
        int ct = g & 511; int row = ct >> 2, cc = ct & 3; \
        const __half* src; \
        uint32_t sz = 16; \
        if (tile <= 1) { \
            int m = bm + row; \
            int bb = m >> 8, tt = (m & 255) + offt; \
            if (tt >= 0 && tt < T_) \
                src = (tile == 0 ? Fh : Fl) + ((size_t)(bb*T_ + tt))*D_ + ci0 + cc*8; \
            else { src = Fh; sz = 0; } \
        } else { \
            src = Wh + (size_t)tap*D_*D_ + (size_t)(bn+row)*D_ + ci0 + cc*8; \
        } \
        CP16(bufu + tile*TILE_B + row*ROWB + cc*16, src, sz); \
    } \
    CP_COMMIT(); } while (0)

    HMMA_LOOP3(KCONV >> 5, ISSUE_C);
#undef ISSUE_C
    epi_f16pair(acc, cbs.p[z], msh, msl, bm, bn, K5D, ccol, wm, wn, lane);
}

// =====================================================================
// LayerNorm + exact GELU: reads z fp32, writes zh/zl fp16 pairs.
// =====================================================================
__global__ __launch_bounds__(256)
void ln_gelu_kernel(const float* __restrict__ z, const float* __restrict__ g,
                    const float* __restrict__ b,
                    __half* __restrict__ zh, __half* __restrict__ zl)
{
    const int row = blockIdx.x;
    const int tid = threadIdx.x;
    const float* p = z + (size_t)row * D_;
    float4 v = ((const float4*)p)[tid];
    float s  = v.x + v.y + v.z + v.w;
    float ss = v.x*v.x + v.y*v.y + v.z*v.z + v.w*v.w;
    #pragma unroll
    for (int o = 16; o; o >>= 1) {
        s  += __shfl_xor_sync(0xffffffffu, s,  o);
        ss += __shfl_xor_sync(0xffffffffu, ss, o);
    }
    __shared__ float ws[8], wss[8];
    __shared__ float mu_s, inv_s;
    int lane = tid & 31, wid = tid >> 5;
    if (lane == 0) { ws[wid] = s; wss[wid] = ss; }
    __syncthreads();
    if (tid == 0) {
        float S = 0.f, SS = 0.f;
        #pragma unroll
        for (int i = 0; i < 8; i++) { S += ws[i]; SS += wss[i]; }
        float mu = S * (1.f / D_);
        float var = SS * (1.f / D_) - mu * mu;
        mu_s = mu;
        inv_s = rsqrtf(var + 1e-5f);
    }
    __syncthreads();
    float mu = mu_s, inv = inv_s;
    float4 gg = ((const float4*)g)[tid];
    float4 bb = ((const float4*)b)[tid];
    float y[4] = { (v.x-mu)*inv*gg.x + bb.x, (v.y-mu)*inv*gg.y + bb.y,
                   (v.z-mu)*inv*gg.z + bb.z, (v.w-mu)*inv*gg.w + bb.w };
    float o[4];
    o[0] = 0.5f*y[0]*(1.f + erff(y[0]*0.70710678118654752f));
    o[1] = 0.5f*y[1]*(1.f + erff(y[1]*0.70710678118654752f));
    o[2] = 0.5f*y[2]*(1.f + erff(y[2]*0.70710678118654752f));
    o[3] = 0.5f*y[3]*(1.f + erff(y[3]*0.70710678118654752f));
    __half h0, h1, h2, h3, l0, l1, l2, l3;
    split_f16(o[0], h0, l0); split_f16(o[1], h1, l1);
    split_f16(o[2], h2, l2); split_f16(o[3], h3, l3);
    __half2* ph = (__half2*)(zh + (size_t)row * D_);
    __half2* pl = (__half2*)(zl + (size_t)row * D_);
    ph[2*tid]   = __half2(h0, h1);
    ph[2*tid+1] = __half2(h2, h3);
    pl[2*tid]   = __half2(l0, l1);
    pl[2*tid+1] = __half2(l2, l3);
}

// =====================================================================
// Attention (fp32 SIMT)
// =====================================================================
__global__ __launch_bounds__(256)
void attn_scores_kernel(const float* __restrict__ q, const float* __restrict__ kmat,
                        float* __restrict__ s)
{
    const int bh = blockIdx.z;
    const int b = bh >> 4, h = bh & 15;
    const int bm = blockIdx.y * 64, bn = blockIdx.x * 64;
    __shared__ __align__(16) float As[16][68];
    __shared__ __align__(16) float Bs[16][68];
    const int tid = threadIdx.x;
    const int lk = tid & 15, lr = tid >> 4;
    const int tx = tid & 15, ty = tid >> 4;
    float acc[4][4] = {};
    for (int k0 = 0; k0 < DH; k0 += 16) {
        #pragma unroll
        for (int p = 0; p < 4; p++) {
            int m = bm + lr + 16*p;
            As[lk][lr+16*p] = q[((size_t)(b*T_ + m))*D_ + h*DH + k0 + lk];
        }
        #pragma unroll
        for (int p = 0; p < 4; p++) {
            int n = bn + lr + 16*p;
            Bs[lk][lr+16*p] = kmat[((size_t)(b*T_ + n))*D_ + h*DH + k0 + lk];
        }
        __syncthreads();
        #pragma unroll
        for (int k = 0; k < 16; k++) {
            float a[4], bb[4];
            *(float4*)a  = *(const float4*)&As[k][ty*4];
            *(float4*)bb = *(const float4*)&Bs[k][tx*4];
            #pragma unroll
            for (int i = 0; i < 4; i++)
                #pragma unroll
                for (int j = 0; j < 4; j++)
                    acc[i][j] += a[i]*bb[j];
        }
        __syncthreads();
    }
    #pragma unroll
    for (int i = 0; i < 4; i++) {
        int m = bm + ty*4 + i;
        #pragma unroll
        for (int j = 0; j < 4; j++) {
            int n = bn + tx*4 + j;
            s[((size_t)bh*T_ + m)*T_ + n] = acc[i][j] * 0.125f;
        }
    }
}

__global__ __launch_bounds__(256)
void softmax_kernel(float* __restrict__ s)
{
    int row  = (blockIdx.x * blockDim.x + threadIdx.x) >> 5;
    int lane = threadIdx.x & 31;
    float* p = s + (size_t)row * T_;
    float v[8];
    float m = -1e30f;
    #pragma unroll
    for (int r = 0; r < 8; r++) { v[r] = p[lane + 32*r]; m = fmaxf(m, v[r]); }
    #pragma unroll
    for (int o = 16; o; o >>= 1) m = fmaxf(m, __shfl_xor_sync(0xffffffffu, m, o));
    float sum = 0.f;
    #pragma unroll
    for (int r = 0; r < 8; r++) { v[r] = __expf(v[r] - m); sum += v[r]; }
    #pragma unroll
    for (int o = 16; o; o >>= 1) sum += __shfl_xor_sync(0xffffffffu, sum, o);
    float inv = 1.f / sum;
    #pragma unroll
    for (int r = 0; r < 8; r++) p[lane + 32*r] = v[r] * inv;
}

// ctx written directly as fp16 hi/lo pairs
__global__ __launch_bounds__(256)
void attn_ctx_kernel(const float* __restrict__ s, const float* __restrict__ v,
                     __half* __restrict__ cxh, __half* __restrict__ cxl)
{
    const int bh = blockIdx.z;
    const int b = bh >> 4, h = bh & 15;
    const int bm = blockIdx.y * 64;
    __shared__ __align__(16) float As[16][68];
    __shared__ __align__(16) float Bs[16][68];
    const int tid = threadIdx.x;
    const int lk = tid & 15, lr = tid >> 4;
    const int bn_ = tid & 63, bkk = tid >> 6;
    const int tx = tid & 15, ty = tid >> 4;
    float acc[4][4] = {};
    for (int k0 = 0; k0 < T_; k0 += 16) {
        #pragma unroll
        for (int p = 0; p < 4; p++) {
            int m = bm + lr + 16*p;
            As[lk][lr+16*p] = s[((size_t)bh*T_ + m)*T_ + k0 + lk];
        }
        #pragma unroll
        for (int p = 0; p < 4; p++) {
            int jj = bkk + 4*p;
            Bs[jj][bn_] = v[((size_t)(b*T_ + k0 + jj))*D_ + h*DH + bn_];
        }
        __syncthreads();
        #pragma unroll
        for (int k = 0; k < 16; k++) {
            float a[4], bb[4];
            *(float4*)a  = *(const float4*)&As[k][ty*4];
            *(float4*)bb = *(const float4*)&Bs[k][tx*4];
            #pragma unroll
            for (int i = 0; i < 4; i++)
                #pragma unroll
                for (int j = 0; j < 4; j++)
                    acc[i][j] += a[i]*bb[j];
        }
        __syncthreads();
    }
    #pragma unroll
    for (int i = 0; i < 4; i++) {
        int m = bm + ty*4 + i;
        size_t o = ((size_t)(b*T_ + m))*D_ + h*DH + tx*4;
        __half h0, h1, h2, h3, l0, l1, l2, l3;
        split_f16(acc[i][0], h0, l0); split_f16(acc[i][1], h1, l1);
        split_f16(acc[i][2], h2, l2); split_f16(acc[i][3], h3, l3);
        *(__half2*)&cxh[o]   = __half2(h0, h1);
        *(__half2*)&cxh[o+2] = __half2(h2, h3);
        *(__half2*)&cxl[o]   = __half2(l0, l1);
        *(__half2*)&cxl[o+2] = __half2(l2, l3);
    }
}

// =====================================================================
// GAT pieces
// =====================================================================
__global__ __launch_bounds__(256)
void e12_kernel(const float* __restrict__ hg, const float* __restrict__ a1,
                const float* __restrict__ a2, float* __restrict__ e1,
                float* __restrict__ e2)
{
    int wid  = (blockIdx.x * blockDim.x + threadIdx.x) >> 5;
    int lane = threadIdx.x & 31;
    int n = wid >> 3, h = wid & 7;
    const float* row = hg + (size_t)n * D_ + h * GDH;
    float s1 = 0.f, s2 = 0.f;
    #pragma unroll
    for (int r = 0; r < 4; r++) {
        float x = row[lane + 32*r];
        s1 += x * a1[lane + 32*r];
        s2 += x * a2[lane + 32*r];
    }
    #pragma unroll
    for (int o = 16; o; o >>= 1) {
        s1 += __shfl_xor_sync(0xffffffffu, s1, o);
        s2 += __shfl_xor_sync(0xffffffffu, s2, o);
    }
    if (lane == 0) { e1[n*HGAT + h] = s1; e2[n*HGAT + h] = s2; }
}

__global__ __launch_bounds__(256)
void e2max_kernel(const float* __restrict__ e2, float* __restrict__ m2)
{
    int h = blockIdx.x, tid = threadIdx.x;
    float m = -1e30f;
    for (int n = tid; n < M_; n += 256) m = fmaxf(m, e2[n*HGAT + h]);
    __shared__ float sm[256];
    sm[tid] = m; __syncthreads();
    for (int s = 128; s > 0; s >>= 1) {
        if (tid < s) sm[tid] = fmaxf(sm[tid], sm[tid + s]);
        __syncthreads();
    }
    if (tid == 0) m2[h] = sm[0];
}

// GAT aggregation: fp16 HMMA with on-the-fly alpha + fused denom/ELU/residual.
// grid (8 heads, 16 m-tiles); 128x128 out per block.
__global__ __launch_bounds__(256)
void gat_hmma_kernel(const __half* __restrict__ hgT, const float* __restrict__ e1,
                     const float* __restrict__ e2, const float* __restrict__ m2,
                     const float* __restrict__ feat, float* __restrict__ out)
{
    __shared__ __align__(16) char sA[TILE_B];
    __shared__ __align__(16) char sB[3][TILE_B];
    __shared__ float s_e1[128], s_mr[128], dpart[256];
    const int h  = blockIdx.x;
    const int bm = blockIdx.y * 128;
    const int tid = threadIdx.x;
    const int wid = tid >> 5, lane = tid & 31;
    const int wm = wid & 1, wn = wid >> 1;
    const uint32_t aU = smem_u32(sA);
    if (tid < 128) {
        float v1 = e1[(bm + tid)*HGAT + h];
        float sv = v1 + m2[h];
        s_mr[tid] = sv > 0.f ? sv : 0.2f * sv;
        s_e1[tid] = v1;
    }
    __syncthreads();
    const int am  = tid >> 1;             // As row owned by this thread
    const int ak0 = (tid & 1) * 16;
    const float e1v = s_e1[am], mrv = s_mr[am];
    float dreg = 0.f;
    float acc[4][4][4] = {};

#define ISSUE_B(c) do { \
    int k0 = (c) << 5; \
    uint32_t bufu = smem_u32(sB[(c) % 3]); \
    _Pragma("unroll") \
    for (int it = 0; it < 2; it++) { \
        int g = tid + it*256; \
        int row = g >> 2, cc = g & 3; \
        const __half* src = hgT + (size_t)(h*GDH + row)*M_ + k0 + cc*8; \
        CP16(bufu + row*ROWB + cc*16, src, 16); \
    } \
    CP_COMMIT(); } while (0)

    const int nc = M_ >> 5;               // 64
    ISSUE_B(0);
    ISSUE_B(1);
    for (int c = 0; c < nc; c++) {
        int k0 = c << 5;
        // compute alpha tile (fp16) + accumulate denominator
        #pragma unroll
        for (int r = 0; r < 16; r++) {
            int j = k0 + ak0 + r;
            float ev = __ldg(&e2[j*HGAT + h]);
            float sv = e1v + ev;
            float lv = sv > 0.f ? sv : 0.2f * sv;
            __half a16 = __float2half_rn(__expf(lv - mrv));
            dreg += __half2float(a16);
            *(__half*)(sA + am*ROWB + (ak0 + r)*2) = a16;
        }
        if (c + 1 < nc) CP_WAIT1(); else CP_WAIT0();
        __syncthreads();
        if (c + 2 < nc) ISSUE_B(c + 2);
        uint32_t bU = smem_u32(sB[c % 3]);
        #pragma unroll
        for (int kk = 0; kk < 32; kk += 16) {
            uint32_t bh[4][2];
            #pragma unroll
            for (int j = 0; j < 4; j++) {
                int nrow = wn*32 + j*8 + (lane & 7);
                int colb = (kk + ((lane >> 3) & 1)*8) * 2;
                LDMX2(bh[j], bU + nrow*ROWB + colb);
            }
            #pragma unroll
            for (int i = 0; i < 4; i++) {
                int mrow = wm*64 + i*16 + (lane & 15);
                int colb = (kk + ((lane >> 4) & 1)*8) * 2;
                uint32_t ah[4];
                LDMX4(ah, aU + mrow*ROWB + colb);
                #pragma unroll
                for (int j = 0; j < 4; j++)
                    MMA16816F(acc[i][j], ah, bh[j]);
            }
        }
        __syncthreads();
    }
#undef ISSUE_B
    dpart[tid] = dreg;
    __syncthreads();
    #pragma unroll
    for (int i = 0; i < 4; i++) {
        int ml = wm*64 + i*16 + (lane >> 2);
        int m0 = bm + ml;
        float inv0 = 1.f / (dpart[2*ml] + dpart[2*ml+1]);
        float inv1 = 1.f / (dpart[2*(ml+8)] + dpart[2*(ml+8)+1]);
        #pragma unroll
        for (int j = 0; j < 4; j++) {
            int n0 = wn*32 + j*8 + (lane & 3)*2;
            int col = h*GDH + n0;
            float v0 = acc[i][j][0]*inv0, v1 = acc[i][j][1]*inv0;
            float v2 = acc[i][j][2]*inv1, v3 = acc[i][j][3]*inv1;
            v0 = v0 > 0.f ? v0 : expm1f(v0);
            v1 = v1 > 0.f ? v1 : expm1f(v1);
            v2 = v2 > 0.f ? v2 : expm1f(v2);
            v3 = v3 > 0.f ? v3 : expm1f(v3);
            size_t o01 = (size_t)m0*D_ + col;
            size_t o23 = (size_t)(m0+8)*D_ + col;
            out[o01]   = v0 + feat[o01];
            out[o01+1] = v1 + feat[o01+1];
            out[o23]   = v2 + feat[o23];
            out[o23+1] = v3 + feat[o23+1];
        }
    }
}

// =====================================================================
extern "C" void kernel_launch(void* const* d_in, const int* in_sizes, int n_in,
                              void* d_out, int out_size)
{
    const float* feat = (const float*)d_in[0];

    Ptr5 cw{}, cb{};
    int wi = 0, bi = 0;
    for (int i = 1; i <= 10; i++) {
        if (in_sizes[i] == D_ * D_ * KW) { if (wi < 5) cw.p[wi++] = (const float*)d_in[i]; }
        else                             { if (bi < 5) cb.p[bi++] = (const float*)d_in[i]; }
    }

    const float* fp_w = (const float*)d_in[11];
    const float* fp_b = (const float*)d_in[12];
    const float* ln_g = (const float*)d_in[13];
    const float* ln_b = (const float*)d_in[14];
    const float* wq = (const float*)d_in[15];
    const float* bq = (const float*)d_in[16];
    const float* wk = (const float*)d_in[17];
    const float* bk = (const float*)d_in[18];
    const float* wv = (const float*)d_in[19];
    const float* bv = (const float*)d_in[20];
    const float* wo = (const float*)d_in[21];
    const float* bo = (const float*)d_in[22];
    const float* gat_w = (const float*)d_in[23];
    const float* gat_b = (const float*)d_in[24];
    const float* a1 = (const float*)d_in[25];
    const float* a2 = (const float*)d_in[26];
    float* out = (float*)d_out;

    __half *f16h, *f16l, *wt16, *fp16, *dw16;
    __half *msh, *msl, *zh, *zl, *cxh, *cxl, *ath, *atl, *hgT;
    float *z, *q, *k, *v, *s, *hg, *e1, *e2, *m2;
    cudaGetSymbolAddress((void**)&f16h, g_f16h);
    cudaGetSymbolAddress((void**)&f16l, g_f16l);
    cudaGetSymbolAddress((void**)&wt16, g_wt16);
    cudaGetSymbolAddress((void**)&fp16, g_fp16);
    cudaGetSymbolAddress((void**)&dw16, g_dw16);
    cudaGetSymbolAddress((void**)&msh, g_msh);
    cudaGetSymbolAddress((void**)&msl, g_msl);
    cudaGetSymbolAddress((void**)&z,   g_z);
    cudaGetSymbolAddress((void**)&zh,  g_zh);
    cudaGetSymbolAddress((void**)&zl,  g_zl);
    cudaGetSymbolAddress((void**)&q,   g_q);
    cudaGetSymbolAddress((void**)&k,   g_k);
    cudaGetSymbolAddress((void**)&v,   g_v);
    cudaGetSymbolAddress((void**)&s,   g_s);
    cudaGetSymbolAddress((void**)&cxh, g_cxh);
    cudaGetSymbolAddress((void**)&cxl, g_cxl);
    cudaGetSymbolAddress((void**)&ath, g_ath);
    cudaGetSymbolAddress((void**)&atl, g_atl);
    cudaGetSymbolAddress((void**)&hg,  g_hg);
    cudaGetSymbolAddress((void**)&hgT, g_hgT);
    cudaGetSymbolAddress((void**)&e1,  g_e1);
    cudaGetSymbolAddress((void**)&e2,  g_e2);
    cudaGetSymbolAddress((void**)&m2,  g_m2);

    cudaFuncSetAttribute(hmma_d16_f32,    cudaFuncAttributeMaxDynamicSharedMemorySize, SMEM_3S);
    cudaFuncSetAttribute(hmma_d16_pair,   cudaFuncAttributeMaxDynamicSharedMemorySize, SMEM_3S);
    cudaFuncSetAttribute(hmma_d16_qkv,    cudaFuncAttributeMaxDynamicSharedMemorySize, SMEM_3S);
    cudaFuncSetAttribute(hmma_conv_kernel, cudaFuncAttributeMaxDynamicSharedMemorySize, SMEM_3S);

    const size_t WTN = (size_t)KW * D_ * D_;

    // 0) conversions
    cvt_pair_f16_kernel<<<(M_*D_/4 + 255)/256, 256>>>(feat, f16h, f16l, M_*D_/4);
    wtrans5_kernel<<<dim3((int)(WTN/256), 5), 256>>>(cw, wt16);
    cvt_f16_kernel<<<(D_*K5D/4 + 255)/256, 256>>>(fp_w, fp16, D_*K5D/4);
    Ptr5 dws{{ wq, wk, wv, wo, gat_w }};
    cvt5_f16_kernel<<<dim3(D_*D_/4/256, 5), 256>>>(dws, dw16);

    // 1) dilated convs (fp16 2-term) -> msh/msl fp16 pairs
    hmma_conv_kernel<<<dim3(8, 16, 5), 256, SMEM_3S>>>(f16h, f16l, wt16, cb, msh, msl);

    // 2) fusion projection (K=5120) -> z fp32, then LN+GELU -> zh/zl fp16
    hmma_d16_f32<<<dim3(8, 16), 256, SMEM_3S>>>(msh, msl, fp16, fp_b, z, K5D, D_);
    ln_gelu_kernel<<<M_, 256>>>(z, ln_g, ln_b, zh, zl);

    // 3) q, k, v projections (merged)
    QkvArgs qkv{{ q, k, v }, { bq, bk, bv }};
    hmma_d16_qkv<<<dim3(8, 16, 3), 256, SMEM_3S>>>(zh, zl, dw16, qkv);

    // 4) attention (fp32) -> cxh/cxl fp16 pairs
    attn_scores_kernel<<<dim3(4, 4, B_*HMHA), 256>>>(q, k, s);
    softmax_kernel<<<(B_*HMHA*T_)/8, 256>>>(s);
    attn_ctx_kernel<<<dim3(1, 4, B_*HMHA), 256>>>(s, v, cxh, cxl);

    // 5) wo -> ath/atl fp16 pairs; gat_w -> hg fp32
    hmma_d16_pair<<<dim3(8, 16), 256, SMEM_3S>>>(cxh, cxl,
        dw16 + 3*(size_t)D_*D_, bo, ath, atl, D_, D_);
    hmma_d16_f32<<<dim3(8, 16), 256, SMEM_3S>>>(ath, atl,
        dw16 + 4*(size_t)D_*D_, gat_b, hg, D_, D_);

    // 6) GAT logits, max, transpose
    e12_kernel<<<(M_*HGAT)/8, 256>>>(hg, a1, a2, e1, e2);
    e2max_kernel<<<HGAT, 256>>>(e2, m2);
    transpose_f16_kernel<<<dim3(M_/32, D_/32), 256>>>(hg, hgT);

    // 7) GAT aggregation (fp16 HMMA) + ELU + residual -> d_out
    gat_hmma_kernel<<<dim3(HGAT, 16), 256>>>(hgT, e1, e2, m2, feat, out);
}

// round 10
// speedup vs baseline: 5.6928x; 1.3094x over previous
#include <cuda_runtime.h>
#include <cuda_bf16.h>
#include <cuda_fp16.h>
#include <math.h>
#include <stdint.h>

#define D_   1024
#define T_   256
#define B_   8
#define M_   (B_*T_)        // 2048 rows (b,t)
#define HMHA 16
#define DH   64
#define HGAT 8
#define GDH  128
#define KW   7
#define K5D  (5*D_)
#define KCONV (KW*D_)       // 7168

#define ROWB   80                    // bytes per smem row (32 fp16 + pad)
#define TILE_B (128*ROWB)            // 10240 B per tile
#define SMEM_3S  (3*3*TILE_B)        // dense: 3 stages x 3 tiles = 92160
#define SMEM_CV  (3*2*TILE_B)        // conv:  3 stages x 2 tiles = 61440

// ===================== PTX helpers (baseline ISA only) =====================
__device__ __forceinline__ uint32_t smem_u32(const void* p) {
    uint32_t a;
    asm("{ .reg .u64 t; cvta.to.shared.u64 t, %1; cvt.u32.u64 %0, t; }"
        : "=r"(a) : "l"(p));
    return a;
}
#define CP16(dst, src, sz) \
    asm volatile("cp.async.cg.shared.global [%0], [%1], 16, %2;" \
                 :: "r"(dst), "l"(src), "r"(sz))
#define CP_COMMIT() asm volatile("cp.async.commit_group;" ::: "memory")
#define CP_WAIT1()  asm volatile("cp.async.wait_group 1;" ::: "memory")
#define CP_WAIT0()  asm volatile("cp.async.wait_group 0;" ::: "memory")

#define LDMX4(r, addr) \
    asm volatile("ldmatrix.sync.aligned.m8n8.x4.shared.b16 {%0,%1,%2,%3}, [%4];" \
        : "=r"((r)[0]), "=r"((r)[1]), "=r"((r)[2]), "=r"((r)[3]) : "r"(addr))
#define LDMX2(r, addr) \
    asm volatile("ldmatrix.sync.aligned.m8n8.x2.shared.b16 {%0,%1}, [%2];" \
        : "=r"((r)[0]), "=r"((r)[1]) : "r"(addr))

#define MMA16816F(c, a, b) \
    asm volatile("mma.sync.aligned.m16n8k16.row.col.f32.f16.f16.f32 " \
        "{%0,%1,%2,%3}, {%4,%5,%6,%7}, {%8,%9}, {%0,%1,%2,%3};" \
        : "+f"((c)[0]), "+f"((c)[1]), "+f"((c)[2]), "+f"((c)[3]) \
        : "r"((a)[0]), "r"((a)[1]), "r"((a)[2]), "r"((a)[3]), \
          "r"((b)[0]), "r"((b)[1]))

struct Ptr5  { const float* p[5]; };
struct QkvArgs { float* o[3]; const float* b[3]; };

// ---------------- scratch (device globals; no allocation) ----------------
__device__ __half g_f16h[M_ * D_];                 // feat fp16
__device__ __half g_wt16[5 * KW * D_ * D_];        // conv weights fp16 [c][tap][o][ci]
__device__ __half g_fp16[D_ * K5D];                // fusion weight fp16
__device__ __half g_dw16[5 * D_ * D_];             // wq,wk,wv,wo,gat_w fp16
__device__ __half g_msh[M_ * K5D];                 // conv out fp16 pair
__device__ __half g_msl[M_ * K5D];
__device__ float  g_z  [M_ * D_];
__device__ __half g_zh [M_ * D_];
__device__ __half g_zl [M_ * D_];
__device__ float  g_q  [M_ * D_];
__device__ float  g_k  [M_ * D_];
__device__ float  g_v  [M_ * D_];
__device__ float  g_s  [B_*HMHA * T_ * T_];
__device__ __half g_cxh[M_ * D_];
__device__ __half g_cxl[M_ * D_];
__device__ __half g_ath[M_ * D_];
__device__ __half g_atl[M_ * D_];
__device__ float  g_hg [M_ * D_];
__device__ __half g_hgT[D_ * M_];                  // transpose of hg, fp16
__device__ float  g_e1[M_ * HGAT];
__device__ float  g_e2[M_ * HGAT];
__device__ float  g_m2[HGAT];

// =====================================================================
// split helpers / conversion kernels
// =====================================================================
__device__ __forceinline__ void split_f16(float v, __half& h, __half& l) {
    h = __float2half_rn(v);
    l = __float2half_rn(v - __half2float(h));
}

__global__ __launch_bounds__(256)
void cvt_f16_kernel(const float* __restrict__ src, __half* __restrict__ hi, int n4)
{
    int i = blockIdx.x * 256 + threadIdx.x;
    if (i >= n4) return;
    float4 v = ((const float4*)src)[i];
    __half2* ph = (__half2*)hi;
    ph[2*i]   = __half2(__float2half_rn(v.x), __float2half_rn(v.y));
    ph[2*i+1] = __half2(__float2half_rn(v.z), __float2half_rn(v.w));
}

// merged dense-weight convert (5 x D*D), fp16 only
__global__ __launch_bounds__(256)
void cvt5_f16_kernel(Ptr5 ws, __half* __restrict__ hi)
{
    int c = blockIdx.y;
    int i = blockIdx.x * 256 + threadIdx.x;           // over D*D/4
    float4 v = ((const float4*)ws.p[c])[i];
    __half2* ph = (__half2*)(hi + (size_t)c * D_ * D_);
    ph[2*i]   = __half2(__float2half_rn(v.x), __float2half_rn(v.y));
    ph[2*i+1] = __half2(__float2half_rn(v.z), __float2half_rn(v.w));
}

// merged conv weight transform: fp16, [c][tap][o][ci]
__global__ __launch_bounds__(256)
void wtrans5_kernel(Ptr5 cw, __half* __restrict__ wh)
{
    int c = blockIdx.y;
    int idx = blockIdx.x * 256 + threadIdx.x;      // over 7*1024*1024
    int tap = idx >> 20;
    int rem = idx & ((1 << 20) - 1);
    int o  = rem >> 10;
    int ci = rem & 1023;
    float x = __ldg(&cw.p[c][(size_t)o * KCONV + ci * 7 + tap]);
    wh[(size_t)c * (KW*D_*D_) + idx] = __float2half_rn(x);
}

// hg fp32 (2048 x 1024) -> hgT fp16 (1024 x 2048)
__global__ __launch_bounds__(256)
void transpose_f16_kernel(const float* __restrict__ hg, __half* __restrict__ hgT)
{
    __shared__ float tile[32][33];
    int j0 = blockIdx.x * 32, c0 = blockIdx.y * 32;
    int tx = threadIdx.x & 31, ty = threadIdx.x >> 5;   // 32 x 8
    #pragma unroll
    for (int r = ty; r < 32; r += 8)
        tile[r][tx] = hg[(size_t)(j0 + r) * D_ + c0 + tx];
    __syncthreads();
    #pragma unroll
    for (int r = ty; r < 32; r += 8)
        hgT[(size_t)(c0 + r) * M_ + j0 + tx] = __float2half_rn(tile[tx][r]);
}

// =====================================================================
// fp16 2-term HMMA chunk (dense): tiles 0=Ah, 1=Al, 2=Bh
// =====================================================================
__device__ __forceinline__
void hmma_chunk_f16(uint32_t bufu, int wm, int wn, int lane, float acc[4][4][4])
{
    #pragma unroll
    for (int kk = 0; kk < 32; kk += 16) {
        uint32_t bh[4][2];
        #pragma unroll
        for (int j = 0; j < 4; j++) {
            int nrow = wn*32 + j*8 + (lane & 7);
            int colb = (kk + ((lane >> 3) & 1)*8) * 2;
            LDMX2(bh[j], bufu + 2*TILE_B + nrow*ROWB + colb);
        }
        #pragma unroll
        for (int i = 0; i < 4; i++) {
            int mrow = wm*64 + i*16 + (lane & 15);
            int colb = (kk + ((lane >> 4) & 1)*8) * 2;
            uint32_t ah[4], al[4];
            LDMX4(ah, bufu + 0*TILE_B + mrow*ROWB + colb);
            LDMX4(al, bufu + 1*TILE_B + mrow*ROWB + colb);
            #pragma unroll
            for (int j = 0; j < 4; j++) {
                MMA16816F(acc[i][j], ah, bh[j]);
                MMA16816F(acc[i][j], al, bh[j]);
            }
        }
    }
}

// fp16 1-term chunk (conv): tiles 0=Ah, 1=Bh
__device__ __forceinline__
void hmma_chunk_1t(uint32_t bufu, int wm, int wn, int lane, float acc[4][4][4])
{
    #pragma unroll
    for (int kk = 0; kk < 32; kk += 16) {
        uint32_t bh[4][2];
        #pragma unroll
        for (int j = 0; j < 4; j++) {
            int nrow = wn*32 + j*8 + (lane & 7);
            int colb = (kk + ((lane >> 3) & 1)*8) * 2;
            LDMX2(bh[j], bufu + 1*TILE_B + nrow*ROWB + colb);
        }
        #pragma unroll
        for (int i = 0; i < 4; i++) {
            int mrow = wm*64 + i*16 + (lane & 15);
            int colb = (kk + ((lane >> 4) & 1)*8) * 2;
            uint32_t ah[4];
            LDMX4(ah, bufu + 0*TILE_B + mrow*ROWB + colb);
            #pragma unroll
            for (int j = 0; j < 4; j++)
                MMA16816F(acc[i][j], ah, bh[j]);
        }
    }
}

__device__ __forceinline__
void issue_d16(uint32_t smem_base, int c, int tid,
               const __half* __restrict__ Ah, const __half* __restrict__ Al,
               const __half* __restrict__ Wh, int bm, int bn, int K)
{
    int k0 = c << 5;
    uint32_t bufu = smem_base + (c % 3) * 3*TILE_B;
    #pragma unroll
    for (int it = 0; it < 6; it++) {
        int g = tid + it*256;
        int tile = g >> 9;
        int ct = g & 511, row = ct >> 2, cc = ct & 3;
        const __half* src;
        if      (tile == 0) src = Ah + (size_t)(bm+row)*K + k0 + cc*8;
        else if (tile == 1) src = Al + (size_t)(bm+row)*K + k0 + cc*8;
        else                src = Wh + (size_t)(bn+row)*K + k0 + cc*8;
        CP16(bufu + tile*TILE_B + row*ROWB + cc*16, src, 16);
    }
    CP_COMMIT();
}

__device__ __forceinline__
void epi_f32(float acc[4][4][4], const float* __restrict__ bias,
             float* __restrict__ C, int bm, int bn, int ldc,
             int wm, int wn, int lane)
{
    #pragma unroll
    for (int i = 0; i < 4; i++) {
        int m0 = bm + wm*64 + i*16 + (lane >> 2);
        #pragma unroll
        for (int j = 0; j < 4; j++) {
            int n0 = wn*32 + j*8 + (lane & 3)*2;
            float b0 = bias[bn + n0], b1 = bias[bn + n0 + 1];
            *(float2*)&C[(size_t)m0*ldc + bn + n0] =
                make_float2(acc[i][j][0] + b0, acc[i][j][1] + b1);
            *(float2*)&C[(size_t)(m0+8)*ldc + bn + n0] =
                make_float2(acc[i][j][2] + b0, acc[i][j][3] + b1);
        }
    }
}

__device__ __forceinline__
void epi_f16pair(float acc[4][4][4], const float* __restrict__ bias,
                 __half* __restrict__ Ch, __half* __restrict__ Cl,
                 int bm, int bn, int ldc, int colbase, int wm, int wn, int lane)
{
    #pragma unroll
    for (int i = 0; i < 4; i++) {
        int m0 = bm + wm*64 + i*16 + (lane >> 2);
        #pragma unroll
        for (int j = 0; j < 4; j++) {
            int n0 = wn*32 + j*8 + (lane & 3)*2;
            float b0 = bias[bn + n0], b1 = bias[bn + n0 + 1];
            float v0 = acc[i][j][0] + b0, v1 = acc[i][j][1] + b1;
            float v2 = acc[i][j][2] + b0, v3 = acc[i][j][3] + b1;
            __half h0, h1, h2, h3, l0, l1, l2, l3;
            split_f16(v0, h0, l0); split_f16(v1, h1, l1);
            split_f16(v2, h2, l2); split_f16(v3, h3, l3);
            size_t o01 = (size_t)m0*ldc + colbase + bn + n0;
            size_t o23 = (size_t)(m0+8)*ldc + colbase + bn + n0;
            *(__half2*)&Ch[o01] = __half2(h0, h1);
            *(__half2*)&Cl[o01] = __half2(l0, l1);
            *(__half2*)&Ch[o23] = __half2(h2, h3);
            *(__half2*)&Cl[o23] = __half2(l2, l3);
        }
    }
}

#define HMMA_PROLOG() \
    extern __shared__ __align__(16) char smem_raw[]; \
    const uint32_t smem_base = smem_u32(smem_raw); \
    const int bm = blockIdx.y * 128, bn = blockIdx.x * 128; \
    const int tid = threadIdx.x; \
    const int wid = tid >> 5, lane = tid & 31; \
    const int wm = wid & 1, wn = wid >> 1; \
    float acc[4][4][4] = {};

#define HMMA_LOOP3(NC, ISSUE, CHUNK, STRIDE) \
    ISSUE(0); \
    ISSUE(1); \
    for (int c = 0; c < (NC); c++) { \
        if (c + 1 < (NC)) CP_WAIT1(); else CP_WAIT0(); \
        __syncthreads(); \
        if (c + 2 < (NC)) ISSUE(c + 2); \
        CHUNK(smem_base + (c % 3)*(STRIDE), wm, wn, lane, acc); \
        __syncthreads(); \
    }

// ---- dense GEMM fp16 2-term, fp32 out ----
__global__ __launch_bounds__(256, 2)
void hmma_d16_f32(const __half* __restrict__ Ah, const __half* __restrict__ Al,
                  const __half* __restrict__ Wh, const float* __restrict__ bias,
                  float* __restrict__ C, int K, int ldc)
{
    HMMA_PROLOG();
#define ISS(c) issue_d16(smem_base, c, tid, Ah, Al, Wh, bm, bn, K)
    HMMA_LOOP3(K >> 5, ISS, hmma_chunk_f16, 3*TILE_B);
#undef ISS
    epi_f32(acc, bias, C, bm, bn, ldc, wm, wn, lane);
}

// ---- dense GEMM fp16 2-term, fp16-pair out ----
__global__ __launch_bounds__(256, 2)
void hmma_d16_pair(const __half* __restrict__ Ah, const __half* __restrict__ Al,
                   const __half* __restrict__ Wh, const float* __restrict__ bias,
                   __half* __restrict__ Ch, __half* __restrict__ Cl, int K, int ldc)
{
    HMMA_PROLOG();
#define ISS(c) issue_d16(smem_base, c, tid, Ah, Al, Wh, bm, bn, K)
    HMMA_LOOP3(K >> 5, ISS, hmma_chunk_f16, 3*TILE_B);
#undef ISS
    epi_f16pair(acc, bias, Ch, Cl, bm, bn, ldc, 0, wm, wn, lane);
}

// ---- QKV: grid.z selects weight/bias/output ----
__global__ __launch_bounds__(256, 2)
void hmma_d16_qkv(const __half* __restrict__ Ah, const __half* __restrict__ Al,
                  const __half* __restrict__ dw16, QkvArgs args)
{
    const int z = blockIdx.z;
    const __half* Wh = dw16 + (size_t)z * D_ * D_;
    HMMA_PROLOG();
#define ISS(c) issue_d16(smem_base, c, tid, Ah, Al, Wh, bm, bn, D_)
    HMMA_LOOP3(D_ >> 5, ISS, hmma_chunk_f16, 3*TILE_B);
#undef ISS
    epi_f32(acc, args.b[z], args.o[z], bm, bn, D_, wm, wn, lane);
}

// ---- convs: fp16 1-term gather, grid.z = conv id ----
__global__ __launch_bounds__(256, 2)
void hmma_conv_kernel(const __half* __restrict__ Fh,
                      const __half* __restrict__ wt16, Ptr5 cbs,
                      __half* __restrict__ msh, __half* __restrict__ msl)
{
    const int z = blockIdx.z;
    const int dil = 1 << z;
    const int ccol = z * D_;
    const __half* Wh = wt16 + (size_t)z * (KW*D_*D_);
    HMMA_PROLOG();

#define ISSUE_C(c) do { \
    int k0 = (c) << 5; \
    int tap = k0 >> 10, ci0 = k0 & 1023; \
    int offt = (tap - 3) * dil; \
    uint32_t bufu = smem_base + ((c) % 3) * 2*TILE_B; \
    _Pragma("unroll") \
    for (int it = 0; it < 4; it++) { \
        int g = tid + it*256; \
        int tile = g >> 9; \
        int ct = g & 511; int row = ct >> 2, cc = ct & 3; \
        const __half* src; \
        uint32_t sz = 16; \
        if (tile == 0) { \
            int m = bm + row; \
            int bb = m >> 8, tt = (m & 255) + offt; \
            if (tt >= 0 && tt < T_) \
                src = Fh + ((size_t)(bb*T_ + tt))*D_ + ci0 + cc*8; \
            else { src = Fh; sz = 0; } \
        } else { \
            src = Wh + (size_t)tap*D_*D_ + (size_t)(bn+row)*D_ + ci0 + cc*8; \
        } \
        CP16(bufu + tile*TILE_B + row*ROWB + cc*16, src, sz); \
    } \
    CP_COMMIT(); } while (0)

    HMMA_LOOP3(KCONV >> 5, ISSUE_C, hmma_chunk_1t, 2*TILE_B);
#undef ISSUE_C
    epi_f16pair(acc, cbs.p[z], msh, msl, bm, bn, K5D, ccol, wm, wn, lane);
}

// =====================================================================
// LayerNorm + exact GELU: reads z fp32, writes zh/zl fp16 pairs.
// =====================================================================
__global__ __launch_bounds__(256)
void ln_gelu_kernel(const float* __restrict__ z, const float* __restrict__ g,
                    const float* __restrict__ b,
                    __half* __restrict__ zh, __half* __restrict__ zl)
{
    const int row = blockIdx.x;
    const int tid = threadIdx.x;
    const float* p = z + (size_t)row * D_;
    float4 v = ((const float4*)p)[tid];
    float s  = v.x + v.y + v.z + v.w;
    float ss = v.x*v.x + v.y*v.y + v.z*v.z + v.w*v.w;
    #pragma unroll
    for (int o = 16; o; o >>= 1) {
        s  += __shfl_xor_sync(0xffffffffu, s,  o);
        ss += __shfl_xor_sync(0xffffffffu, ss, o);
    }
    __shared__ float ws[8], wss[8];
    __shared__ float mu_s, inv_s;
    int lane = tid & 31, wid = tid >> 5;
    if (lane == 0) { ws[wid] = s; wss[wid] = ss; }
    __syncthreads();
    if (tid == 0) {
        float S = 0.f, SS = 0.f;
        #pragma unroll
        for (int i = 0; i < 8; i++) { S += ws[i]; SS += wss[i]; }
        float mu = S * (1.f / D_);
        float var = SS * (1.f / D_) - mu * mu;
        mu_s = mu;
        inv_s = rsqrtf(var + 1e-5f);
    }
    __syncthreads();
    float mu = mu_s, inv = inv_s;
    float4 gg = ((const float4*)g)[tid];
    float4 bb = ((const float4*)b)[tid];
    float y[4] = { (v.x-mu)*inv*gg.x + bb.x, (v.y-mu)*inv*gg.y + bb.y,
                   (v.z-mu)*inv*gg.z + bb.z, (v.w-mu)*inv*gg.w + bb.w };
    float o[4];
    o[0] = 0.5f*y[0]*(1.f + erff(y[0]*0.70710678118654752f));
    o[1] = 0.5f*y[1]*(1.f + erff(y[1]*0.70710678118654752f));
    o[2] = 0.5f*y[2]*(1.f + erff(y[2]*0.70710678118654752f));
    o[3] = 0.5f*y[3]*(1.f + erff(y[3]*0.70710678118654752f));
    __half h0, h1, h2, h3, l0, l1, l2, l3;
    split_f16(o[0], h0, l0); split_f16(o[1], h1, l1);
    split_f16(o[2], h2, l2); split_f16(o[3], h3, l3);
    __half2* ph = (__half2*)(zh + (size_t)row * D_);
    __half2* pl = (__half2*)(zl + (size_t)row * D_);
    ph[2*tid]   = __half2(h0, h1);
    ph[2*tid+1] = __half2(h2, h3);
    pl[2*tid]   = __half2(l0, l1);
    pl[2*tid+1] = __half2(l2, l3);
}

// =====================================================================
// Attention (fp32 SIMT)
// =====================================================================
__global__ __launch_bounds__(256)
void attn_scores_kernel(const float* __restrict__ q, const float* __restrict__ kmat,
                        float* __restrict__ s)
{
    const int bh = blockIdx.z;
    const int b = bh >> 4, h = bh & 15;
    const int bm = blockIdx.y * 64, bn = blockIdx.x * 64;
    __shared__ __align__(16) float As[16][68];
    __shared__ __align__(16) float Bs[16][68];
    const int tid = threadIdx.x;
    const int lk = tid & 15, lr = tid >> 4;
    const int tx = tid & 15, ty = tid >> 4;
    float acc[4][4] = {};
    for (int k0 = 0; k0 < DH; k0 += 16) {
        #pragma unroll
        for (int p = 0; p < 4; p++) {
            int m = bm + lr + 16*p;
            As[lk][lr+16*p] = q[((size_t)(b*T_ + m))*D_ + h*DH + k0 + lk];
        }
        #pragma unroll
        for (int p = 0; p < 4; p++) {
            int n = bn + lr + 16*p;
            Bs[lk][lr+16*p] = kmat[((size_t)(b*T_ + n))*D_ + h*DH + k0 + lk];
        }
        __syncthreads();
        #pragma unroll
        for (int k = 0; k < 16; k++) {
            float a[4], bb[4];
            *(float4*)a  = *(const float4*)&As[k][ty*4];
            *(float4*)bb = *(const float4*)&Bs[k][tx*4];
            #pragma unroll
            for (int i = 0; i < 4; i++)
                #pragma unroll
                for (int j = 0; j < 4; j++)
                    acc[i][j] += a[i]*bb[j];
        }
        __syncthreads();
    }
    #pragma unroll
    for (int i = 0; i < 4; i++) {
        int m = bm + ty*4 + i;
        #pragma unroll
        for (int j = 0; j < 4; j++) {
            int n = bn + tx*4 + j;
            s[((size_t)bh*T_ + m)*T_ + n] = acc[i][j] * 0.125f;
        }
    }
}

__global__ __launch_bounds__(256)
void softmax_kernel(float* __restrict__ s)
{
    int row  = (blockIdx.x * blockDim.x + threadIdx.x) >> 5;
    int lane = threadIdx.x & 31;
    float* p = s + (size_t)row * T_;
    float v[8];
    float m = -1e30f;
    #pragma unroll
    for (int r = 0; r < 8; r++) { v[r] = p[lane + 32*r]; m = fmaxf(m, v[r]); }
    #pragma unroll
    for (int o = 16; o; o >>= 1) m = fmaxf(m, __shfl_xor_sync(0xffffffffu, m, o));
    float sum = 0.f;
    #pragma unroll
    for (int r = 0; r < 8; r++) { v[r] = __expf(v[r] - m); sum += v[r]; }
    #pragma unroll
    for (int o = 16; o; o >>= 1) sum += __shfl_xor_sync(0xffffffffu, sum, o);
    float inv = 1.f / sum;
    #pragma unroll
    for (int r = 0; r < 8; r++) p[lane + 32*r] = v[r] * inv;
}

// ctx written directly as fp16 hi/lo pairs
__global__ __launch_bounds__(256)
void attn_ctx_kernel(const float* __restrict__ s, const float* __restrict__ v,
                     __half* __restrict__ cxh, __half* __restrict__ cxl)
{
    const int bh = blockIdx.z;
    const int b = bh >> 4, h = bh & 15;
    const int bm = blockIdx.y * 64;
    __shared__ __align__(16) float As[16][68];
    __shared__ __align__(16) float Bs[16][68];
    const int tid = threadIdx.x;
    const int lk = tid & 15, lr = tid >> 4;
    const int bn_ = tid & 63, bkk = tid >> 6;
    const int tx = tid & 15, ty = tid >> 4;
    float acc[4][4] = {};
    for (int k0 = 0; k0 < T_; k0 += 16) {
        #pragma unroll
        for (int p = 0; p < 4; p++) {
            int m = bm + lr + 16*p;
            As[lk][lr+16*p] = s[((size_t)bh*T_ + m)*T_ + k0 + lk];
        }
        #pragma unroll
        for (int p = 0; p < 4; p++) {
            int jj = bkk + 4*p;
            Bs[jj][bn_] = v[((size_t)(b*T_ + k0 + jj))*D_ + h*DH + bn_];
        }
        __syncthreads();
        #pragma unroll
        for (int k = 0; k < 16; k++) {
            float a[4], bb[4];
            *(float4*)a  = *(const float4*)&As[k][ty*4];
            *(float4*)bb = *(const float4*)&Bs[k][tx*4];
            #pragma unroll
            for (int i = 0; i < 4; i++)
                #pragma unroll
                for (int j = 0; j < 4; j++)
                    acc[i][j] += a[i]*bb[j];
        }
        __syncthreads();
    }
    #pragma unroll
    for (int i = 0; i < 4; i++) {
        int m = bm + ty*4 + i;
        size_t o = ((size_t)(b*T_ + m))*D_ + h*DH + tx*4;
        __half h0, h1, h2, h3, l0, l1, l2, l3;
        split_f16(acc[i][0], h0, l0); split_f16(acc[i][1], h1, l1);
        split_f16(acc[i][2], h2, l2); split_f16(acc[i][3], h3, l3);
        *(__half2*)&cxh[o]   = __half2(h0, h1);
        *(__half2*)&cxh[o+2] = __half2(h2, h3);
        *(__half2*)&cxl[o]   = __half2(l0, l1);
        *(__half2*)&cxl[o+2] = __half2(l2, l3);
    }
}

// =====================================================================
// GAT pieces
// =====================================================================
__global__ __launch_bounds__(256)
void e12_kernel(const float* __restrict__ hg, const float* __restrict__ a1,
                const float* __restrict__ a2, float* __restrict__ e1,
                float* __restrict__ e2)
{
    int wid  = (blockIdx.x * blockDim.x + threadIdx.x) >> 5;
    int lane = threadIdx.x & 31;
    int n = wid >> 3, h = wid & 7;
    const float* row = hg + (size_t)n * D_ + h * GDH;
    float s1 = 0.f, s2 = 0.f;
    #pragma unroll
    for (int r = 0; r < 4; r++) {
        float x = row[lane + 32*r];
        s1 += x * a1[lane + 32*r];
        s2 += x * a2[lane + 32*r];
    }
    #pragma unroll
    for (int o = 16; o; o >>= 1) {
        s1 += __shfl_xor_sync(0xffffffffu, s1, o);
        s2 += __shfl_xor_sync(0xffffffffu, s2, o);
    }
    if (lane == 0) { e1[n*HGAT + h] = s1; e2[n*HGAT + h] = s2; }
}

__global__ __launch_bounds__(256)
void e2max_kernel(const float* __restrict__ e2, float* __restrict__ m2)
{
    int h = blockIdx.x, tid = threadIdx.x;
    float m = -1e30f;
    for (int n = tid; n < M_; n += 256) m = fmaxf(m, e2[n*HGAT + h]);
    __shared__ float sm[256];
    sm[tid] = m; __syncthreads();
    for (int s = 128; s > 0; s >>= 1) {
        if (tid < s) sm[tid] = fmaxf(sm[tid], sm[tid + s]);
        __syncthreads();
    }
    if (tid == 0) m2[h] = sm[0];
}

// GAT aggregation: fp16 HMMA with on-the-fly alpha + fused denom/ELU/residual.
__global__ __launch_bounds__(256)
void gat_hmma_kernel(const __half* __restrict__ hgT, const float* __restrict__ e1,
                     const float* __restrict__ e2, const float* __restrict__ m2,
                     const float* __restrict__ feat, float* __restrict__ out)
{
    __shared__ __align__(16) char sA[TILE_B];
    __shared__ __align__(16) char sB[3][TILE_B];
    __shared__ float s_e1[128], s_mr[128], dpart[256];
    const int h  = blockIdx.x;
    const int bm = blockIdx.y * 128;
    const int tid = threadIdx.x;
    const int wid = tid >> 5, lane = tid & 31;
    const int wm = wid & 1, wn = wid >> 1;
    const uint32_t aU = smem_u32(sA);
    if (tid < 128) {
        float v1 = e1[(bm + tid)*HGAT + h];
        float sv = v1 + m2[h];
        s_mr[tid] = sv > 0.f ? sv : 0.2f * sv;
        s_e1[tid] = v1;
    }
    __syncthreads();
    const int am  = tid >> 1;
    const int ak0 = (tid & 1) * 16;
    const float e1v = s_e1[am], mrv = s_mr[am];
    float dreg = 0.f;
    float acc[4][4][4] = {};

#define ISSUE_B(c) do { \
    int k0 = (c) << 5; \
    uint32_t bufu = smem_u32(sB[(c) % 3]); \
    _Pragma("unroll") \
    for (int it = 0; it < 2; it++) { \
        int g = tid + it*256; \
        int row = g >> 2, cc = g & 3; \
        const __half* src = hgT + (size_t)(h*GDH + row)*M_ + k0 + cc*8; \
        CP16(bufu + row*ROWB + cc*16, src, 16); \
    } \
    CP_COMMIT(); } while (0)

    const int nc = M_ >> 5;               // 64
    ISSUE_B(0);
    ISSUE_B(1);
    for (int c = 0; c < nc; c++) {
        int k0 = c << 5;
        #pragma unroll
        for (int r = 0; r < 16; r++) {
            int j = k0 + ak0 + r;
            float ev = __ldg(&e2[j*HGAT + h]);
            float sv = e1v + ev;
            float lv = sv > 0.f ? sv : 0.2f * sv;
            __half a16 = __float2half_rn(__expf(lv - mrv));
            dreg += __half2float(a16);
            *(__half*)(sA + am*ROWB + (ak0 + r)*2) = a16;
        }
        if (c + 1 < nc) CP_WAIT1(); else CP_WAIT0();
        __syncthreads();
        if (c + 2 < nc) ISSUE_B(c + 2);
        uint32_t bU = smem_u32(sB[c % 3]);
        #pragma unroll
        for (int kk = 0; kk < 32; kk += 16) {
            uint32_t bh[4][2];
            #pragma unroll
            for (int j = 0; j < 4; j++) {
                int nrow = wn*32 + j*8 + (lane & 7);
                int colb = (kk + ((lane >> 3) & 1)*8) * 2;
                LDMX2(bh[j], bU + nrow*ROWB + colb);
            }
            #pragma unroll
            for (int i = 0; i < 4; i++) {
                int mrow = wm*64 + i*16 + (lane & 15);
                int colb = (kk + ((lane >> 4) & 1)*8) * 2;
                uint32_t ah[4];
                LDMX4(ah, aU + mrow*ROWB + colb);
                #pragma unroll
                for (int j = 0; j < 4; j++)
                    MMA16816F(acc[i][j], ah, bh[j]);
            }
        }
        __syncthreads();
    }
#undef ISSUE_B
    dpart[tid] = dreg;
    __syncthreads();
    #pragma unroll
    for (int i = 0; i < 4; i++) {
        int ml = wm*64 + i*16 + (lane >> 2);
        int m0 = bm + ml;
        float inv0 = 1.f / (dpart[2*ml] + dpart[2*ml+1]);
        float inv1 = 1.f / (dpart[2*(ml+8)] + dpart[2*(ml+8)+1]);
        #pragma unroll
        for (int j = 0; j < 4; j++) {
            int n0 = wn*32 + j*8 + (lane & 3)*2;
            int col = h*GDH + n0;
            float v0 = acc[i][j][0]*inv0, v1 = acc[i][j][1]*inv0;
            float v2 = acc[i][j][2]*inv1, v3 = acc[i][j][3]*inv1;
            v0 = v0 > 0.f ? v0 : expm1f(v0);
            v1 = v1 > 0.f ? v1 : expm1f(v1);
            v2 = v2 > 0.f ? v2 : expm1f(v2);
            v3 = v3 > 0.f ? v3 : expm1f(v3);
            size_t o01 = (size_t)m0*D_ + col;
            size_t o23 = (size_t)(m0+8)*D_ + col;
            out[o01]   = v0 + feat[o01];
            out[o01+1] = v1 + feat[o01+1];
            out[o23]   = v2 + feat[o23];
            out[o23+1] = v3 + feat[o23+1];
        }
    }
}

// =====================================================================
extern "C" void kernel_launch(void* const* d_in, const int* in_sizes, int n_in,
                              void* d_out, int out_size)
{
    const float* feat = (const float*)d_in[0];

    Ptr5 cw{}, cb{};
    int wi = 0, bi = 0;
    for (int i = 1; i <= 10; i++) {
        if (in_sizes[i] == D_ * D_ * KW) { if (wi < 5) cw.p[wi++] = (const float*)d_in[i]; }
        else                             { if (bi < 5) cb.p[bi++] = (const float*)d_in[i]; }
    }

    const float* fp_w = (const float*)d_in[11];
    const float* fp_b = (const float*)d_in[12];
    const float* ln_g = (const float*)d_in[13];
    const float* ln_b = (const float*)d_in[14];
    const float* wq = (const float*)d_in[15];
    const float* bq = (const float*)d_in[16];
    const float* wk = (const float*)d_in[17];
    const float* bk = (const float*)d_in[18];
    const float* wv = (const float*)d_in[19];
    const float* bv = (const float*)d_in[20];
    const float* wo = (const float*)d_in[21];
    const float* bo = (const float*)d_in[22];
    const float* gat_w = (const float*)d_in[23];
    const float* gat_b = (const float*)d_in[24];
    const float* a1 = (const float*)d_in[25];
    const float* a2 = (const float*)d_in[26];
    float* out = (float*)d_out;

    __half *f16h, *wt16, *fp16, *dw16;
    __half *msh, *msl, *zh, *zl, *cxh, *cxl, *ath, *atl, *hgT;
    float *z, *q, *k, *v, *s, *hg, *e1, *e2, *m2;
    cudaGetSymbolAddress((void**)&f16h, g_f16h);
    cudaGetSymbolAddress((void**)&wt16, g_wt16);
    cudaGetSymbolAddress((void**)&fp16, g_fp16);
    cudaGetSymbolAddress((void**)&dw16, g_dw16);
    cudaGetSymbolAddress((void**)&msh, g_msh);
    cudaGetSymbolAddress((void**)&msl, g_msl);
    cudaGetSymbolAddress((void**)&z,   g_z);
    cudaGetSymbolAddress((void**)&zh,  g_zh);
    cudaGetSymbolAddress((void**)&zl,  g_zl);
    cudaGetSymbolAddress((void**)&q,   g_q);
    cudaGetSymbolAddress((void**)&k,   g_k);
    cudaGetSymbolAddress((void**)&v,   g_v);
    cudaGetSymbolAddress((void**)&s,   g_s);
    cudaGetSymbolAddress((void**)&cxh, g_cxh);
    cudaGetSymbolAddress((void**)&cxl, g_cxl);
    cudaGetSymbolAddress((void**)&ath, g_ath);
    cudaGetSymbolAddress((void**)&atl, g_atl);
    cudaGetSymbolAddress((void**)&hg,  g_hg);
    cudaGetSymbolAddress((void**)&hgT, g_hgT);
    cudaGetSymbolAddress((void**)&e1,  g_e1);
    cudaGetSymbolAddress((void**)&e2,  g_e2);
    cudaGetSymbolAddress((void**)&m2,  g_m2);

    cudaFuncSetAttribute(hmma_d16_f32,     cudaFuncAttributeMaxDynamicSharedMemorySize, SMEM_3S);
    cudaFuncSetAttribute(hmma_d16_pair,    cudaFuncAttributeMaxDynamicSharedMemorySize, SMEM_3S);
    cudaFuncSetAttribute(hmma_d16_qkv,     cudaFuncAttributeMaxDynamicSharedMemorySize, SMEM_3S);
    cudaFuncSetAttribute(hmma_conv_kernel, cudaFuncAttributeMaxDynamicSharedMemorySize, SMEM_CV);

    const size_t WTN = (size_t)KW * D_ * D_;

    // 0) conversions
    cvt_f16_kernel<<<(M_*D_/4 + 255)/256, 256>>>(feat, f16h, M_*D_/4);
    wtrans5_kernel<<<dim3((int)(WTN/256), 5), 256>>>(cw, wt16);
    cvt_f16_kernel<<<(D_*K5D/4 + 255)/256, 256>>>(fp_w, fp16, D_*K5D/4);
    Ptr5 dws{{ wq, wk, wv, wo, gat_w }};
    cvt5_f16_kernel<<<dim3(D_*D_/4/256, 5), 256>>>(dws, dw16);

    // 1) dilated convs (fp16 1-term) -> msh/msl fp16 pairs
    hmma_conv_kernel<<<dim3(8, 16, 5), 256, SMEM_CV>>>(f16h, wt16, cb, msh, msl);

    // 2) fusion projection (K=5120, 2-term) -> z fp32, then LN+GELU -> zh/zl
    hmma_d16_f32<<<dim3(8, 16), 256, SMEM_3S>>>(msh, msl, fp16, fp_b, z, K5D, D_);
    ln_gelu_kernel<<<M_, 256>>>(z, ln_g, ln_b, zh, zl);

    // 3) q, k, v projections (merged, 2-term)
    QkvArgs qkv{{ q, k, v }, { bq, bk, bv }};
    hmma_d16_qkv<<<dim3(8, 16, 3), 256, SMEM_3S>>>(zh, zl, dw16, qkv);

    // 4) attention (fp32) -> cxh/cxl fp16 pairs
    attn_scores_kernel<<<dim3(4, 4, B_*HMHA), 256>>>(q, k, s);
    softmax_kernel<<<(B_*HMHA*T_)/8, 256>>>(s);
    attn_ctx_kernel<<<dim3(1, 4, B_*HMHA), 256>>>(s, v, cxh, cxl);

    // 5) wo -> ath/atl fp16 pairs; gat_w -> hg fp32 (2-term)
    hmma_d16_pair<<<dim3(8, 16), 256, SMEM_3S>>>(cxh, cxl,
        dw16 + 3*(size_t)D_*D_, bo, ath, atl, D_, D_);
    hmma_d16_f32<<<dim3(8, 16), 256, SMEM_3S>>>(ath, atl,
        dw16 + 4*(size_t)D_*D_, gat_b, hg, D_, D_);

    // 6) GAT logits, max, transpose
    e12_kernel<<<(M_*HGAT)/8, 256>>>(hg, a1, a2, e1, e2);
    e2max_kernel<<<HGAT, 256>>>(e2, m2);
    transpose_f16_kernel<<<dim3(M_/32, D_/32), 256>>>(hg, hgT);

    // 7) GAT aggregation (fp16 HMMA) + ELU + residual -> d_out
    gat_hmma_kernel<<<dim3(HGAT, 16), 256>>>(hgT, e1, e2, m2, feat, out);
}

// round 11
// speedup vs baseline: 6.6938x; 1.1758x over previous
#include <cuda_runtime.h>
#include <cuda_fp16.h>
#include <math.h>
#include <stdint.h>

#define D_   1024
#define T_   256
#define B_   8
#define M_   (B_*T_)        // 2048 rows (b,t)
#define HMHA 16
#define DH   64
#define HGAT 8
#define GDH  128
#define KW   7
#define K5D  (5*D_)
#define KCONV (KW*D_)       // 7168

#define ROWB    80                   // bytes per smem row (32 fp16 + pad)
#define TILE_B  (128*ROWB)           // 10240 B per 128-row tile
#define TILE_BN (64*ROWB)            // 5120 B per 64-row tile
#define SMEM_CV (3*2*TILE_B)         // 3 stages x 2 tiles = 61440

// ===================== PTX helpers (baseline ISA only) =====================
__device__ __forceinline__ uint32_t smem_u32(const void* p) {
    uint32_t a;
    asm("{ .reg .u64 t; cvta.to.shared.u64 t, %1; cvt.u32.u64 %0, t; }"
        : "=r"(a) : "l"(p));
    return a;
}
#define CP16(dst, src, sz) \
    asm volatile("cp.async.cg.shared.global [%0], [%1], 16, %2;" \
                 :: "r"(dst), "l"(src), "r"(sz))
#define CP_COMMIT() asm volatile("cp.async.commit_group;" ::: "memory")
#define CP_WAIT1()  asm volatile("cp.async.wait_group 1;" ::: "memory")
#define CP_WAIT0()  asm volatile("cp.async.wait_group 0;" ::: "memory")

#define LDMX4(r, addr) \
    asm volatile("ldmatrix.sync.aligned.m8n8.x4.shared.b16 {%0,%1,%2,%3}, [%4];" \
        : "=r"((r)[0]), "=r"((r)[1]), "=r"((r)[2]), "=r"((r)[3]) : "r"(addr))
#define LDMX2(r, addr) \
    asm volatile("ldmatrix.sync.aligned.m8n8.x2.shared.b16 {%0,%1}, [%2];" \
        : "=r"((r)[0]), "=r"((r)[1]) : "r"(addr))

#define MMA16816F(c, a, b) \
    asm volatile("mma.sync.aligned.m16n8k16.row.col.f32.f16.f16.f32 " \
        "{%0,%1,%2,%3}, {%4,%5,%6,%7}, {%8,%9}, {%0,%1,%2,%3};" \
        : "+f"((c)[0]), "+f"((c)[1]), "+f"((c)[2]), "+f"((c)[3]) \
        : "r"((a)[0]), "r"((a)[1]), "r"((a)[2]), "r"((a)[3]), \
          "r"((b)[0]), "r"((b)[1]))

struct Ptr5  { const float* p[5]; };
struct QkvArgs { __half* o[3]; const float* b[3]; };

// ---------------- scratch (device globals; no allocation) ----------------
__device__ __half g_f16 [M_ * D_];                 // feat fp16
__device__ __half g_wt16[5 * KW * D_ * D_];        // conv weights fp16 [c][tap][o][ci]
__device__ __half g_fp16[D_ * K5D];                // fusion weight fp16
__device__ __half g_dw16[5 * D_ * D_];             // wq,wk,wv,wo,gat_w fp16
__device__ __half g_ms16[M_ * K5D];                // conv out fp16
__device__ float  g_z  [M_ * D_];
__device__ __half g_z16[M_ * D_];
__device__ __half g_q16[M_ * D_];
__device__ __half g_k16[M_ * D_];
__device__ __half g_v16[M_ * D_];
__device__ __half g_vT [B_*HMHA * DH * T_];        // V transposed per head
__device__ float  g_s  [B_*HMHA * T_ * T_];
__device__ __half g_p16[B_*HMHA * T_ * T_];        // softmax probs fp16
__device__ __half g_cx16[M_ * D_];
__device__ __half g_at16[M_ * D_];
__device__ float  g_hg [M_ * D_];
__device__ __half g_hgT[D_ * M_];
__device__ float  g_e1[M_ * HGAT];
__device__ float  g_e2[M_ * HGAT];
__device__ float  g_m2[HGAT];

// =====================================================================
// conversion kernels
// =====================================================================
__global__ __launch_bounds__(256)
void cvt_f16_kernel(const float* __restrict__ src, __half* __restrict__ hi, int n4)
{
    int i = blockIdx.x * 256 + threadIdx.x;
    if (i >= n4) return;
    float4 v = ((const float4*)src)[i];
    __half2* ph = (__half2*)hi;
    ph[2*i]   = __half2(__float2half_rn(v.x), __float2half_rn(v.y));
    ph[2*i+1] = __half2(__float2half_rn(v.z), __float2half_rn(v.w));
}

__global__ __launch_bounds__(256)
void cvt5_f16_kernel(Ptr5 ws, __half* __restrict__ hi)
{
    int c = blockIdx.y;
    int i = blockIdx.x * 256 + threadIdx.x;           // over D*D/4
    float4 v = ((const float4*)ws.p[c])[i];
    __half2* ph = (__half2*)(hi + (size_t)c * D_ * D_);
    ph[2*i]   = __half2(__float2half_rn(v.x), __float2half_rn(v.y));
    ph[2*i+1] = __half2(__float2half_rn(v.z), __float2half_rn(v.w));
}

__global__ __launch_bounds__(256)
void wtrans5_kernel(Ptr5 cw, __half* __restrict__ wh)
{
    int c = blockIdx.y;
    int idx = blockIdx.x * 256 + threadIdx.x;      // over 7*1024*1024
    int tap = idx >> 20;
    int rem = idx & ((1 << 20) - 1);
    int o  = rem >> 10;
    int ci = rem & 1023;
    float x = __ldg(&cw.p[c][(size_t)o * KCONV + ci * 7 + tap]);
    wh[(size_t)c * (KW*D_*D_) + idx] = __float2half_rn(x);
}

// hg fp32 (2048 x 1024) -> hgT fp16 (1024 x 2048)
__global__ __launch_bounds__(256)
void transpose_f16_kernel(const float* __restrict__ hg, __half* __restrict__ hgT)
{
    __shared__ float tile[32][33];
    int j0 = blockIdx.x * 32, c0 = blockIdx.y * 32;
    int tx = threadIdx.x & 31, ty = threadIdx.x >> 5;   // 32 x 8
    #pragma unroll
    for (int r = ty; r < 32; r += 8)
        tile[r][tx] = hg[(size_t)(j0 + r) * D_ + c0 + tx];
    __syncthreads();
    #pragma unroll
    for (int r = ty; r < 32; r += 8)
        hgT[(size_t)(c0 + r) * M_ + j0 + tx] = __float2half_rn(tile[tx][r]);
}

// v16 [b*T+t][h*64+d] -> vT [(b*16+h)*64+d][t]
__global__ __launch_bounds__(256)
void vtrans_kernel(const __half* __restrict__ v16, __half* __restrict__ vT)
{
    __shared__ __half tile[32][34];
    const int bh = blockIdx.z;
    const int b = bh >> 4, h = bh & 15;
    const int t0 = blockIdx.x * 32, d0 = blockIdx.y * 32;
    int tx = threadIdx.x & 31, ty = threadIdx.x >> 5;
    #pragma unroll
    for (int r = ty; r < 32; r += 8)
        tile[r][tx] = v16[(size_t)(b*T_ + t0 + r)*D_ + h*DH + d0 + tx];
    __syncthreads();
    #pragma unroll
    for (int r = ty; r < 32; r += 8)
        vT[(size_t)(bh*DH + d0 + r)*T_ + t0 + tx] = tile[tx][r];
}

// =====================================================================
// fp16 1-term HMMA core: tiles 0=A, 1=B
// =====================================================================
__device__ __forceinline__
void hmma_chunk_1t(uint32_t bufu, int wm, int wn, int lane, float acc[4][4][4])
{
    #pragma unroll
    for (int kk = 0; kk < 32; kk += 16) {
        uint32_t bh[4][2];
        #pragma unroll
        for (int j = 0; j < 4; j++) {
            int nrow = wn*32 + j*8 + (lane & 7);
            int colb = (kk + ((lane >> 3) & 1)*8) * 2;
            LDMX2(bh[j], bufu + 1*TILE_B + nrow*ROWB + colb);
        }
        #pragma unroll
        for (int i = 0; i < 4; i++) {
            int mrow = wm*64 + i*16 + (lane & 15);
            int colb = (kk + ((lane >> 4) & 1)*8) * 2;
            uint32_t ah[4];
            LDMX4(ah, bufu + 0*TILE_B + mrow*ROWB + colb);
            #pragma unroll
            for (int j = 0; j < 4; j++)
                MMA16816F(acc[i][j], ah, bh[j]);
        }
    }
}

__device__ __forceinline__
void issue_1t(uint32_t smem_base, int c, int tid,
              const __half* __restrict__ A, const __half* __restrict__ W,
              int bm, int bn, int K)
{
    int k0 = c << 5;
    uint32_t bufu = smem_base + (c % 3) * 2*TILE_B;
    #pragma unroll
    for (int it = 0; it < 4; it++) {
        int g = tid + it*256;
        int tile = g >> 9;
        int ct = g & 511, row = ct >> 2, cc = ct & 3;
        const __half* src = (tile == 0)
            ? A + (size_t)(bm+row)*K + k0 + cc*8
            : W + (size_t)(bn+row)*K + k0 + cc*8;
        CP16(bufu + tile*TILE_B + row*ROWB + cc*16, src, 16);
    }
    CP_COMMIT();
}

__device__ __forceinline__
void epi_f32(float acc[4][4][4], const float* __restrict__ bias,
             float* __restrict__ C, int bm, int bn, int ldc,
             int wm, int wn, int lane)
{
    #pragma unroll
    for (int i = 0; i < 4; i++) {
        int m0 = bm + wm*64 + i*16 + (lane >> 2);
        #pragma unroll
        for (int j = 0; j < 4; j++) {
            int n0 = wn*32 + j*8 + (lane & 3)*2;
            float b0 = bias[bn + n0], b1 = bias[bn + n0 + 1];
            *(float2*)&C[(size_t)m0*ldc + bn + n0] =
                make_float2(acc[i][j][0] + b0, acc[i][j][1] + b1);
            *(float2*)&C[(size_t)(m0+8)*ldc + bn + n0] =
                make_float2(acc[i][j][2] + b0, acc[i][j][3] + b1);
        }
    }
}

__device__ __forceinline__
void epi_f16(float acc[4][4][4], const float* __restrict__ bias,
             __half* __restrict__ C, int bm, int bn, int ldc, int colbase,
             int wm, int wn, int lane)
{
    #pragma unroll
    for (int i = 0; i < 4; i++) {
        int m0 = bm + wm*64 + i*16 + (lane >> 2);
        #pragma unroll
        for (int j = 0; j < 4; j++) {
            int n0 = wn*32 + j*8 + (lane & 3)*2;
            float b0 = bias[bn + n0], b1 = bias[bn + n0 + 1];
            size_t o01 = (size_t)m0*ldc + colbase + bn + n0;
            size_t o23 = (size_t)(m0+8)*ldc + colbase + bn + n0;
            *(__half2*)&C[o01] = __half2(__float2half_rn(acc[i][j][0] + b0),
                                         __float2half_rn(acc[i][j][1] + b1));
            *(__half2*)&C[o23] = __half2(__float2half_rn(acc[i][j][2] + b0),
                                         __float2half_rn(acc[i][j][3] + b1));
        }
    }
}

#define HMMA_PROLOG() \
    extern __shared__ __align__(16) char smem_raw[]; \
    const uint32_t smem_base = smem_u32(smem_raw); \
    const int bm = blockIdx.y * 128, bn = blockIdx.x * 128; \
    const int tid = threadIdx.x; \
    const int wid = tid >> 5, lane = tid & 31; \
    const int wm = wid & 1, wn = wid >> 1; \
    float acc[4][4][4] = {};

#define HMMA_LOOP3(NC, ISSUE) \
    ISSUE(0); \
    ISSUE(1); \
    for (int c = 0; c < (NC); c++) { \
        if (c + 1 < (NC)) CP_WAIT1(); else CP_WAIT0(); \
        __syncthreads(); \
        if (c + 2 < (NC)) ISSUE(c + 2); \
        hmma_chunk_1t(smem_base + (c % 3)*2*TILE_B, wm, wn, lane, acc); \
        __syncthreads(); \
    }

// ---- dense 1-term, fp32 out (fusion, gat_w) ----
__global__ __launch_bounds__(256, 2)
void hmma_1t_f32(const __half* __restrict__ A, const __half* __restrict__ W,
                 const float* __restrict__ bias, float* __restrict__ C,
                 int K, int ldc)
{
    HMMA_PROLOG();
#define ISS(c) issue_1t(smem_base, c, tid, A, W, bm, bn, K)
    HMMA_LOOP3(K >> 5, ISS);
#undef ISS
    epi_f32(acc, bias, C, bm, bn, ldc, wm, wn, lane);
}

// ---- dense 1-term, fp16 out (wo) ----
__global__ __launch_bounds__(256, 2)
void hmma_1t_f16(const __half* __restrict__ A, const __half* __restrict__ W,
                 const float* __restrict__ bias, __half* __restrict__ C,
                 int K, int ldc)
{
    HMMA_PROLOG();
#define ISS(c) issue_1t(smem_base, c, tid, A, W, bm, bn, K)
    HMMA_LOOP3(K >> 5, ISS);
#undef ISS
    epi_f16(acc, bias, C, bm, bn, ldc, 0, wm, wn, lane);
}

// ---- QKV: grid.z selects weight/bias/output, fp16 out ----
__global__ __launch_bounds__(256, 2)
void hmma_1t_qkv(const __half* __restrict__ A, const __half* __restrict__ dw16,
                 QkvArgs args)
{
    const int z = blockIdx.z;
    const __half* Wh = dw16 + (size_t)z * D_ * D_;
    HMMA_PROLOG();
#define ISS(c) issue_1t(smem_base, c, tid, A, Wh, bm, bn, D_)
    HMMA_LOOP3(D_ >> 5, ISS);
#undef ISS
    epi_f16(acc, args.b[z], args.o[z], bm, bn, D_, 0, wm, wn, lane);
}

// ---- convs: fp16 1-term gather, grid.z = conv id, fp16 out ----
__global__ __launch_bounds__(256, 2)
void hmma_conv_kernel(const __half* __restrict__ Fh,
                      const __half* __restrict__ wt16, Ptr5 cbs,
                      __half* __restrict__ ms16)
{
    const int z = blockIdx.z;
    const int dil = 1 << z;
    const int ccol = z * D_;
    const __half* Wh = wt16 + (size_t)z * (KW*D_*D_);
    HMMA_PROLOG();

#define ISSUE_C(c) do { \
    int k0 = (c) << 5; \
    int tap = k0 >> 10, ci0 = k0 & 1023; \
    int offt = (tap - 3) * dil; \
    uint32_t bufu = smem_base + ((c) % 3) * 2*TILE_B; \
    _Pragma("unroll") \
    for (int it = 0; it < 4; it++) { \
        int g = tid + it*256; \
        int tile = g >> 9; \
        int ct = g & 511; int row = ct >> 2, cc = ct & 3; \
        const __half* src; \
        uint32_t sz = 16; \
        if (tile == 0) { \
            int m = bm + row; \
            int bb = m >> 8, tt = (m & 255) + offt; \
            if (tt >= 0 && tt < T_) \
                src = Fh + ((size_t)(bb*T_ + tt))*D_ + ci0 + cc*8; \
            else { src = Fh; sz = 0; } \
        } else { \
            src = Wh + (size_t)tap*D_*D_ + (size_t)(bn+row)*D_ + ci0 + cc*8; \
        } \
        CP16(bufu + tile*TILE_B + row*ROWB + cc*16, src, sz); \
    } \
    CP_COMMIT(); } while (0)

    HMMA_LOOP3(KCONV >> 5, ISSUE_C);
#undef ISSUE_C
    epi_f16(acc, cbs.p[z], ms16, bm, bn, K5D, ccol, wm, wn, lane);
}

// =====================================================================
// LayerNorm + exact GELU: reads z fp32, writes z16 fp16.
// =====================================================================
__global__ __launch_bounds__(256)
void ln_gelu_kernel(const float* __restrict__ z, const float* __restrict__ g,
                    const float* __restrict__ b, __half* __restrict__ z16)
{
    const int row = blockIdx.x;
    const int tid = threadIdx.x;
    const float* p = z + (size_t)row * D_;
    float4 v = ((const float4*)p)[tid];
    float s  = v.x + v.y + v.z + v.w;
    float ss = v.x*v.x + v.y*v.y + v.z*v.z + v.w*v.w;
    #pragma unroll
    for (int o = 16; o; o >>= 1) {
        s  += __shfl_xor_sync(0xffffffffu, s,  o);
        ss += __shfl_xor_sync(0xffffffffu, ss, o);
    }
    __shared__ float ws[8], wss[8];
    __shared__ float mu_s, inv_s;
    int lane = tid & 31, wid = tid >> 5;
    if (lane == 0) { ws[wid] = s; wss[wid] = ss; }
    __syncthreads();
    if (tid == 0) {
        float S = 0.f, SS = 0.f;
        #pragma unroll
        for (int i = 0; i < 8; i++) { S += ws[i]; SS += wss[i]; }
        float mu = S * (1.f / D_);
        float var = SS * (1.f / D_) - mu * mu;
        mu_s = mu;
        inv_s = rsqrtf(var + 1e-5f);
    }
    __syncthreads();
    float mu = mu_s, inv = inv_s;
    float4 gg = ((const float4*)g)[tid];
    float4 bb = ((const float4*)b)[tid];
    float y[4] = { (v.x-mu)*inv*gg.x + bb.x, (v.y-mu)*inv*gg.y + bb.y,
                   (v.z-mu)*inv*gg.z + bb.z, (v.w-mu)*inv*gg.w + bb.w };
    float o[4];
    o[0] = 0.5f*y[0]*(1.f + erff(y[0]*0.70710678118654752f));
    o[1] = 0.5f*y[1]*(1.f + erff(y[1]*0.70710678118654752f));
    o[2] = 0.5f*y[2]*(1.f + erff(y[2]*0.70710678118654752f));
    o[3] = 0.5f*y[3]*(1.f + erff(y[3]*0.70710678118654752f));
    __half2* ph = (__half2*)(z16 + (size_t)row * D_);
    ph[2*tid]   = __half2(__float2half_rn(o[0]), __float2half_rn(o[1]));
    ph[2*tid+1] = __half2(__float2half_rn(o[2]), __float2half_rn(o[3]));
}

// =====================================================================
// Attention, fp16 HMMA
// =====================================================================
// scores: S[bh, m, n] = 0.125 * q16[b,m,h,:] . k16[b,n,h,:]   (K = 64)
__global__ __launch_bounds__(256)
void attn_scores_hmma(const __half* __restrict__ q16, const __half* __restrict__ k16,
                      float* __restrict__ s)
{
    __shared__ __align__(16) char smem[2][2*TILE_B];
    const int bh = blockIdx.z;
    const int b = bh >> 4, h = bh & 15;
    const int bm = blockIdx.y * 128, bn = blockIdx.x * 128;
    const int tid = threadIdx.x;
    const int wid = tid >> 5, lane = tid & 31;
    const int wm = wid & 1, wn = wid >> 1;
    float acc[4][4][4] = {};

#define ISSUE_S(c) do { \
    int k0 = (c) << 5; \
    uint32_t bufu = smem_u32(smem[(c) & 1]); \
    _Pragma("unroll") \
    for (int it = 0; it < 4; it++) { \
        int g = tid + it*256; \
        int tile = g >> 9; \
        int ct = g & 511, row = ct >> 2, cc = ct & 3; \
        const __half* src = (tile == 0) \
            ? q16 + (size_t)(b*T_ + bm + row)*D_ + h*DH + k0 + cc*8 \
            : k16 + (size_t)(b*T_ + bn + row)*D_ + h*DH + k0 + cc*8; \
        CP16(bufu + tile*TILE_B + row*ROWB + cc*16, src, 16); \
    } \
    CP_COMMIT(); } while (0)

    ISSUE_S(0);
    ISSUE_S(1);
    CP_WAIT1();
    __syncthreads();
    hmma_chunk_1t(smem_u32(smem[0]), wm, wn, lane, acc);
    CP_WAIT0();
    __syncthreads();
    hmma_chunk_1t(smem_u32(smem[1]), wm, wn, lane, acc);
#undef ISSUE_S

    float* sp = s + (size_t)bh * T_ * T_;
    #pragma unroll
    for (int i = 0; i < 4; i++) {
        int m0 = bm + wm*64 + i*16 + (lane >> 2);
        #pragma unroll
        for (int j = 0; j < 4; j++) {
            int n0 = bn + wn*32 + j*8 + (lane & 3)*2;
            *(float2*)&sp[(size_t)m0*T_ + n0] =
                make_float2(acc[i][j][0]*0.125f, acc[i][j][1]*0.125f);
            *(float2*)&sp[(size_t)(m0+8)*T_ + n0] =
                make_float2(acc[i][j][2]*0.125f, acc[i][j][3]*0.125f);
        }
    }
}

// softmax fp32 -> fp16 probs
__global__ __launch_bounds__(256)
void softmax_kernel(const float* __restrict__ s, __half* __restrict__ p16)
{
    int row  = (blockIdx.x * blockDim.x + threadIdx.x) >> 5;
    int lane = threadIdx.x & 31;
    const float* p = s + (size_t)row * T_;
    __half* po = p16 + (size_t)row * T_;
    float v[8];
    float m = -1e30f;
    #pragma unroll
    for (int r = 0; r < 8; r++) { v[r] = p[lane + 32*r]; m = fmaxf(m, v[r]); }
    #pragma unroll
    for (int o = 16; o; o >>= 1) m = fmaxf(m, __shfl_xor_sync(0xffffffffu, m, o));
    float sum = 0.f;
    #pragma unroll
    for (int r = 0; r < 8; r++) { v[r] = __expf(v[r] - m); sum += v[r]; }
    #pragma unroll
    for (int o = 16; o; o >>= 1) sum += __shfl_xor_sync(0xffffffffu, sum, o);
    float inv = 1.f / sum;
    #pragma unroll
    for (int r = 0; r < 8; r++) po[lane + 32*r] = __float2half_rn(v[r] * inv);
}

// ctx = P @ V^T-tile: M=128, N=64, K=256. grid (2 m-tiles, bh).
__global__ __launch_bounds__(256)
void attn_ctx_hmma(const __half* __restrict__ p16, const __half* __restrict__ vT,
                   __half* __restrict__ cx16)
{
    __shared__ __align__(16) char smem[2][TILE_B + TILE_BN];
    const int bh = blockIdx.y;
    const int b = bh >> 4, h = bh & 15;
    const int bm = blockIdx.x * 128;
    const int tid = threadIdx.x;
    const int wid = tid >> 5, lane = tid & 31;
    const int wm = wid & 1, wn = wid >> 1;          // 2 x 4 warps, warp 64x16
    float acc[4][2][4] = {};

#define ISSUE_X(c) do { \
    int k0 = (c) << 5; \
    uint32_t bufu = smem_u32(smem[(c) & 1]); \
    _Pragma("unroll") \
    for (int it = 0; it < 3; it++) { \
        int g = tid + it*256; \
        if (g < 512) { \
            int row = g >> 2, cc = g & 3; \
            const __half* src = p16 + (size_t)(bh*T_ + bm + row)*T_ + k0 + cc*8; \
            CP16(bufu + row*ROWB + cc*16, src, 16); \
        } else { \
            int gg = g - 512; \
            int row = gg >> 2, cc = gg & 3; \
            const __half* src = vT + (size_t)(bh*DH + row)*T_ + k0 + cc*8; \
            CP16(bufu + TILE_B + row*ROWB + cc*16, src, 16); \
        } \
    } \
    CP_COMMIT(); } while (0)

    const int nc = T_ >> 5;     // 8
    ISSUE_X(0);
    for (int c = 0; c < nc; c++) {
        if (c + 1 < nc) { ISSUE_X(c + 1); CP_WAIT1(); }
        else            { CP_WAIT0(); }
        __syncthreads();
        uint32_t bufu = smem_u32(smem[c & 1]);
        #pragma unroll
        for (int kk = 0; kk < 32; kk += 16) {
            uint32_t bhf[2][2];
            #pragma unroll
            for (int j = 0; j < 2; j++) {
                int nrow = wn*16 + j*8 + (lane & 7);
                int colb = (kk + ((lane >> 3) & 1)*8) * 2;
                LDMX2(bhf[j], bufu + TILE_B + nrow*ROWB + colb);
            }
            #pragma unroll
            for (int i = 0; i < 4; i++) {
                int mrow = wm*64 + i*16 + (lane & 15);
                int colb = (kk + ((lane >> 4) & 1)*8) * 2;
                uint32_t ah[4];
                LDMX4(ah, bufu + mrow*ROWB + colb);
                #pragma unroll
                for (int j = 0; j < 2; j++)
                    MMA16816F(acc[i][j], ah, bhf[j]);
            }
        }
        __syncthreads();
    }
#undef ISSUE_X
    #pragma unroll
    for (int i = 0; i < 4; i++) {
        int m0 = bm + wm*64 + i*16 + (lane >> 2);
        #pragma unroll
        for (int j = 0; j < 2; j++) {
            int n0 = wn*16 + j*8 + (lane & 3)*2;
            size_t o01 = (size_t)(b*T_ + m0)*D_ + h*DH + n0;
            size_t o23 = (size_t)(b*T_ + m0 + 8)*D_ + h*DH + n0;
            *(__half2*)&cx16[o01] = __half2(__float2half_rn(acc[i][j][0]),
                                            __float2half_rn(acc[i][j][1]));
            *(__half2*)&cx16[o23] = __half2(__float2half_rn(acc[i][j][2]),
                                            __float2half_rn(acc[i][j][3]));
        }
    }
}

// =====================================================================
// GAT pieces
// =====================================================================
__global__ __launch_bounds__(256)
void e12_kernel(const float* __restrict__ hg, const float* __restrict__ a1,
                const float* __restrict__ a2, float* __restrict__ e1,
                float* __restrict__ e2)
{
    int wid  = (blockIdx.x * blockDim.x + threadIdx.x) >> 5;
    int lane = threadIdx.x & 31;
    int n = wid >> 3, h = wid & 7;
    const float* row = hg + (size_t)n * D_ + h * GDH;
    float s1 = 0.f, s2 = 0.f;
    #pragma unroll
    for (int r = 0; r < 4; r++) {
        float x = row[lane + 32*r];
        s1 += x * a1[lane + 32*r];
        s2 += x * a2[lane + 32*r];
    }
    #pragma unroll
    for (int o = 16; o; o >>= 1) {
        s1 += __shfl_xor_sync(0xffffffffu, s1, o);
        s2 += __shfl_xor_sync(0xffffffffu, s2, o);
    }
    if (lane == 0) { e1[n*HGAT + h] = s1; e2[n*HGAT + h] = s2; }
}

__global__ __launch_bounds__(256)
void e2max_kernel(const float* __restrict__ e2, float* __restrict__ m2)
{
    int h = blockIdx.x, tid = threadIdx.x;
    float m = -1e30f;
    for (int n = tid; n < M_; n += 256) m = fmaxf(m, e2[n*HGAT + h]);
    __shared__ float sm[256];
    sm[tid] = m; __syncthreads();
    for (int s = 128; s > 0; s >>= 1) {
        if (tid < s) sm[tid] = fmaxf(sm[tid], sm[tid + s]);
        __syncthreads();
    }
    if (tid == 0) m2[h] = sm[0];
}

// GAT aggregation: fp16 HMMA with on-the-fly alpha + fused denom/ELU/residual.
__global__ __launch_bounds__(256)
void gat_hmma_kernel(const __half* __restrict__ hgT, const float* __restrict__ e1,
                     const float* __restrict__ e2, const float* __restrict__ m2,
                     const float* __restrict__ feat, float* __restrict__ out)
{
    __shared__ __align__(16) char sA[TILE_B];
    __shared__ __align__(16) char sB[3][TILE_B];
    __shared__ float s_e1[128], s_mr[128], dpart[256];
    const int h  = blockIdx.x;
    const int bm = blockIdx.y * 128;
    const int tid = threadIdx.x;
    const int wid = tid >> 5, lane = tid & 31;
    const int wm = wid & 1, wn = wid >> 1;
    const uint32_t aU = smem_u32(sA);
    if (tid < 128) {
        float v1 = e1[(bm + tid)*HGAT + h];
        float sv = v1 + m2[h];
        s_mr[tid] = sv > 0.f ? sv : 0.2f * sv;
        s_e1[tid] = v1;
    }
    __syncthreads();
    const int am  = tid >> 1;
    const int ak0 = (tid & 1) * 16;
    const float e1v = s_e1[am], mrv = s_mr[am];
    float dreg = 0.f;
    float acc[4][4][4] = {};

#define ISSUE_B(c) do { \
    int k0 = (c) << 5; \
    uint32_t bufu = smem_u32(sB[(c) % 3]); \
    _Pragma("unroll") \
    for (int it = 0; it < 2; it++) { \
        int g = tid + it*256; \
        int row = g >> 2, cc = g & 3; \
        const __half* src = hgT + (size_t)(h*GDH + row)*M_ + k0 + cc*8; \
        CP16(bufu + row*ROWB + cc*16, src, 16); \
    } \
    CP_COMMIT(); } while (0)

    const int nc = M_ >> 5;               // 64
    ISSUE_B(0);
    ISSUE_B(1);
    for (int c = 0; c < nc; c++) {
        int k0 = c << 5;
        #pragma unroll
        for (int r = 0; r < 16; r++) {
            int j = k0 + ak0 + r;
            float ev = __ldg(&e2[j*HGAT + h]);
            float sv = e1v + ev;
            float lv = sv > 0.f ? sv : 0.2f * sv;
            __half a16 = __float2half_rn(__expf(lv - mrv));
            dreg += __half2float(a16);
            *(__half*)(sA + am*ROWB + (ak0 + r)*2) = a16;
        }
        if (c + 1 < nc) CP_WAIT1(); else CP_WAIT0();
        __syncthreads();
        if (c + 2 < nc) ISSUE_B(c + 2);
        uint32_t bU = smem_u32(sB[c % 3]);
        #pragma unroll
        for (int kk = 0; kk < 32; kk += 16) {
            uint32_t bhf[4][2];
            #pragma unroll
            for (int j = 0; j < 4; j++) {
                int nrow = wn*32 + j*8 + (lane & 7);
                int colb = (kk + ((lane >> 3) & 1)*8) * 2;
                LDMX2(bhf[j], bU + nrow*ROWB + colb);
            }
            #pragma unroll
            for (int i = 0; i < 4; i++) {
                int mrow = wm*64 + i*16 + (lane & 15);
                int colb = (kk + ((lane >> 4) & 1)*8) * 2;
                uint32_t ah[4];
                LDMX4(ah, aU + mrow*ROWB + colb);
                #pragma unroll
                for (int j = 0; j < 4; j++)
                    MMA16816F(acc[i][j], ah, bhf[j]);
            }
        }
        __syncthreads();
    }
#undef ISSUE_B
    dpart[tid] = dreg;
    __syncthreads();
    #pragma unroll
    for (int i = 0; i < 4; i++) {
        int ml = wm*64 + i*16 + (lane >> 2);
        int m0 = bm + ml;
        float inv0 = 1.f / (dpart[2*ml] + dpart[2*ml+1]);
        float inv1 = 1.f / (dpart[2*(ml+8)] + dpart[2*(ml+8)+1]);
        #pragma unroll
        for (int j = 0; j < 4; j++) {
            int n0 = wn*32 + j*8 + (lane & 3)*2;
            int col = h*GDH + n0;
            float v0 = acc[i][j][0]*inv0, v1 = acc[i][j][1]*inv0;
            float v2 = acc[i][j][2]*inv1, v3 = acc[i][j][3]*inv1;
            v0 = v0 > 0.f ? v0 : expm1f(v0);
            v1 = v1 > 0.f ? v1 : expm1f(v1);
            v2 = v2 > 0.f ? v2 : expm1f(v2);
            v3 = v3 > 0.f ? v3 : expm1f(v3);
            size_t o01 = (size_t)m0*D_ + col;
            size_t o23 = (size_t)(m0+8)*D_ + col;
            out[o01]   = v0 + feat[o01];
            out[o01+1] = v1 + feat[o01+1];
            out[o23]   = v2 + feat[o23];
            out[o23+1] = v3 + feat[o23+1];
        }
    }
}

// =====================================================================
extern "C" void kernel_launch(void* const* d_in, const int* in_sizes, int n_in,
                              void* d_out, int out_size)
{
    const float* feat = (const float*)d_in[0];

    Ptr5 cw{}, cb{};
    int wi = 0, bi = 0;
    for (int i = 1; i <= 10; i++) {
        if (in_sizes[i] == D_ * D_ * KW) { if (wi < 5) cw.p[wi++] = (const float*)d_in[i]; }
        else                             { if (bi < 5) cb.p[bi++] = (const float*)d_in[i]; }
    }

    const float* fp_w = (const float*)d_in[11];
    const float* fp_b = (const float*)d_in[12];
    const float* ln_g = (const float*)d_in[13];
    const float* ln_b = (const float*)d_in[14];
    const float* wq = (const float*)d_in[15];
    const float* bq = (const float*)d_in[16];
    const float* wk = (const float*)d_in[17];
    const float* bk = (const float*)d_in[18];
    const float* wv = (const float*)d_in[19];
    const float* bv = (const float*)d_in[20];
    const float* wo = (const float*)d_in[21];
    const float* bo = (const float*)d_in[22];
    const float* gat_w = (const float*)d_in[23];
    const float* gat_b = (const float*)d_in[24];
    const float* a1 = (const float*)d_in[25];
    const float* a2 = (const float*)d_in[26];
    float* out = (float*)d_out;

    __half *f16, *wt16, *fp16, *dw16, *ms16, *z16, *q16, *k16, *v16, *vT;
    __half *p16, *cx16, *at16, *hgT;
    float *z, *s, *hg, *e1, *e2, *m2;
    cudaGetSymbolAddress((void**)&f16,  g_f16);
    cudaGetSymbolAddress((void**)&wt16, g_wt16);
    cudaGetSymbolAddress((void**)&fp16, g_fp16);
    cudaGetSymbolAddress((void**)&dw16, g_dw16);
    cudaGetSymbolAddress((void**)&ms16, g_ms16);
    cudaGetSymbolAddress((void**)&z,    g_z);
    cudaGetSymbolAddress((void**)&z16,  g_z16);
    cudaGetSymbolAddress((void**)&q16,  g_q16);
    cudaGetSymbolAddress((void**)&k16,  g_k16);
    cudaGetSymbolAddress((void**)&v16,  g_v16);
    cudaGetSymbolAddress((void**)&vT,   g_vT);
    cudaGetSymbolAddress((void**)&s,    g_s);
    cudaGetSymbolAddress((void**)&p16,  g_p16);
    cudaGetSymbolAddress((void**)&cx16, g_cx16);
    cudaGetSymbolAddress((void**)&at16, g_at16);
    cudaGetSymbolAddress((void**)&hg,   g_hg);
    cudaGetSymbolAddress((void**)&hgT,  g_hgT);
    cudaGetSymbolAddress((void**)&e1,   g_e1);
    cudaGetSymbolAddress((void**)&e2,   g_e2);
    cudaGetSymbolAddress((void**)&m2,   g_m2);

    cudaFuncSetAttribute(hmma_1t_f32,      cudaFuncAttributeMaxDynamicSharedMemorySize, SMEM_CV);
    cudaFuncSetAttribute(hmma_1t_f16,      cudaFuncAttributeMaxDynamicSharedMemorySize, SMEM_CV);
    cudaFuncSetAttribute(hmma_1t_qkv,      cudaFuncAttributeMaxDynamicSharedMemorySize, SMEM_CV);
    cudaFuncSetAttribute(hmma_conv_kernel, cudaFuncAttributeMaxDynamicSharedMemorySize, SMEM_CV);

    const size_t WTN = (size_t)KW * D_ * D_;

    // 0) conversions
    cvt_f16_kernel<<<(M_*D_/4 + 255)/256, 256>>>(feat, f16, M_*D_/4);
    wtrans5_kernel<<<dim3((int)(WTN/256), 5), 256>>>(cw, wt16);
    cvt_f16_kernel<<<(D_*K5D/4 + 255)/256, 256>>>(fp_w, fp16, D_*K5D/4);
    Ptr5 dws{{ wq, wk, wv, wo, gat_w }};
    cvt5_f16_kernel<<<dim3(D_*D_/4/256, 5), 256>>>(dws, dw16);

    // 1) dilated convs (fp16 1-term) -> ms16
    hmma_conv_kernel<<<dim3(8, 16, 5), 256, SMEM_CV>>>(f16, wt16, cb, ms16);

    // 2) fusion projection (K=5120, 1-term) -> z fp32, then LN+GELU -> z16
    hmma_1t_f32<<<dim3(8, 16), 256, SMEM_CV>>>(ms16, fp16, fp_b, z, K5D, D_);
    ln_gelu_kernel<<<M_, 256>>>(z, ln_g, ln_b, z16);

    // 3) q, k, v projections (merged, fp16 out)
    QkvArgs qkv{{ q16, k16, v16 }, { bq, bk, bv }};
    hmma_1t_qkv<<<dim3(8, 16, 3), 256, SMEM_CV>>>(z16, dw16, qkv);

    // 4) attention (fp16 HMMA)
    vtrans_kernel<<<dim3(8, 2, B_*HMHA), 256>>>(v16, vT);
    attn_scores_hmma<<<dim3(2, 2, B_*HMHA), 256>>>(q16, k16, s);
    softmax_kernel<<<(B_*HMHA*T_)/8, 256>>>(s, p16);
    attn_ctx_hmma<<<dim3(2, B_*HMHA), 256>>>(p16, vT, cx16);

    // 5) wo -> at16 fp16; gat_w -> hg fp32
    hmma_1t_f16<<<dim3(8, 16), 256, SMEM_CV>>>(cx16,
        dw16 + 3*(size_t)D_*D_, bo, at16, D_, D_);
    hmma_1t_f32<<<dim3(8, 16), 256, SMEM_CV>>>(at16,
        dw16 + 4*(size_t)D_*D_, gat_b, hg, D_, D_);

    // 6) GAT logits, max, transpose
    e12_kernel<<<(M_*HGAT)/8, 256>>>(hg, a1, a2, e1, e2);
    e2max_kernel<<<HGAT, 256>>>(e2, m2);
    transpose_f16_kernel<<<dim3(M_/32, D_/32), 256>>>(hg, hgT);

    // 7) GAT aggregation (fp16 HMMA) + ELU + residual -> d_out
    gat_hmma_kernel<<<dim3(HGAT, 16), 256>>>(hgT, e1, e2, m2, feat, out);
}

// round 13
// speedup vs baseline: 8.8409x; 1.3208x over previous
#include <cuda_runtime.h>
#include <cuda_fp16.h>
#include <math.h>
#include <stdint.h>

#define D_   1024
#define T_   256
#define B_   8
#define M_   (B_*T_)        // 2048 rows (b,t)
#define HMHA 16
#define DH   64
#define HGAT 8
#define GDH  128
#define KW   7
#define K5D  (5*D_)
#define KCONV (KW*D_)       // 7168

// K64 pipeline geometry (dense + conv)
#define RB64  144                    // 64 fp16 = 128B + 16 pad
#define TB64  (128*RB64)             // 18432 B per tile
#define SMEM_K64 (2*2*TB64)          // 2 stages x 2 tiles = 73728

// GAT kernel geometry (K32)
#define GRB   80
#define GTB   (128*GRB)              // 10240

// Flash attention smem offsets
#define FQ_OFF   0
#define FK_OFF   (128*RB64)                 // 18432
#define FV_OFF   (FK_OFF + 256*RB64)        // 55296
#define FP_OFF   (FV_OFF + 64*528)          // 89088
#define FRED_OFF (FP_OFF + 128*528)         // 156672
#define FSM_TOT  (FRED_OFF + 4096)          // 160768

// ===================== PTX helpers (baseline ISA only) =====================
__device__ __forceinline__ uint32_t smem_u32(const void* p) {
    uint32_t a;
    asm("{ .reg .u64 t; cvta.to.shared.u64 t, %1; cvt.u32.u64 %0, t; }"
        : "=r"(a) : "l"(p));
    return a;
}
#define CP16(dst, src, sz) \
    asm volatile("cp.async.cg.shared.global [%0], [%1], 16, %2;" \
                 :: "r"(dst), "l"(src), "r"(sz))
#define CP_COMMIT() asm volatile("cp.async.commit_group;" ::: "memory")
#define CP_WAIT1()  asm volatile("cp.async.wait_group 1;" ::: "memory")
#define CP_WAIT0()  asm volatile("cp.async.wait_group 0;" ::: "memory")

#define LDMX4(r, addr) \
    asm volatile("ldmatrix.sync.aligned.m8n8.x4.shared.b16 {%0,%1,%2,%3}, [%4];" \
        : "=r"((r)[0]), "=r"((r)[1]), "=r"((r)[2]), "=r"((r)[3]) : "r"(addr))
#define LDMX2(r, addr) \
    asm volatile("ldmatrix.sync.aligned.m8n8.x2.shared.b16 {%0,%1}, [%2];" \
        : "=r"((r)[0]), "=r"((r)[1]) : "r"(addr))

#define MMA16816F(c, a, b) \
    asm volatile("mma.sync.aligned.m16n8k16.row.col.f32.f16.f16.f32 " \
        "{%0,%1,%2,%3}, {%4,%5,%6,%7}, {%8,%9}, {%0,%1,%2,%3};" \
        : "+f"((c)[0]), "+f"((c)[1]), "+f"((c)[2]), "+f"((c)[3]) \
        : "r"((a)[0]), "r"((a)[1]), "r"((a)[2]), "r"((a)[3]), \
          "r"((b)[0]), "r"((b)[1]))

struct Ptr5  { const float* p[5]; };
struct QkvArgs { __half* o[3]; const float* b[3]; };

// ---------------- scratch (device globals; no allocation) ----------------
__device__ __half g_f16 [M_ * D_];
__device__ __half g_wt16[5 * KW * D_ * D_];        // [c][tap][o][ci]
__device__ __half g_fp16[D_ * K5D];
__device__ __half g_dw16[5 * D_ * D_];
__device__ __half g_ms16[M_ * K5D];
__device__ float  g_z  [M_ * D_];
__device__ __half g_z16[M_ * D_];
__device__ __half g_q16[M_ * D_];
__device__ __half g_k16[M_ * D_];
__device__ __half g_v16[M_ * D_];
__device__ __half g_cx16[M_ * D_];
__device__ __half g_at16[M_ * D_];
__device__ float  g_hg [M_ * D_];
__device__ __half g_hgT[D_ * M_];
__device__ float  g_e1[M_ * HGAT];
__device__ float  g_e2[M_ * HGAT];
__device__ float  g_m2[HGAT];

// =====================================================================
// conversion kernels
// =====================================================================
__global__ __launch_bounds__(256)
void cvt_f16_kernel(const float* __restrict__ src, __half* __restrict__ hi, int n4)
{
    int i = blockIdx.x * 256 + threadIdx.x;
    if (i >= n4) return;
    float4 v = ((const float4*)src)[i];
    __half2* ph = (__half2*)hi;
    ph[2*i]   = __half2(__float2half_rn(v.x), __float2half_rn(v.y));
    ph[2*i+1] = __half2(__float2half_rn(v.z), __float2half_rn(v.w));
}

__global__ __launch_bounds__(256)
void cvt5_f16_kernel(Ptr5 ws, __half* __restrict__ hi)
{
    int c = blockIdx.y;
    int i = blockIdx.x * 256 + threadIdx.x;
    float4 v = ((const float4*)ws.p[c])[i];
    __half2* ph = (__half2*)(hi + (size_t)c * D_ * D_);
    ph[2*i]   = __half2(__float2half_rn(v.x), __float2half_rn(v.y));
    ph[2*i+1] = __half2(__float2half_rn(v.z), __float2half_rn(v.w));
}

// smem-staged conv weight transform: block = (o row, conv); coalesced both ways
__global__ __launch_bounds__(256)
void wtrans5_smem_kernel(Ptr5 cw, __half* __restrict__ wh)
{
    __shared__ float srow[KCONV];
    const int c = blockIdx.y;
    const int o = blockIdx.x;
    const int tid = threadIdx.x;
    const float4* src = (const float4*)(cw.p[c] + (size_t)o * KCONV);
    #pragma unroll
    for (int it = 0; it < 7; it++)
        ((float4*)srow)[tid + it*256] = src[tid + it*256];
    __syncthreads();
    const int ci0 = tid * 4;
    #pragma unroll
    for (int tap = 0; tap < KW; tap++) {
        float x0 = srow[(ci0+0)*7 + tap];
        float x1 = srow[(ci0+1)*7 + tap];
        float x2 = srow[(ci0+2)*7 + tap];
        float x3 = srow[(ci0+3)*7 + tap];
        __half2* dst = (__half2*)(wh + ((size_t)(c*KW + tap) << 20) + (o << 10) + ci0);
        dst[0] = __half2(__float2half_rn(x0), __float2half_rn(x1));
        dst[1] = __half2(__float2half_rn(x2), __float2half_rn(x3));
    }
}

// hg fp32 (2048 x 1024) -> hgT fp16 (1024 x 2048)
__global__ __launch_bounds__(256)
void transpose_f16_kernel(const float* __restrict__ hg, __half* __restrict__ hgT)
{
    __shared__ float tile[32][33];
    int j0 = blockIdx.x * 32, c0 = blockIdx.y * 32;
    int tx = threadIdx.x & 31, ty = threadIdx.x >> 5;
    #pragma unroll
    for (int r = ty; r < 32; r += 8)
        tile[r][tx] = hg[(size_t)(j0 + r) * D_ + c0 + tx];
    __syncthreads();
    #pragma unroll
    for (int r = ty; r < 32; r += 8)
        hgT[(size_t)(c0 + r) * M_ + j0 + tx] = __float2half_rn(tile[tx][r]);
}

// =====================================================================
// K64 fp16 1-term HMMA core: tiles 0=A, 1=B  (pitch RB64)
// =====================================================================
__device__ __forceinline__
void hmma_chunk64(uint32_t bufu, int wm, int wn, int lane, float acc[4][4][4])
{
    #pragma unroll
    for (int kk = 0; kk < 64; kk += 16) {
        uint32_t bh[4][2];
        #pragma unroll
        for (int j = 0; j < 4; j++) {
            int nrow = wn*32 + j*8 + (lane & 7);
            int colb = (kk + ((lane >> 3) & 1)*8) * 2;
            LDMX2(bh[j], bufu + 1*TB64 + nrow*RB64 + colb);
        }
        #pragma unroll
        for (int i = 0; i < 4; i++) {
            int mrow = wm*64 + i*16 + (lane & 15);
            int colb = (kk + ((lane >> 4) & 1)*8) * 2;
            uint32_t ah[4];
            LDMX4(ah, bufu + 0*TB64 + mrow*RB64 + colb);
            #pragma unroll
            for (int j = 0; j < 4; j++)
                MMA16816F(acc[i][j], ah, bh[j]);
        }
    }
}

__device__ __forceinline__
void issue64(uint32_t smem_base, int c, int tid,
             const __half* __restrict__ A, const __half* __restrict__ W,
             int bm, int bn, int K)
{
    int k0 = c << 6;
    uint32_t bufu = smem_base + (c & 1) * 2*TB64;
    #pragma unroll
    for (int it = 0; it < 8; it++) {
        int g = tid + it*256;
        int tile = g >> 10;
        int ct = g & 1023, row = ct >> 3, cc = ct & 7;
        const __half* src = (tile == 0)
            ? A + (size_t)(bm+row)*K + k0 + cc*8
            : W + (size_t)(bn+row)*K + k0 + cc*8;
        CP16(bufu + tile*TB64 + row*RB64 + cc*16, src, 16);
    }
    CP_COMMIT();
}

__device__ __forceinline__
void epi_f32(float acc[4][4][4], const float* __restrict__ bias,
             float* __restrict__ C, int bm, int bn, int ldc,
             int wm, int wn, int lane)
{
    #pragma unroll
    for (int i = 0; i < 4; i++) {
        int m0 = bm + wm*64 + i*16 + (lane >> 2);
        #pragma unroll
        for (int j = 0; j < 4; j++) {
            int n0 = wn*32 + j*8 + (lane & 3)*2;
            float b0 = bias[bn + n0], b1 = bias[bn + n0 + 1];
            *(float2*)&C[(size_t)m0*ldc + bn + n0] =
                make_float2(acc[i][j][0] + b0, acc[i][j][1] + b1);
            *(float2*)&C[(size_t)(m0+8)*ldc + bn + n0] =
                make_float2(acc[i][j][2] + b0, acc[i][j][3] + b1);
        }
    }
}

__device__ __forceinline__
void epi_f16(float acc[4][4][4], const float* __restrict__ bias,
             __half* __restrict__ C, int bm, int bn, int ldc, int colbase,
             int wm, int wn, int lane)
{
    #pragma unroll
    for (int i = 0; i < 4; i++) {
        int m0 = bm + wm*64 + i*16 + (lane >> 2);
        #pragma unroll
        for (int j = 0; j < 4; j++) {
            int n0 = wn*32 + j*8 + (lane & 3)*2;
            float b0 = bias[bn + n0], b1 = bias[bn + n0 + 1];
            size_t o01 = (size_t)m0*ldc + colbase + bn + n0;
            size_t o23 = (size_t)(m0+8)*ldc + colbase + bn + n0;
            *(__half2*)&C[o01] = __half2(__float2half_rn(acc[i][j][0] + b0),
                                         __float2half_rn(acc[i][j][1] + b1));
            *(__half2*)&C[o23] = __half2(__float2half_rn(acc[i][j][2] + b0),
                                         __float2half_rn(acc[i][j][3] + b1));
        }
    }
}

#define HMMA_PROLOG() \
    extern __shared__ __align__(16) char smem_raw[]; \
    const uint32_t smem_base = smem_u32(smem_raw); \
    const int bm = blockIdx.y * 128, bn = blockIdx.x * 128; \
    const int tid = threadIdx.x; \
    const int wid = tid >> 5, lane = tid & 31; \
    const int wm = wid & 1, wn = wid >> 1; \
    float acc[4][4][4] = {};

#define HMMA_LOOP2(NC, ISSUE) \
    ISSUE(0); \
    for (int c = 0; c < (NC); c++) { \
        if (c + 1 < (NC)) { ISSUE(c + 1); CP_WAIT1(); } \
        else              { CP_WAIT0(); } \
        __syncthreads(); \
        hmma_chunk64(smem_base + (c & 1)*2*TB64, wm, wn, lane, acc); \
        __syncthreads(); \
    }

// ---- dense 1-term, fp32 out (fusion, gat_w) ----
__global__ __launch_bounds__(256, 2)
void hmma_1t_f32(const __half* __restrict__ A, const __half* __restrict__ W,
                 const float* __restrict__ bias, float* __restrict__ C,
                 int K, int ldc)
{
    HMMA_PROLOG();
#define ISS(c) issue64(smem_base, c, tid, A, W, bm, bn, K)
    HMMA_LOOP2(K >> 6, ISS);
#undef ISS
    epi_f32(acc, bias, C, bm, bn, ldc, wm, wn, lane);
}

// ---- dense 1-term, fp16 out (wo) ----
__global__ __launch_bounds__(256, 2)
void hmma_1t_f16(const __half* __restrict__ A, const __half* __restrict__ W,
                 const float* __restrict__ bias, __half* __restrict__ C,
                 int K, int ldc)
{
    HMMA_PROLOG();
#define ISS(c) issue64(smem_base, c, tid, A, W, bm, bn, K)
    HMMA_LOOP2(K >> 6, ISS);
#undef ISS
    epi_f16(acc, bias, C, bm, bn, ldc, 0, wm, wn, lane);
}

// ---- QKV: grid.z selects weight/bias/output, fp16 out ----
__global__ __launch_bounds__(256, 2)
void hmma_1t_qkv(const __half* __restrict__ A, const __half* __restrict__ dw16,
                 QkvArgs args)
{
    const int z = blockIdx.z;
    const __half* Wh = dw16 + (size_t)z * D_ * D_;
    HMMA_PROLOG();
#define ISS(c) issue64(smem_base, c, tid, A, Wh, bm, bn, D_)
    HMMA_LOOP2(D_ >> 6, ISS);
#undef ISS
    epi_f16(acc, args.b[z], args.o[z], bm, bn, D_, 0, wm, wn, lane);
}

// ---- convs: fp16 1-term gather, grid.z = conv id, fp16 out ----
__global__ __launch_bounds__(256, 2)
void hmma_conv_kernel(const __half* __restrict__ Fh,
                      const __half* __restrict__ wt16, Ptr5 cbs,
                      __half* __restrict__ ms16)
{
    const int z = blockIdx.z;
    const int dil = 1 << z;
    const int ccol = z * D_;
    const __half* Wh = wt16 + (size_t)z * (KW*D_*D_);
    HMMA_PROLOG();

#define ISSUE_C(c) do { \
    int k0 = (c) << 6; \
    int tap = k0 >> 10, ci0 = k0 & 1023; \
    int offt = (tap - 3) * dil; \
    uint32_t bufu = smem_base + ((c) & 1) * 2*TB64; \
    _Pragma("unroll") \
    for (int it = 0; it < 8; it++) { \
        int g = tid + it*256; \
        int tile = g >> 10; \
        int ct = g & 1023; int row = ct >> 3, cc = ct & 7; \
        const __half* src; \
        uint32_t sz = 16; \
        if (tile == 0) { \
            int m = bm + row; \
            int bb = m >> 8, tt = (m & 255) + offt; \
            if (tt >= 0 && tt < T_) \
                src = Fh + ((size_t)(bb*T_ + tt))*D_ + ci0 + cc*8; \
            else { src = Fh; sz = 0; } \
        } else { \
            src = Wh + (size_t)tap*D_*D_ + (size_t)(bn+row)*D_ + ci0 + cc*8; \
        } \
        CP16(bufu + tile*TB64 + row*RB64 + cc*16, src, sz); \
    } \
    CP_COMMIT(); } while (0)

    HMMA_LOOP2(KCONV >> 6, ISSUE_C);
#undef ISSUE_C
    epi_f16(acc, cbs.p[z], ms16, bm, bn, K5D, ccol, wm, wn, lane);
}

// =====================================================================
// LayerNorm + exact GELU: reads z fp32, writes z16 fp16.
// =====================================================================
__global__ __launch_bounds__(256)
void ln_gelu_kernel(const float* __restrict__ z, const float* __restrict__ g,
                    const float* __restrict__ b, __half* __restrict__ z16)
{
    const int row = blockIdx.x;
    const int tid = threadIdx.x;
    const float* p = z + (size_t)row * D_;
    float4 v = ((const float4*)p)[tid];
    float s  = v.x + v.y + v.z + v.w;
    float ss = v.x*v.x + v.y*v.y + v.z*v.z + v.w*v.w;
    #pragma unroll
    for (int o = 16; o; o >>= 1) {
        s  += __shfl_xor_sync(0xffffffffu, s,  o);
        ss += __shfl_xor_sync(0xffffffffu, ss, o);
    }
    __shared__ float ws[8], wss[8];
    __shared__ float mu_s, inv_s;
    int lane = tid & 31, wid = tid >> 5;
    if (lane == 0) { ws[wid] = s; wss[wid] = ss; }
    __syncthreads();
    if (tid == 0) {
        float S = 0.f, SS = 0.f;
        #pragma unroll
        for (int i = 0; i < 8; i++) { S += ws[i]; SS += wss[i]; }
        float mu = S * (1.f / D_);
        float var = SS * (1.f / D_) - mu * mu;
        mu_s = mu;
        inv_s = rsqrtf(var + 1e-5f);
    }
    __syncthreads();
    float mu = mu_s, inv = inv_s;
    float4 gg = ((const float4*)g)[tid];
    float4 bb = ((const float4*)b)[tid];
    float y[4] = { (v.x-mu)*inv*gg.x + bb.x, (v.y-mu)*inv*gg.y + bb.y,
                   (v.z-mu)*inv*gg.z + bb.z, (v.w-mu)*inv*gg.w + bb.w };
    float o[4];
    o[0] = 0.5f*y[0]*(1.f + erff(y[0]*0.70710678118654752f));
    o[1] = 0.5f*y[1]*(1.f + erff(y[1]*0.70710678118654752f));
    o[2] = 0.5f*y[2]*(1.f + erff(y[2]*0.70710678118654752f));
    o[3] = 0.5f*y[3]*(1.f + erff(y[3]*0.70710678118654752f));
    __half2* ph = (__half2*)(z16 + (size_t)row * D_);
    ph[2*tid]   = __half2(__float2half_rn(o[0]), __float2half_rn(o[1]));
    ph[2*tid+1] = __half2(__float2half_rn(o[2]), __float2half_rn(o[3]));
}

// =====================================================================
// Flash attention: one kernel per (m-tile 128, bh). smem: Q,K,V^T,P.
// =====================================================================
__global__ __launch_bounds__(256)
void attn_flash_kernel(const __half* __restrict__ q16, const __half* __restrict__ k16,
                       const __half* __restrict__ v16, __half* __restrict__ cx16)
{
    extern __shared__ __align__(16) char fsm[];
    const uint32_t base = smem_u32(fsm);
    float* pmax = (float*)(fsm + FRED_OFF);          // [4][128]
    float* psum = (float*)(fsm + FRED_OFF + 2048);   // [4][128]
    const int bh = blockIdx.y;
    const int b = bh >> 4, h = bh & 15;
    const int bm = blockIdx.x * 128;
    const int tid = threadIdx.x;
    const int wid = tid >> 5, lane = tid & 31;
    const int wm = wid & 1, wn = wid >> 1;

    // Q (128x64), K (256x64) via cp.async
    #pragma unroll
    for (int it = 0; it < 4; it++) {
        int g = tid + it*256;
        int row = g >> 3, cc = g & 7;
        CP16(base + FQ_OFF + row*RB64 + cc*16,
             q16 + (size_t)(b*T_ + bm + row)*D_ + h*DH + cc*8, 16);
    }
    #pragma unroll
    for (int it = 0; it < 8; it++) {
        int g = tid + it*256;
        int row = g >> 3, cc = g & 7;
        CP16(base + FK_OFF + row*RB64 + cc*16,
             k16 + (size_t)(b*T_ + row)*D_ + h*DH + cc*8, 16);
    }
    CP_COMMIT();
    // V transpose load: [t][d] -> sV[d][t] (pitch 528)
    #pragma unroll
    for (int it = 0; it < 64; it++) {
        int g = tid + it*256;
        int t = g >> 6, d = g & 63;
        *(__half*)(fsm + FV_OFF + d*528 + t*2) =
            v16[(size_t)(b*T_ + t)*D_ + h*DH + d];
    }
    CP_WAIT0();
    __syncthreads();

    // S = Q@K^T: warp tile 64x64 over N=256
    float acc[4][8][4] = {};
    #pragma unroll
    for (int kk = 0; kk < 64; kk += 16) {
        uint32_t bf[8][2];
        #pragma unroll
        for (int j = 0; j < 8; j++) {
            int nrow = wn*64 + j*8 + (lane & 7);
            int colb = (kk + ((lane >> 3) & 1)*8) * 2;
            LDMX2(bf[j], base + FK_OFF + nrow*RB64 + colb);
        }
        #pragma unroll
        for (int i = 0; i < 4; i++) {
            int mrow = wm*64 + i*16 + (lane & 15);
            int colb = (kk + ((lane >> 4) & 1)*8) * 2;
            uint32_t af[4];
            LDMX4(af, base + FQ_OFF + mrow*RB64 + colb);
            #pragma unroll
            for (int j = 0; j < 8; j++)
                MMA16816F(acc[i][j], af, bf[j]);
        }
    }
    // scale
    #pragma unroll
    for (int i = 0; i < 4; i++)
        #pragma unroll
        for (int j = 0; j < 8; j++)
            #pragma unroll
            for (int q = 0; q < 4; q++)
                acc[i][j][q] *= 0.125f;

    // row max (warp slice -> smem partials)
    #pragma unroll
    for (int i = 0; i < 4; i++) {
        float m0 = -1e30f, m1 = -1e30f;
        #pragma unroll
        for (int j = 0; j < 8; j++) {
            m0 = fmaxf(m0, fmaxf(acc[i][j][0], acc[i][j][1]));
            m1 = fmaxf(m1, fmaxf(acc[i][j][2], acc[i][j][3]));
        }
        #pragma unroll
        for (int o = 1; o < 4; o <<= 1) {
            m0 = fmaxf(m0, __shfl_xor_sync(0xffffffffu, m0, o));
            m1 = fmaxf(m1, __shfl_xor_sync(0xffffffffu, m1, o));
        }
        if ((lane & 3) == 0) {
            int r = wm*64 + i*16 + (lane >> 2);
            pmax[wn*128 + r]     = m0;
            pmax[wn*128 + r + 8] = m1;
        }
    }
    __syncthreads();
    // exp + partial sums + write unnormalized P (fp16, pitch 528)
    #pragma unroll
    for (int i = 0; i < 4; i++) {
        int r0 = wm*64 + i*16 + (lane >> 2);
        float rm0 = fmaxf(fmaxf(pmax[r0], pmax[128+r0]),
                          fmaxf(pmax[256+r0], pmax[384+r0]));
        float rm1 = fmaxf(fmaxf(pmax[r0+8], pmax[128+r0+8]),
                          fmaxf(pmax[256+r0+8], pmax[384+r0+8]));
        float s0 = 0.f, s1 = 0.f;
        #pragma unroll
        for (int j = 0; j < 8; j++) {
            int col = wn*64 + j*8 + (lane & 3)*2;
            float e0 = __expf(acc[i][j][0] - rm0);
            float e1 = __expf(acc[i][j][1] - rm0);
            float e2 = __expf(acc[i][j][2] - rm1);
            float e3 = __expf(acc[i][j][3] - rm1);
            s0 += e0 + e1; s1 += e2 + e3;
            *(__half2*)(fsm + FP_OFF + r0*528 + col*2) =
                __half2(__float2half_rn(e0), __float2half_rn(e1));
            *(__half2*)(fsm + FP_OFF + (r0+8)*528 + col*2) =
                __half2(__float2half_rn(e2), __float2half_rn(e3));
        }
        #pragma unroll
        for (int o = 1; o < 4; o <<= 1) {
            s0 += __shfl_xor_sync(0xffffffffu, s0, o);
            s1 += __shfl_xor_sync(0xffffffffu, s1, o);
        }
        if ((lane & 3) == 0) {
            int r = wm*64 + i*16 + (lane >> 2);
            psum[wn*128 + r]     = s0;
            psum[wn*128 + r + 8] = s1;
        }
    }
    __syncthreads();

    // ctx = P @ V^T: warp tile 64x16 over N=64, K=256
    float acc2[4][2][4] = {};
    #pragma unroll
    for (int kk = 0; kk < 256; kk += 16) {
        uint32_t bf[2][2];
        #pragma unroll
        for (int j = 0; j < 2; j++) {
            int nrow = wn*16 + j*8 + (lane & 7);
            int colb = (kk + ((lane >> 3) & 1)*8) * 2;
            LDMX2(bf[j], base + FV_OFF + nrow*528 + colb);
        }
        #pragma unroll
        for (int i = 0; i < 4; i++) {
            int mrow = wm*64 + i*16 + (lane & 15);
            int colb = (kk + ((lane >> 4) & 1)*8) * 2;
            uint32_t af[4];
            LDMX4(af, base + FP_OFF + mrow*528 + colb);
            #pragma unroll
            for (int j = 0; j < 2; j++)
                MMA16816F(acc2[i][j], af, bf[j]);
        }
    }
    // epilogue: divide by rowsum, write
    #pragma unroll
    for (int i = 0; i < 4; i++) {
        int r0 = wm*64 + i*16 + (lane >> 2);
        float inv0 = 1.f / (psum[r0] + psum[128+r0] + psum[256+r0] + psum[384+r0]);
        float inv1 = 1.f / (psum[r0+8] + psum[128+r0+8] + psum[256+r0+8] + psum[384+r0+8]);
        #pragma unroll
        for (int j = 0; j < 2; j++) {
            int n0 = wn*16 + j*8 + (lane & 3)*2;
            size_t o01 = (size_t)(b*T_ + bm + r0)*D_ + h*DH + n0;
            size_t o23 = (size_t)(b*T_ + bm + r0 + 8)*D_ + h*DH + n0;
            *(__half2*)&cx16[o01] = __half2(__float2half_rn(acc2[i][j][0]*inv0),
                                            __float2half_rn(acc2[i][j][1]*inv0));
            *(__half2*)&cx16[o23] = __half2(__float2half_rn(acc2[i][j][2]*inv1),
                                            __float2half_rn(acc2[i][j][3]*inv1));
        }
    }
}

// =====================================================================
// GAT pieces
// =====================================================================
__global__ __launch_bounds__(256)
void e12_kernel(const float* __restrict__ hg, const float* __restrict__ a1,
                const float* __restrict__ a2, float* __restrict__ e1,
                float* __restrict__ e2)
{
    int wid  = (blockIdx.x * blockDim.x + threadIdx.x) >> 5;
    int lane = threadIdx.x & 31;
    int n = wid >> 3, h = wid & 7;
    const float* row = hg + (size_t)n * D_ + h * GDH;
    float s1 = 0.f, s2 = 0.f;
    #pragma unroll
    for (int r = 0; r < 4; r++) {
        float x = row[lane + 32*r];
        s1 += x * a1[lane + 32*r];
        s2 += x * a2[lane + 32*r];
    }
    #pragma unroll
    for (int o = 16; o; o >>= 1) {
        s1 += __shfl_xor_sync(0xffffffffu, s1, o);
        s2 += __shfl_xor_sync(0xffffffffu, s2, o);
    }
    if (lane == 0) { e1[n*HGAT + h] = s1; e2[n*HGAT + h] = s2; }
}

__global__ __launch_bounds__(256)
void e2max_kernel(const float* __restrict__ e2, float* __restrict__ m2)
{
    int h = blockIdx.x, tid = threadIdx.x;
    float m = -1e30f;
    for (int n = tid; n < M_; n += 256) m = fmaxf(m, e2[n*HGAT + h]);
    __shared__ float sm[256];
    sm[tid] = m; __syncthreads();
    for (int s = 128; s > 0; s >>= 1) {
        if (tid < s) sm[tid] = fmaxf(sm[tid], sm[tid + s]);
        __syncthreads();
    }
    if (tid == 0) m2[h] = sm[0];
}

// GAT aggregation: fp16 HMMA with on-the-fly alpha + fused denom/ELU/residual.
__global__ __launch_bounds__(256)
void gat_hmma_kernel(const __half* __restrict__ hgT, const float* __restrict__ e1,
                     const float* __restrict__ e2, const float* __restrict__ m2,
                     const float* __restrict__ feat, float* __restrict__ out)
{
    __shared__ __align__(16) char sA[GTB];
    __shared__ __align__(16) char sB[3][GTB];
    __shared__ float s_e1[128], s_mr[128], dpart[256];
    const int h  = blockIdx.x;
    const int bm = blockIdx.y * 128;
    const int tid = threadIdx.x;
    const int wid = tid >> 5, lane = tid & 31;
    const int wm = wid & 1, wn = wid >> 1;
    const uint32_t aU = smem_u32(sA);
    if (tid < 128) {
        float v1 = e1[(bm + tid)*HGAT + h];
        float sv = v1 + m2[h];
        s_mr[tid] = sv > 0.f ? sv : 0.2f * sv;
        s_e1[tid] = v1;
    }
    __syncthreads();
    const int am  = tid >> 1;
    const int ak0 = (tid & 1) * 16;
    const float e1v = s_e1[am], mrv = s_mr[am];
    float dreg = 0.f;
    float acc[4][4][4] = {};

#define ISSUE_B(c) do { \
    int k0 = (c) << 5; \
    uint32_t bufu = smem_u32(sB[(c) % 3]); \
    _Pragma("unroll") \
    for (int it = 0; it < 2; it++) { \
        int g = tid + it*256; \
        int row = g >> 2, cc = g & 3; \
        const __half* src = hgT + (size_t)(h*GDH + row)*M_ + k0 + cc*8; \
        CP16(bufu + row*GRB + cc*16, src, 16); \
    } \
    CP_COMMIT(); } while (0)

    const int nc = M_ >> 5;               // 64
    ISSUE_B(0);
    ISSUE_B(1);
    for (int c = 0; c < nc; c++) {
        int k0 = c << 5;
        #pragma unroll
        for (int r = 0; r < 16; r++) {
            int j = k0 + ak0 + r;
            float ev = __ldg(&e2[j*HGAT + h]);
            float sv = e1v + ev;
            float lv = sv > 0.f ? sv : 0.2f * sv;
            __half a16 = __float2half_rn(__expf(lv - mrv));
            dreg += __half2float(a16);
            *(__half*)(sA + am*GRB + (ak0 + r)*2) = a16;
        }
        if (c + 1 < nc) CP_WAIT1(); else CP_WAIT0();
        __syncthreads();
        if (c + 2 < nc) ISSUE_B(c + 2);
        uint32_t bU = smem_u32(sB[c % 3]);
        #pragma unroll
        for (int kk = 0; kk < 32; kk += 16) {
            uint32_t bhf[4][2];
            #pragma unroll
            for (int j = 0; j < 4; j++) {
                int nrow = wn*32 + j*8 + (lane & 7);
                int colb = (kk + ((lane >> 3) & 1)*8) * 2;
                LDMX2(bhf[j], bU + nrow*GRB + colb);
            }
            #pragma unroll
            for (int i = 0; i < 4; i++) {
                int mrow = wm*64 + i*16 + (lane & 15);
                int colb = (kk + ((lane >> 4) & 1)*8) * 2;
                uint32_t ah[4];
                LDMX4(ah, aU + mrow*GRB + colb);
                #pragma unroll
                for (int j = 0; j < 4; j++)
                    MMA16816F(acc[i][j], ah, bhf[j]);
            }
        }
        __syncthreads();
    }
#undef ISSUE_B
    dpart[tid] = dreg;
    __syncthreads();
    #pragma unroll
    for (int i = 0; i < 4; i++) {
        int ml = wm*64 + i*16 + (lane >> 2);
        int m0 = bm + ml;
        float inv0 = 1.f / (dpart[2*ml] + dpart[2*ml+1]);
        float inv1 = 1.f / (dpart[2*(ml+8)] + dpart[2*(ml+8)+1]);
        #pragma unroll
        for (int j = 0; j < 4; j++) {
            int n0 = wn*32 + j*8 + (lane & 3)*2;
            int col = h*GDH + n0;
            float v0 = acc[i][j][0]*inv0, v1 = acc[i][j][1]*inv0;
            float v2 = acc[i][j][2]*inv1, v3 = acc[i][j][3]*inv1;
            v0 = v0 > 0.f ? v0 : expm1f(v0);
            v1 = v1 > 0.f ? v1 : expm1f(v1);
            v2 = v2 > 0.f ? v2 : expm1f(v2);
            v3 = v3 > 0.f ? v3 : expm1f(v3);
            size_t o01 = (size_t)m0*D_ + col;
            size_t o23 = (size_t)(m0+8)*D_ + col;
            out[o01]   = v0 + feat[o01];
            out[o01+1] = v1 + feat[o01+1];
            out[o23]   = v2 + feat[o23];
            out[o23+1] = v3 + feat[o23+1];
        }
    }
}

// =====================================================================
extern "C" void kernel_launch(void* const* d_in, const int* in_sizes, int n_in,
                              void* d_out, int out_size)
{
    const float* feat = (const float*)d_in[0];

    Ptr5 cw{}, cb{};
    int wi = 0, bi = 0;
    for (int i = 1; i <= 10; i++) {
        if (in_sizes[i] == D_ * D_ * KW) { if (wi < 5) cw.p[wi++] = (const float*)d_in[i]; }
        else                             { if (bi < 5) cb.p[bi++] = (const float*)d_in[i]; }
    }

    const float* fp_w = (const float*)d_in[11];
    const float* fp_b = (const float*)d_in[12];
    const float* ln_g = (const float*)d_in[13];
    const float* ln_b = (const float*)d_in[14];
    const float* wq = (const float*)d_in[15];
    const float* bq = (const float*)d_in[16];
    const float* wk = (const float*)d_in[17];
    const float* bk = (const float*)d_in[18];
    const float* wv = (const float*)d_in[19];
    const float* bv = (const float*)d_in[20];
    const float* wo = (const float*)d_in[21];
    const float* bo = (const float*)d_in[22];
    const float* gat_w = (const float*)d_in[23];
    const float* gat_b = (const float*)d_in[24];
    const float* a1 = (const float*)d_in[25];
    const float* a2 = (const float*)d_in[26];
    float* out = (float*)d_out;

    __half *f16, *wt16, *fp16, *dw16, *ms16, *z16, *q16, *k16, *v16;
    __half *cx16, *at16, *hgT;
    float *z, *hg, *e1, *e2, *m2;
    cudaGetSymbolAddress((void**)&f16,  g_f16);
    cudaGetSymbolAddress((void**)&wt16, g_wt16);
    cudaGetSymbolAddress((void**)&fp16, g_fp16);
    cudaGetSymbolAddress((void**)&dw16, g_dw16);
    cudaGetSymbolAddress((void**)&ms16, g_ms16);
    cudaGetSymbolAddress((void**)&z,    g_z);
    cudaGetSymbolAddress((void**)&z16,  g_z16);
    cudaGetSymbolAddress((void**)&q16,  g_q16);
    cudaGetSymbolAddress((void**)&k16,  g_k16);
    cudaGetSymbolAddress((void**)&v16,  g_v16);
    cudaGetSymbolAddress((void**)&cx16, g_cx16);
    cudaGetSymbolAddress((void**)&at16, g_at16);
    cudaGetSymbolAddress((void**)&hg,   g_hg);
    cudaGetSymbolAddress((void**)&hgT,  g_hgT);
    cudaGetSymbolAddress((void**)&e1,   g_e1);
    cudaGetSymbolAddress((void**)&e2,   g_e2);
    cudaGetSymbolAddress((void**)&m2,   g_m2);

    cudaFuncSetAttribute(hmma_1t_f32,       cudaFuncAttributeMaxDynamicSharedMemorySize, SMEM_K64);
    cudaFuncSetAttribute(hmma_1t_f16,       cudaFuncAttributeMaxDynamicSharedMemorySize, SMEM_K64);
    cudaFuncSetAttribute(hmma_1t_qkv,       cudaFuncAttributeMaxDynamicSharedMemorySize, SMEM_K64);
    cudaFuncSetAttribute(hmma_conv_kernel,  cudaFuncAttributeMaxDynamicSharedMemorySize, SMEM_K64);
    cudaFuncSetAttribute(attn_flash_kernel, cudaFuncAttributeMaxDynamicSharedMemorySize, FSM_TOT);

    // 0) conversions
    cvt_f16_kernel<<<(M_*D_/4 + 255)/256, 256>>>(feat, f16, M_*D_/4);
    wtrans5_smem_kernel<<<dim3(D_, 5), 256>>>(cw, wt16);
    cvt_f16_kernel<<<(D_*K5D/4 + 255)/256, 256>>>(fp_w, fp16, D_*K5D/4);
    Ptr5 dws{{ wq, wk, wv, wo, gat_w }};
    cvt5_f16_kernel<<<dim3(D_*D_/4/256, 5), 256>>>(dws, dw16);

    // 1) dilated convs (fp16 1-term, K64) -> ms16
    hmma_conv_kernel<<<dim3(8, 16, 5), 256, SMEM_K64>>>(f16, wt16, cb, ms16);

    // 2) fusion projection (K=5120) -> z fp32, then LN+GELU -> z16
    hmma_1t_f32<<<dim3(8, 16), 256, SMEM_K64>>>(ms16, fp16, fp_b, z, K5D, D_);
    ln_gelu_kernel<<<M_, 256>>>(z, ln_g, ln_b, z16);

    // 3) q, k, v projections (merged)
    QkvArgs qkv{{ q16, k16, v16 }, { bq, bk, bv }};
    hmma_1t_qkv<<<dim3(8, 16, 3), 256, SMEM_K64>>>(z16, dw16, qkv);

    // 4) attention: single flash kernel
    attn_flash_kernel<<<dim3(2, B_*HMHA), 256, FSM_TOT>>>(q16, k16, v16, cx16);

    // 5) wo -> at16; gat_w -> hg fp32
    hmma_1t_f16<<<dim3(8, 16), 256, SMEM_K64>>>(cx16,
        dw16 + 3*(size_t)D_*D_, bo, at16, D_, D_);
    hmma_1t_f32<<<dim3(8, 16), 256, SMEM_K64>>>(at16,
        dw16 + 4*(size_t)D_*D_, gat_b, hg, D_, D_);

    // 6) GAT logits, max, transpose
    e12_kernel<<<(M_*HGAT)/8, 256>>>(hg, a1, a2, e1, e2);
    e2max_kernel<<<HGAT, 256>>>(e2, m2);
    transpose_f16_kernel<<<dim3(M_/32, D_/32), 256>>>(hg, hgT);

    // 7) GAT aggregation (fp16 HMMA) + ELU + residual -> d_out
    gat_hmma_kernel<<<dim3(HGAT, 16), 256>>>(hgT, e1, e2, m2, feat, out);
}